// round 8
// baseline (speedup 1.0000x reference)
#include <cuda_runtime.h>
#include <cuda_bf16.h>
#include <math.h>
#include <stdint.h>

#define L_ 6
#define H_ 16
#define N_ 2048
#define DM_ 1024
#define DK_ 64
#define DV_ 64
#define DFF_ 4096
#define QSTR (H_ * DK_)   // 1024, interleaved Q/K/V row stride

// ---------------- helpers ----------------
__device__ __forceinline__ uint32_t smem_u32(const void* p) {
    uint32_t a;
    asm("{ .reg .u64 t; cvta.to.shared.u64 t, %1; cvt.u32.u64 %0, t; }" : "=r"(a) : "l"(p));
    return a;
}
#define CPA16(saddr, gptr) \
    asm volatile("cp.async.cg.shared.global [%0], [%1], 16;" :: "r"(saddr), "l"(gptr) : "memory")
#define CP_COMMIT() asm volatile("cp.async.commit_group;" ::: "memory")
#define CP_WAIT0()  asm volatile("cp.async.wait_group 0;" ::: "memory")
#define CP_WAIT1()  asm volatile("cp.async.wait_group 1;" ::: "memory")

__device__ __forceinline__ void mma16816(float* c, const uint32_t* a, const uint32_t* b) {
    asm volatile(
        "mma.sync.aligned.m16n8k16.row.col.f32.bf16.bf16.f32 "
        "{%0,%1,%2,%3}, {%4,%5,%6,%7}, {%8,%9}, {%0,%1,%2,%3};"
        : "+f"(c[0]), "+f"(c[1]), "+f"(c[2]), "+f"(c[3])
        : "r"(a[0]), "r"(a[1]), "r"(a[2]), "r"(a[3]), "r"(b[0]), "r"(b[1]));
}

__device__ __forceinline__ uint32_t pack_bf2(float a, float b) {
    __nv_bfloat162 p = {__float2bfloat16(a), __float2bfloat16(b)};
    return *(uint32_t*)&p;
}

// ---------------- scratch ----------------
__device__ float g_h[N_ * DM_];
__device__ float g_Q[N_ * QSTR];
__device__ float g_K[N_ * QSTR];
__device__ float g_V[N_ * QSTR];
__device__ float g_lse[H_ * N_];
__device__ float g_KtV[H_ * DK_ * DV_];
__device__ float g_lseV[H_ * DV_];
__device__ float g_Z[N_ * DM_];
__device__ float g_h2[N_ * DM_];
__device__ float g_R[N_ * DM_];
__device__ __nv_bfloat16 g_hh[N_ * DM_], g_hl[N_ * DM_];
__device__ __nv_bfloat16 g_Qh[N_ * QSTR], g_Ql[N_ * QSTR];
__device__ __nv_bfloat16 g_Kh[N_ * QSTR], g_Kl[N_ * QSTR];
__device__ __nv_bfloat16 g_h2h[N_ * DM_], g_h2l[N_ * DM_];
__device__ __nv_bfloat16 g_ath[N_ * DM_], g_atl[N_ * DM_];
__device__ __nv_bfloat16 g_F1h[N_ * DFF_], g_F1l[N_ * DFF_];
__device__ __nv_bfloat16 g_Wth[DFF_ * DM_], g_Wtl[DFF_ * DM_];

// one shared extern dynamic smem symbol for ALL kernels
extern __shared__ char dynsm[];

// ---------------- embedding + positional encoding ----------------
__global__ void embed_kernel(const int* __restrict__ X, const float* __restrict__ emb,
                             float* __restrict__ h, __nv_bfloat16* __restrict__ oh,
                             __nv_bfloat16* __restrict__ ol) {
    int n = blockIdx.x;
    int t = threadIdx.x;
    const float* e = emb + (size_t)X[n] * DM_;
    float pos = (float)(n + 1);
#pragma unroll
    for (int k = 0; k < 2; k++) {
        int i = t + k * 256;
        float a = (float)(2 * i) / (float)DM_ * -9.210340371976184f;
        float f = expf(a);
        float tt = pos * f;
        float v0 = e[2 * i] + sinf(tt);
        float v1 = e[2 * i + 1] + cosf(tt);
        h[(size_t)n * DM_ + 2 * i] = v0;
        h[(size_t)n * DM_ + 2 * i + 1] = v1;
        __nv_bfloat16 h0 = __float2bfloat16(v0), h1 = __float2bfloat16(v1);
        oh[(size_t)n * DM_ + 2 * i] = h0;
        oh[(size_t)n * DM_ + 2 * i + 1] = h1;
        ol[(size_t)n * DM_ + 2 * i] = __float2bfloat16(v0 - __bfloat162float(h0));
        ol[(size_t)n * DM_ + 2 * i + 1] = __float2bfloat16(v1 - __bfloat162float(h1));
    }
}

// ---------------- batched transpose + split: in [B][K][Nb] -> out [B*Nb][K] -------
__global__ void cvtT_kernel(const float* __restrict__ in, __nv_bfloat16* __restrict__ oh,
                            __nv_bfloat16* __restrict__ ol, int K, int Nb) {
    __shared__ float tile[32][33];
    int b = blockIdx.z;
    int k0 = blockIdx.x * 32, n0 = blockIdx.y * 32;
    int tx = threadIdx.x, ty = threadIdx.y;
    const float* W = in + (size_t)b * K * Nb;
#pragma unroll
    for (int r = 0; r < 4; r++)
        tile[ty + 8 * r][tx] = W[(size_t)(k0 + ty + 8 * r) * Nb + n0 + tx];
    __syncthreads();
#pragma unroll
    for (int r = 0; r < 4; r++) {
        float a = tile[tx][ty + 8 * r];
        size_t o = (size_t)(b * Nb + n0 + ty + 8 * r) * K + k0 + tx;
        __nv_bfloat16 h = __float2bfloat16(a);
        oh[o] = h;
        ol[o] = __float2bfloat16(a - __bfloat162float(h));
    }
}

// ---------------- HMMA GEMM: C[M,N] = A[M,K] @ Bt[N,K]^T + bias, opt relu ---------
// hi/lo split: C = Ah*Bh + Ah*Bl + Al*Bh. Optional fp32 out C, optional bf16 hi/lo out.
#define BM 128
#define BN 128
#define BK 32
#define KP 40
#define MAT_ELE (BM * KP)
#define STAGE_ELE (4 * MAT_ELE)
#define HG_SMEM (2 * STAGE_ELE * 2)
template <bool RELU>
__global__ void __launch_bounds__(256) hmma_gemm(
    const __nv_bfloat16* __restrict__ Ah, const __nv_bfloat16* __restrict__ Al,
    const __nv_bfloat16* __restrict__ Bh, const __nv_bfloat16* __restrict__ Bl,
    float* __restrict__ C, __nv_bfloat16* __restrict__ Oh, __nv_bfloat16* __restrict__ Ol,
    const float* __restrict__ bias, int M, int N, int K) {
    __nv_bfloat16* smem = (__nv_bfloat16*)dynsm;
    uint32_t smb = smem_u32(dynsm);

    int t = threadIdx.x;
    int warp = t >> 5, lane = t & 31;
    int wm = warp & 3, wn = warp >> 2;
    int g = lane >> 2, tg = lane & 3;
    int bn0 = blockIdx.x * BN, bm0 = blockIdx.y * BM;

    const __nv_bfloat16* srcs[4] = {Ah, Al, Bh, Bl};
    int rowbase[4] = {bm0, bm0, bn0, bn0};

    float acc[2][8][4];
#pragma unroll
    for (int i = 0; i < 2; i++)
#pragma unroll
        for (int j = 0; j < 8; j++)
#pragma unroll
            for (int k = 0; k < 4; k++) acc[i][j][k] = 0.f;

    const int nch = K / BK;

    auto issue = [&](int c) {
        uint32_t sb = smb + (uint32_t)((c & 1) * STAGE_ELE * 2);
#pragma unroll
        for (int mt = 0; mt < 4; mt++) {
#pragma unroll
            for (int r = 0; r < 2; r++) {
                int f = t + 256 * r;
                int m = f >> 2, ck = f & 3;
                const __nv_bfloat16* gp =
                    srcs[mt] + (size_t)(rowbase[mt] + m) * K + c * BK + ck * 8;
                uint32_t sa = sb + (uint32_t)((mt * MAT_ELE + m * KP + ck * 8) * 2);
                CPA16(sa, gp);
            }
        }
    };

    issue(0);
    CP_COMMIT();

    for (int c = 0; c < nch; c++) {
        if (c + 1 < nch) {
            issue(c + 1);
            CP_COMMIT();
            CP_WAIT1();
        } else {
            CP_WAIT0();
        }
        __syncthreads();

        const __nv_bfloat16* cur = smem + (c & 1) * STAGE_ELE;
        const __nv_bfloat16* As_h = cur;
        const __nv_bfloat16* As_l = cur + MAT_ELE;
        const __nv_bfloat16* Bs_h = cur + 2 * MAT_ELE;
        const __nv_bfloat16* Bs_l = cur + 3 * MAT_ELE;

#pragma unroll
        for (int ks = 0; ks < 2; ks++) {
            int k0 = ks * 16 + tg * 2;
            uint32_t ah[2][4], al[2][4];
#pragma unroll
            for (int mt = 0; mt < 2; mt++) {
                int row = wm * 32 + mt * 16;
                ah[mt][0] = *(const uint32_t*)&As_h[(row + g) * KP + k0];
                ah[mt][1] = *(const uint32_t*)&As_h[(row + 8 + g) * KP + k0];
                ah[mt][2] = *(const uint32_t*)&As_h[(row + g) * KP + k0 + 8];
                ah[mt][3] = *(const uint32_t*)&As_h[(row + 8 + g) * KP + k0 + 8];
                al[mt][0] = *(const uint32_t*)&As_l[(row + g) * KP + k0];
                al[mt][1] = *(const uint32_t*)&As_l[(row + 8 + g) * KP + k0];
                al[mt][2] = *(const uint32_t*)&As_l[(row + g) * KP + k0 + 8];
                al[mt][3] = *(const uint32_t*)&As_l[(row + 8 + g) * KP + k0 + 8];
            }
#pragma unroll
            for (int nt = 0; nt < 8; nt++) {
                int rn = wn * 64 + nt * 8 + g;
                uint32_t bh[2], bl[2];
                bh[0] = *(const uint32_t*)&Bs_h[rn * KP + k0];
                bh[1] = *(const uint32_t*)&Bs_h[rn * KP + k0 + 8];
                bl[0] = *(const uint32_t*)&Bs_l[rn * KP + k0];
                bl[1] = *(const uint32_t*)&Bs_l[rn * KP + k0 + 8];
#pragma unroll
                for (int mt = 0; mt < 2; mt++) {
                    mma16816(acc[mt][nt], ah[mt], bh);
                    mma16816(acc[mt][nt], ah[mt], bl);
                    mma16816(acc[mt][nt], al[mt], bh);
                }
            }
        }
        __syncthreads();
    }

#pragma unroll
    for (int mt = 0; mt < 2; mt++) {
        int row = bm0 + wm * 32 + mt * 16;
#pragma unroll
        for (int nt = 0; nt < 8; nt++) {
            int coln = bn0 + wn * 64 + nt * 8 + tg * 2;
            float bx = bias[coln], by = bias[coln + 1];
            float v0 = acc[mt][nt][0] + bx;
            float v1 = acc[mt][nt][1] + by;
            float v2 = acc[mt][nt][2] + bx;
            float v3 = acc[mt][nt][3] + by;
            if (RELU) {
                v0 = fmaxf(v0, 0.f); v1 = fmaxf(v1, 0.f);
                v2 = fmaxf(v2, 0.f); v3 = fmaxf(v3, 0.f);
            }
            size_t o0 = (size_t)(row + g) * N + coln;
            size_t o1 = (size_t)(row + 8 + g) * N + coln;
            if (C) {
                float2 p0 = {v0, v1}, p1 = {v2, v3};
                *(float2*)&C[o0] = p0;
                *(float2*)&C[o1] = p1;
            }
            if (Oh) {
                uint32_t h0 = pack_bf2(v0, v1), h1 = pack_bf2(v2, v3);
                *(uint32_t*)&Oh[o0] = h0;
                *(uint32_t*)&Oh[o1] = h1;
                __nv_bfloat162 hp0 = *(__nv_bfloat162*)&h0;
                __nv_bfloat162 hp1 = *(__nv_bfloat162*)&h1;
                *(uint32_t*)&Ol[o0] = pack_bf2(v0 - __bfloat162float(hp0.x),
                                               v1 - __bfloat162float(hp0.y));
                *(uint32_t*)&Ol[o1] = pack_bf2(v2 - __bfloat162float(hp1.x),
                                               v3 - __bfloat162float(hp1.y));
            }
        }
    }
}

// ---------------- HMMA lse: column-wise (over queries) logsumexp of S = Q K^T / 8 ---
// grid (N/128 key tiles, H). K tile resident; stream Q tiles; S via hi/lo HMMA.
#define LKP 72
#define LMAT (128 * LKP)
#define LSE_FBASE (6 * LMAT * 2)                 // byte offset of float region
#define LSE_SMEM (LSE_FBASE + (128 * 5 * 2 + 256) * 4)
__global__ void __launch_bounds__(256) lse_hmma(
    const __nv_bfloat16* __restrict__ Qh_, const __nv_bfloat16* __restrict__ Ql_,
    const __nv_bfloat16* __restrict__ Kh_, const __nv_bfloat16* __restrict__ Kl_,
    float* __restrict__ lse) {
    __nv_bfloat16* smem = (__nv_bfloat16*)dynsm;
    uint32_t smb = smem_u32(dynsm);
    float* part_m = (float*)(dynsm + LSE_FBASE);   // [128][5]
    float* part_s = part_m + 128 * 5;              // [128][5]
    float* Ms = part_s + 128 * 5;                  // [128]
    float* Ls = Ms + 128;                          // [128]

    int h = blockIdx.y;
    int m0 = blockIdx.x * 128;
    const __nv_bfloat16* Kh = Kh_ + h * 64;
    const __nv_bfloat16* Kl = Kl_ + h * 64;
    const __nv_bfloat16* Qh = Qh_ + h * 64;
    const __nv_bfloat16* Ql = Ql_ + h * 64;

    int t = threadIdx.x;
    int warp = t >> 5, lane = t & 31;
    int wm = warp & 3, wn = warp >> 2;
    int g = lane >> 2, tg = lane & 3;

    // K tile (hi at mat0, lo at mat1): 2048 16B-chunks
#pragma unroll
    for (int r = 0; r < 8; r++) {
        int idx = t + 256 * r;
        int mat = idx >> 10, m = (idx >> 3) & 127, ck = idx & 7;
        const __nv_bfloat16* gp = (mat ? Kl : Kh) + (size_t)(m0 + m) * QSTR + ck * 8;
        uint32_t sa = smb + (uint32_t)((mat * LMAT + m * LKP + ck * 8) * 2);
        CPA16(sa, gp);
    }
    // Q tile stage s buffers at mats 2+2s (hi), 3+2s (lo)
    auto issueQ = [&](int q) {
        int s = q & 1;
#pragma unroll
        for (int r = 0; r < 8; r++) {
            int idx = t + 256 * r;
            int mat = idx >> 10, m = (idx >> 3) & 127, ck = idx & 7;
            const __nv_bfloat16* gp = (mat ? Ql : Qh) + (size_t)(q * 128 + m) * QSTR + ck * 8;
            uint32_t sa = smb + (uint32_t)(((2 + 2 * s + mat) * LMAT + m * LKP + ck * 8) * 2);
            CPA16(sa, gp);
        }
    };

    issueQ(0);
    CP_COMMIT();
    if (t < 128) { Ms[t] = -INFINITY; Ls[t] = 0.f; }

    const int nq = N_ / 128;
    for (int q = 0; q < nq; q++) {
        if (q + 1 < nq) {
            issueQ(q + 1);
            CP_COMMIT();
            CP_WAIT1();
        } else {
            CP_WAIT0();
        }
        __syncthreads();

        const __nv_bfloat16* Qsh = smem + (2 + 2 * (q & 1)) * LMAT;
        const __nv_bfloat16* Qsl = Qsh + LMAT;
        const __nv_bfloat16* Ksh = smem;
        const __nv_bfloat16* Ksl = smem + LMAT;

        float acc[2][8][4];
#pragma unroll
        for (int i = 0; i < 2; i++)
#pragma unroll
            for (int j = 0; j < 8; j++)
#pragma unroll
                for (int k = 0; k < 4; k++) acc[i][j][k] = 0.f;

#pragma unroll
        for (int ks = 0; ks < 4; ks++) {
            int k0 = ks * 16 + tg * 2;
            uint32_t ah[2][4], al[2][4];
#pragma unroll
            for (int mt = 0; mt < 2; mt++) {
                int row = wm * 32 + mt * 16;
                ah[mt][0] = *(const uint32_t*)&Qsh[(row + g) * LKP + k0];
                ah[mt][1] = *(const uint32_t*)&Qsh[(row + 8 + g) * LKP + k0];
                ah[mt][2] = *(const uint32_t*)&Qsh[(row + g) * LKP + k0 + 8];
                ah[mt][3] = *(const uint32_t*)&Qsh[(row + 8 + g) * LKP + k0 + 8];
                al[mt][0] = *(const uint32_t*)&Qsl[(row + g) * LKP + k0];
                al[mt][1] = *(const uint32_t*)&Qsl[(row + 8 + g) * LKP + k0];
                al[mt][2] = *(const uint32_t*)&Qsl[(row + g) * LKP + k0 + 8];
                al[mt][3] = *(const uint32_t*)&Qsl[(row + 8 + g) * LKP + k0 + 8];
            }
#pragma unroll
            for (int nt = 0; nt < 8; nt++) {
                int rn = wn * 64 + nt * 8 + g;
                uint32_t bh[2], bl[2];
                bh[0] = *(const uint32_t*)&Ksh[rn * LKP + k0];
                bh[1] = *(const uint32_t*)&Ksh[rn * LKP + k0 + 8];
                bl[0] = *(const uint32_t*)&Ksl[rn * LKP + k0];
                bl[1] = *(const uint32_t*)&Ksl[rn * LKP + k0 + 8];
#pragma unroll
                for (int mt = 0; mt < 2; mt++) {
                    mma16816(acc[mt][nt], ah[mt], bh);
                    mma16816(acc[mt][nt], ah[mt], bl);
                    mma16816(acc[mt][nt], al[mt], bh);
                }
            }
        }

        // column reductions: this warp covers 32 q-rows x 64 key-cols
        float cm[8][2], cs[8][2];
#pragma unroll
        for (int nt = 0; nt < 8; nt++) {
#pragma unroll
            for (int j = 0; j < 2; j++) {
                float v0 = acc[0][nt][j] * 0.125f;
                float v1 = acc[0][nt][j + 2] * 0.125f;
                float v2 = acc[1][nt][j] * 0.125f;
                float v3 = acc[1][nt][j + 2] * 0.125f;
                float m = fmaxf(fmaxf(v0, v1), fmaxf(v2, v3));
#pragma unroll
                for (int o = 4; o <= 16; o <<= 1)
                    m = fmaxf(m, __shfl_xor_sync(0xFFFFFFFFu, m, o));
                float s = expf(v0 - m) + expf(v1 - m) + expf(v2 - m) + expf(v3 - m);
#pragma unroll
                for (int o = 4; o <= 16; o <<= 1)
                    s += __shfl_xor_sync(0xFFFFFFFFu, s, o);
                cm[nt][j] = m;
                cs[nt][j] = s;
            }
        }
        if (g == 0) {
#pragma unroll
            for (int nt = 0; nt < 8; nt++) {
#pragma unroll
                for (int j = 0; j < 2; j++) {
                    int col = wn * 64 + nt * 8 + tg * 2 + j;
                    part_m[col * 5 + wm] = cm[nt][j];
                    part_s[col * 5 + wm] = cs[nt][j];
                }
            }
        }
        __syncthreads();
        if (t < 128) {
            float m4 = fmaxf(fmaxf(part_m[t * 5 + 0], part_m[t * 5 + 1]),
                             fmaxf(part_m[t * 5 + 2], part_m[t * 5 + 3]));
            float s4 = part_s[t * 5 + 0] * expf(part_m[t * 5 + 0] - m4) +
                       part_s[t * 5 + 1] * expf(part_m[t * 5 + 1] - m4) +
                       part_s[t * 5 + 2] * expf(part_m[t * 5 + 2] - m4) +
                       part_s[t * 5 + 3] * expf(part_m[t * 5 + 3] - m4);
            float M = Ms[t], Ll = Ls[t];
            float m2 = fmaxf(M, m4);
            Ls[t] = Ll * expf(M - m2) + s4 * expf(m4 - m2);
            Ms[t] = m2;
        }
        __syncthreads();
    }

    if (t < 128) lse[(size_t)h * N_ + m0 + t] = Ms[t] + logf(Ls[t]);
}

// ---------------- KtV[h] = K[h]^T V[h], lseV[h] = lse[h]^T V[h] ------------
__global__ void zero_ktv(float* __restrict__ KtV, float* __restrict__ lseV) {
    int i = blockIdx.x * 256 + threadIdx.x;
    if (i < H_ * DK_ * DV_) KtV[i] = 0.f;
    if (i < H_ * DV_) lseV[i] = 0.f;
}

__global__ void __launch_bounds__(256) ktv_kernel(const float* __restrict__ K,
                                                  const float* __restrict__ V,
                                                  const float* __restrict__ lse,
                                                  float* __restrict__ KtV,
                                                  float* __restrict__ lseV) {
    __shared__ float Ks[64][64];
    __shared__ float Vs[64][64];
    __shared__ float ls[64];
    int h = blockIdx.y;
    int k0 = blockIdx.x * 256;
    const float* Kh = K + h * 64;
    const float* Vh = V + h * 64;
    const float* lh = lse + (size_t)h * N_;
    int t = threadIdx.x;
    int ty = t >> 4, tx = t & 15;

    float c[4][4];
#pragma unroll
    for (int i = 0; i < 4; i++)
#pragma unroll
        for (int j = 0; j < 4; j++) c[i][j] = 0.f;
    float lv[4] = {0.f, 0.f, 0.f, 0.f};

    for (int kc = k0; kc < k0 + 256; kc += 64) {
#pragma unroll
        for (int r = 0; r < 4; r++) {
            int f = t + 256 * r;
            int row = f >> 4, c4 = f & 15;
            *(float4*)&Ks[row][c4 * 4] = *(const float4*)(Kh + (size_t)(kc + row) * QSTR + c4 * 4);
            *(float4*)&Vs[row][c4 * 4] = *(const float4*)(Vh + (size_t)(kc + row) * QSTR + c4 * 4);
        }
        if (t < 64) ls[t] = lh[kc + t];
        __syncthreads();
#pragma unroll 8
        for (int kk = 0; kk < 64; kk++) {
            float4 a = *(float4*)&Ks[kk][ty * 4];
            float4 b = *(float4*)&Vs[kk][tx * 4];
            float aa[4] = {a.x, a.y, a.z, a.w};
            float bb[4] = {b.x, b.y, b.z, b.w};
#pragma unroll
            for (int i = 0; i < 4; i++)
#pragma unroll
                for (int j = 0; j < 4; j++) c[i][j] += aa[i] * bb[j];
            if (ty == 0) {
                float l = ls[kk];
#pragma unroll
                for (int j = 0; j < 4; j++) lv[j] += l * bb[j];
            }
        }
        __syncthreads();
    }
#pragma unroll
    for (int i = 0; i < 4; i++)
#pragma unroll
        for (int j = 0; j < 4; j++)
            atomicAdd(&KtV[(size_t)h * DK_ * DV_ + (ty * 4 + i) * DV_ + tx * 4 + j], c[i][j]);
    if (ty == 0) {
#pragma unroll
        for (int j = 0; j < 4; j++) atomicAdd(&lseV[(size_t)h * DV_ + tx * 4 + j], lv[j]);
    }
}

// ---------------- SIMT sgemm (small per-head attn GEMM) with bf16 hi/lo out -------
__global__ void __launch_bounds__(256) sgemm_kernel(
    const float* __restrict__ A, const float* __restrict__ B,
    __nv_bfloat16* __restrict__ Oh, __nv_bfloat16* __restrict__ Ol,
    const float* __restrict__ colsub,
    int M, int Nc, int Kd, int lda, int ldb, int ldc,
    long sA, long sB, long sC, long sSub, float alpha) {
    __shared__ float As[16][132];
    __shared__ float Bs[16][64];

    int b = blockIdx.z;
    A += (size_t)b * sA;
    B += (size_t)b * sB;
    Oh += (size_t)b * sC;
    Ol += (size_t)b * sC;
    colsub += (size_t)b * sSub;

    int bm0 = blockIdx.y * 128;
    int bn0 = blockIdx.x * 64;
    int t = threadIdx.x;
    int row0 = (t >> 4) * 8;
    int col0 = (t & 15) * 4;

    float acc[8][4];
#pragma unroll
    for (int i = 0; i < 8; i++)
#pragma unroll
        for (int j = 0; j < 4; j++) acc[i][j] = 0.f;

    for (int kt = 0; kt < Kd; kt += 16) {
#pragma unroll
        for (int r = 0; r < 2; r++) {
            int f = t + 256 * r;
            int m = f >> 2, k4 = f & 3;
            float4 av = *(const float4*)(A + (size_t)(bm0 + m) * lda + kt + k4 * 4);
            As[k4 * 4 + 0][m] = av.x;
            As[k4 * 4 + 1][m] = av.y;
            As[k4 * 4 + 2][m] = av.z;
            As[k4 * 4 + 3][m] = av.w;
        }
        {
            int kb = t >> 4, c4 = t & 15;
            *(float4*)&Bs[kb][c4 * 4] =
                *(const float4*)(B + (size_t)(kt + kb) * ldb + bn0 + c4 * 4);
        }
        __syncthreads();
#pragma unroll
        for (int kk = 0; kk < 16; kk++) {
            float4 b0 = *(float4*)&Bs[kk][col0];
            float4 a0 = *(float4*)&As[kk][row0];
            float4 a1 = *(float4*)&As[kk][row0 + 4];
            float aa[8] = {a0.x, a0.y, a0.z, a0.w, a1.x, a1.y, a1.z, a1.w};
            float bb[4] = {b0.x, b0.y, b0.z, b0.w};
#pragma unroll
            for (int i = 0; i < 8; i++)
#pragma unroll
                for (int j = 0; j < 4; j++) acc[i][j] += aa[i] * bb[j];
        }
        __syncthreads();
    }

    float sub[4];
#pragma unroll
    for (int j = 0; j < 4; j++) sub[j] = colsub[bn0 + col0 + j];
#pragma unroll
    for (int i = 0; i < 8; i++) {
        float v[4];
#pragma unroll
        for (int j = 0; j < 4; j++) v[j] = alpha * acc[i][j] - sub[j];
        uint32_t h0 = pack_bf2(v[0], v[1]), h1 = pack_bf2(v[2], v[3]);
        __nv_bfloat162 hp0 = *(__nv_bfloat162*)&h0;
        __nv_bfloat162 hp1 = *(__nv_bfloat162*)&h1;
        uint32_t l0 = pack_bf2(v[0] - __bfloat162float(hp0.x), v[1] - __bfloat162float(hp0.y));
        uint32_t l1 = pack_bf2(v[2] - __bfloat162float(hp1.x), v[3] - __bfloat162float(hp1.y));
        size_t o = (size_t)(bm0 + row0 + i) * ldc + bn0 + col0;
        uint2 ph = {h0, h1}, pl = {l0, l1};
        *(uint2*)&Oh[o] = ph;
        *(uint2*)&Ol[o] = pl;
    }
}

// ---------------- layernorm (ddof=1) with fused bf16 hi/lo output ----------------
__global__ void __launch_bounds__(256) ln_kernel(const float* __restrict__ a,
                                                 const float* __restrict__ b,
                                                 const float* __restrict__ g,
                                                 const float* __restrict__ be,
                                                 float* __restrict__ out,
                                                 __nv_bfloat16* __restrict__ oh,
                                                 __nv_bfloat16* __restrict__ ol) {
    __shared__ float red[256];
    int n = blockIdx.x;
    int t = threadIdx.x;
    size_t base = (size_t)n * DM_;
    float x[4];
    float s = 0.f;
#pragma unroll
    for (int k = 0; k < 4; k++) {
        int d = t + k * 256;
        x[k] = a[base + d] + b[base + d];
        s += x[k];
    }
    red[t] = s;
    __syncthreads();
    for (int o = 128; o > 0; o >>= 1) {
        if (t < o) red[t] += red[t + o];
        __syncthreads();
    }
    float mean = red[0] * (1.f / (float)DM_);
    __syncthreads();
    float s2 = 0.f;
#pragma unroll
    for (int k = 0; k < 4; k++) {
        float d = x[k] - mean;
        s2 += d * d;
    }
    red[t] = s2;
    __syncthreads();
    for (int o = 128; o > 0; o >>= 1) {
        if (t < o) red[t] += red[t + o];
        __syncthreads();
    }
    float var = red[0] * (1.f / (float)(DM_ - 1));
    float invstd = 1.f / sqrtf(var);
#pragma unroll
    for (int k = 0; k < 4; k++) {
        int d = t + k * 256;
        float v = g[base + d] * invstd * (x[k] - mean) + be[base + d];
        out[base + d] = v;
        if (oh) {
            __nv_bfloat16 hv = __float2bfloat16(v);
            oh[base + d] = hv;
            ol[base + d] = __float2bfloat16(v - __bfloat162float(hv));
        }
    }
}

// ---------------- launch ----------------
extern "C" void kernel_launch(void* const* d_in, const int* in_sizes, int n_in,
                              void* d_out, int out_size) {
    (void)in_sizes; (void)n_in; (void)out_size;
    const int*   X   = (const int*)d_in[0];
    const float* emb = (const float*)d_in[1];
    const float* WQ  = (const float*)d_in[2];
    const float* bQ  = (const float*)d_in[3];
    const float* WK  = (const float*)d_in[4];
    const float* bK  = (const float*)d_in[5];
    const float* WV  = (const float*)d_in[6];
    const float* bV  = (const float*)d_in[7];
    const float* WO  = (const float*)d_in[8];
    const float* bO  = (const float*)d_in[9];
    const float* W1  = (const float*)d_in[10];
    const float* b1  = (const float*)d_in[11];
    const float* W2  = (const float*)d_in[12];
    const float* b2  = (const float*)d_in[13];
    const float* g1  = (const float*)d_in[14];
    const float* be1 = (const float*)d_in[15];
    const float* g2  = (const float*)d_in[16];
    const float* be2 = (const float*)d_in[17];
    float* out = (float*)d_out;

    float *h, *Q, *K, *V, *lse, *KtV, *lseV, *Z, *h2, *R;
    __nv_bfloat16 *hh, *hl, *Qh, *Ql, *Kh, *Kl, *h2h, *h2l, *ath, *atl, *F1h, *F1l, *Wth, *Wtl;
    cudaGetSymbolAddress((void**)&h, g_h);
    cudaGetSymbolAddress((void**)&Q, g_Q);
    cudaGetSymbolAddress((void**)&K, g_K);
    cudaGetSymbolAddress((void**)&V, g_V);
    cudaGetSymbolAddress((void**)&lse, g_lse);
    cudaGetSymbolAddress((void**)&KtV, g_KtV);
    cudaGetSymbolAddress((void**)&lseV, g_lseV);
    cudaGetSymbolAddress((void**)&Z, g_Z);
    cudaGetSymbolAddress((void**)&h2, g_h2);
    cudaGetSymbolAddress((void**)&R, g_R);
    cudaGetSymbolAddress((void**)&hh, g_hh);
    cudaGetSymbolAddress((void**)&hl, g_hl);
    cudaGetSymbolAddress((void**)&Qh, g_Qh);
    cudaGetSymbolAddress((void**)&Ql, g_Ql);
    cudaGetSymbolAddress((void**)&Kh, g_Kh);
    cudaGetSymbolAddress((void**)&Kl, g_Kl);
    cudaGetSymbolAddress((void**)&h2h, g_h2h);
    cudaGetSymbolAddress((void**)&h2l, g_h2l);
    cudaGetSymbolAddress((void**)&ath, g_ath);
    cudaGetSymbolAddress((void**)&atl, g_atl);
    cudaGetSymbolAddress((void**)&F1h, g_F1h);
    cudaGetSymbolAddress((void**)&F1l, g_F1l);
    cudaGetSymbolAddress((void**)&Wth, g_Wth);
    cudaGetSymbolAddress((void**)&Wtl, g_Wtl);

    cudaFuncSetAttribute(lse_hmma, cudaFuncAttributeMaxDynamicSharedMemorySize, LSE_SMEM);
    cudaFuncSetAttribute(hmma_gemm<false>, cudaFuncAttributeMaxDynamicSharedMemorySize, HG_SMEM);
    cudaFuncSetAttribute(hmma_gemm<true>, cudaFuncAttributeMaxDynamicSharedMemorySize, HG_SMEM);

    embed_kernel<<<N_, 256>>>(X, emb, h, hh, hl);

    for (int l = 0; l < L_; l++) {
        const float* WQl = WQ + (size_t)l * H_ * DM_ * DK_;
        const float* WKl = WK + (size_t)l * H_ * DM_ * DK_;
        const float* WVl = WV + (size_t)l * H_ * DM_ * DV_;
        const float* bQl = bQ + (size_t)l * H_ * DK_;
        const float* bKl = bK + (size_t)l * H_ * DK_;
        const float* bVl = bV + (size_t)l * H_ * DV_;
        const float* WOl = WO + (size_t)l * (H_ * DV_) * DM_;
        const float* bOl = bO + (size_t)l * DM_;
        const float* W1l = W1 + (size_t)l * DM_ * DFF_;
        const float* b1l = b1 + (size_t)l * DFF_;
        const float* W2l = W2 + (size_t)l * DFF_ * DM_;
        const float* b2l = b2 + (size_t)l * DM_;
        const float* g1l = g1 + (size_t)l * N_ * DM_;
        const float* be1l = be1 + (size_t)l * N_ * DM_;
        const float* g2l = g2 + (size_t)l * N_ * DM_;
        const float* be2l = be2 + (size_t)l * N_ * DM_;

        // ---- Q/K/V projections (Q,K also emit bf16 hi/lo for the lse kernel)
        cvtT_kernel<<<dim3(DM_ / 32, DK_ / 32, H_), dim3(32, 8)>>>(WQl, Wth, Wtl, DM_, DK_);
        hmma_gemm<false><<<dim3(QSTR / 128, N_ / 128), 256, HG_SMEM>>>(
            hh, hl, Wth, Wtl, Q, Qh, Ql, bQl, N_, QSTR, DM_);
        cvtT_kernel<<<dim3(DM_ / 32, DK_ / 32, H_), dim3(32, 8)>>>(WKl, Wth, Wtl, DM_, DK_);
        hmma_gemm<false><<<dim3(QSTR / 128, N_ / 128), 256, HG_SMEM>>>(
            hh, hl, Wth, Wtl, K, Kh, Kl, bKl, N_, QSTR, DM_);
        cvtT_kernel<<<dim3(DM_ / 32, DV_ / 32, H_), dim3(32, 8)>>>(WVl, Wth, Wtl, DM_, DV_);
        hmma_gemm<false><<<dim3(QSTR / 128, N_ / 128), 256, HG_SMEM>>>(
            hh, hl, Wth, Wtl, V, nullptr, nullptr, bVl, N_, QSTR, DM_);

        // ---- attention: HMMA lse over queries, then Q@(K^T V)/8 - lse^T V
        lse_hmma<<<dim3(N_ / 128, H_), 256, LSE_SMEM>>>(Qh, Ql, Kh, Kl, lse);
        zero_ktv<<<(H_ * DK_ * DV_ + 255) / 256, 256>>>(KtV, lseV);
        ktv_kernel<<<dim3(N_ / 256, H_), 256>>>(K, V, lse, KtV, lseV);
        sgemm_kernel<<<dim3(1, N_ / 128, H_), 256>>>(
            Q, KtV, ath, atl, lseV, N_, DV_, DK_, QSTR, DV_, DM_,
            64L, (long)DK_ * DV_, 64L, (long)DV_, 0.125f);

        // ---- Z = attn @ WO + bO
        cvtT_kernel<<<dim3((H_ * DV_) / 32, DM_ / 32, 1), dim3(32, 8)>>>(WOl, Wth, Wtl,
                                                                         H_ * DV_, DM_);
        hmma_gemm<false><<<dim3(DM_ / 128, N_ / 128), 256, HG_SMEM>>>(
            ath, atl, Wth, Wtl, Z, nullptr, nullptr, bOl, N_, DM_, DM_);

        // ---- h2 = LN(h + Z)
        ln_kernel<<<N_, 256>>>(h, Z, g1l, be1l, h2, h2h, h2l);

        // ---- F1 = relu(h2 @ W1 + b1) (bf16 hi/lo only)
        cvtT_kernel<<<dim3(DM_ / 32, DFF_ / 32, 1), dim3(32, 8)>>>(W1l, Wth, Wtl, DM_, DFF_);
        hmma_gemm<true><<<dim3(DFF_ / 128, N_ / 128), 256, HG_SMEM>>>(
            h2h, h2l, Wth, Wtl, nullptr, F1h, F1l, b1l, N_, DFF_, DM_);

        // ---- R = F1 @ W2 + b2
        cvtT_kernel<<<dim3(DFF_ / 32, DM_ / 32, 1), dim3(32, 8)>>>(W2l, Wth, Wtl, DFF_, DM_);
        hmma_gemm<false><<<dim3(DM_ / 128, N_ / 128), 256, HG_SMEM>>>(
            F1h, F1l, Wth, Wtl, R, nullptr, nullptr, b2l, N_, DM_, DFF_);

        // ---- h = LN(h2 + R)
        if (l == L_ - 1) {
            ln_kernel<<<N_, 256>>>(h2, R, g2l, be2l, out, nullptr, nullptr);
        } else {
            ln_kernel<<<N_, 256>>>(h2, R, g2l, be2l, h, hh, hl);
        }
    }
}

// round 9
// speedup vs baseline: 1.3488x; 1.3488x over previous
#include <cuda_runtime.h>
#include <cuda_bf16.h>
#include <math.h>
#include <stdint.h>

#define L_ 6
#define H_ 16
#define N_ 2048
#define DM_ 1024
#define DK_ 64
#define DV_ 64
#define DFF_ 4096
#define QSTR (H_ * DK_)   // 1024, interleaved Q/K/V row stride

// ---------------- helpers ----------------
__device__ __forceinline__ uint32_t smem_u32(const void* p) {
    uint32_t a;
    asm("{ .reg .u64 t; cvta.to.shared.u64 t, %1; cvt.u32.u64 %0, t; }" : "=r"(a) : "l"(p));
    return a;
}
#define CPA16(saddr, gptr) \
    asm volatile("cp.async.cg.shared.global [%0], [%1], 16;" :: "r"(saddr), "l"(gptr) : "memory")
#define CP_COMMIT() asm volatile("cp.async.commit_group;" ::: "memory")
#define CP_WAIT0()  asm volatile("cp.async.wait_group 0;" ::: "memory")
#define CP_WAIT1()  asm volatile("cp.async.wait_group 1;" ::: "memory")

#define LDSM4(r, a)                                                                     \
    asm volatile("ldmatrix.sync.aligned.m8n8.x4.shared.b16 {%0,%1,%2,%3}, [%4];"        \
                 : "=r"((r)[0]), "=r"((r)[1]), "=r"((r)[2]), "=r"((r)[3]) : "r"(a))

__device__ __forceinline__ void mma16816(float* c, const uint32_t* a, const uint32_t* b) {
    asm volatile(
        "mma.sync.aligned.m16n8k16.row.col.f32.bf16.bf16.f32 "
        "{%0,%1,%2,%3}, {%4,%5,%6,%7}, {%8,%9}, {%0,%1,%2,%3};"
        : "+f"(c[0]), "+f"(c[1]), "+f"(c[2]), "+f"(c[3])
        : "r"(a[0]), "r"(a[1]), "r"(a[2]), "r"(a[3]), "r"(b[0]), "r"(b[1]));
}

__device__ __forceinline__ uint32_t pack_bf2(float a, float b) {
    __nv_bfloat162 p = {__float2bfloat16(a), __float2bfloat16(b)};
    return *(uint32_t*)&p;
}

// ---------------- scratch ----------------
__device__ float g_h[N_ * DM_];
__device__ float g_Q[N_ * QSTR];
__device__ float g_K[N_ * QSTR];
__device__ float g_V[N_ * QSTR];
__device__ float g_lse[H_ * N_];
__device__ float g_KtV[H_ * DK_ * DV_];
__device__ float g_lseV[H_ * DV_];
__device__ float g_Z[N_ * DM_];
__device__ float g_h2[N_ * DM_];
__device__ float g_R[N_ * DM_];
__device__ __nv_bfloat16 g_hh[N_ * DM_], g_hl[N_ * DM_];
__device__ __nv_bfloat16 g_h2h[N_ * DM_], g_h2l[N_ * DM_];
__device__ __nv_bfloat16 g_ath[N_ * DM_], g_atl[N_ * DM_];
__device__ __nv_bfloat16 g_F1h[N_ * DFF_], g_F1l[N_ * DFF_];
__device__ __nv_bfloat16 g_Wth[DFF_ * DM_], g_Wtl[DFF_ * DM_];

// one shared extern dynamic smem symbol for ALL kernels
extern __shared__ char dynsm[];

// ---------------- embedding + positional encoding (fused bf16 split) -------------
__global__ void embed_kernel(const int* __restrict__ X, const float* __restrict__ emb,
                             float* __restrict__ h, __nv_bfloat16* __restrict__ oh,
                             __nv_bfloat16* __restrict__ ol) {
    int n = blockIdx.x;
    int t = threadIdx.x;
    const float* e = emb + (size_t)X[n] * DM_;
    float pos = (float)(n + 1);
#pragma unroll
    for (int k = 0; k < 2; k++) {
        int i = t + k * 256;
        float a = (float)(2 * i) / (float)DM_ * -9.210340371976184f;
        float f = expf(a);
        float tt = pos * f;
        float v0 = e[2 * i] + sinf(tt);
        float v1 = e[2 * i + 1] + cosf(tt);
        h[(size_t)n * DM_ + 2 * i] = v0;
        h[(size_t)n * DM_ + 2 * i + 1] = v1;
        __nv_bfloat16 h0 = __float2bfloat16(v0), h1 = __float2bfloat16(v1);
        oh[(size_t)n * DM_ + 2 * i] = h0;
        oh[(size_t)n * DM_ + 2 * i + 1] = h1;
        ol[(size_t)n * DM_ + 2 * i] = __float2bfloat16(v0 - __bfloat162float(h0));
        ol[(size_t)n * DM_ + 2 * i + 1] = __float2bfloat16(v1 - __bfloat162float(h1));
    }
}

// ---------------- batched transpose + split: in [B][K][Nb] -> out [B*Nb][K] -------
__global__ void cvtT_kernel(const float* __restrict__ in, __nv_bfloat16* __restrict__ oh,
                            __nv_bfloat16* __restrict__ ol, int K, int Nb) {
    __shared__ float tile[32][33];
    int b = blockIdx.z;
    int k0 = blockIdx.x * 32, n0 = blockIdx.y * 32;
    int tx = threadIdx.x, ty = threadIdx.y;
    const float* W = in + (size_t)b * K * Nb;
#pragma unroll
    for (int r = 0; r < 4; r++)
        tile[ty + 8 * r][tx] = W[(size_t)(k0 + ty + 8 * r) * Nb + n0 + tx];
    __syncthreads();
#pragma unroll
    for (int r = 0; r < 4; r++) {
        float a = tile[tx][ty + 8 * r];
        size_t o = (size_t)(b * Nb + n0 + ty + 8 * r) * K + k0 + tx;
        __nv_bfloat16 h = __float2bfloat16(a);
        oh[o] = h;
        ol[o] = __float2bfloat16(a - __bfloat162float(h));
    }
}

// ---------------- HMMA GEMM (ldmatrix fragments): C = A @ Bt^T + bias, opt relu ---
// hi/lo split: C = Ah*Bh + Ah*Bl + Al*Bh. fp32 out C XOR bf16 hi/lo out Oh/Ol.
#define BM 128
#define BN 128
#define BK 32
#define KP 40
#define MAT_ELE (BM * KP)
#define STAGE_ELE (4 * MAT_ELE)
#define HG_SMEM (2 * STAGE_ELE * 2)
template <bool RELU>
__global__ void __launch_bounds__(256) hmma_gemm(
    const __nv_bfloat16* __restrict__ Ah, const __nv_bfloat16* __restrict__ Al,
    const __nv_bfloat16* __restrict__ Bh, const __nv_bfloat16* __restrict__ Bl,
    float* __restrict__ C, __nv_bfloat16* __restrict__ Oh, __nv_bfloat16* __restrict__ Ol,
    const float* __restrict__ bias, int M, int N, int K) {
    uint32_t smb = smem_u32(dynsm);

    int t = threadIdx.x;
    int warp = t >> 5, lane = t & 31;
    int wm = warp & 3, wn = warp >> 2;
    int g = lane >> 2, tg = lane & 3;
    int bn0 = blockIdx.x * BN, bm0 = blockIdx.y * BM;

    const __nv_bfloat16* srcs[4] = {Ah, Al, Bh, Bl};
    int rowbase[4] = {bm0, bm0, bn0, bn0};

    // ldmatrix lane-address offsets (bytes, relative to matrix base)
    int lrow = lane & 15;
    int lko = (lane >> 4) * 8;
    uint32_t aoff = (uint32_t)(((wm * 32 + lrow) * KP + lko) * 2);
    int bn_off = (lane & 7) + ((lane >> 4) ? 8 : 0);
    int bk_off = ((lane >> 3) & 1) * 8;
    uint32_t boff = (uint32_t)(((wn * 64 + bn_off) * KP + bk_off) * 2);

    float acc[2][8][4];
#pragma unroll
    for (int i = 0; i < 2; i++)
#pragma unroll
        for (int j = 0; j < 8; j++)
#pragma unroll
            for (int k = 0; k < 4; k++) acc[i][j][k] = 0.f;

    const int nch = K / BK;

    auto issue = [&](int c) {
        uint32_t sb = smb + (uint32_t)((c & 1) * STAGE_ELE * 2);
#pragma unroll
        for (int mt = 0; mt < 4; mt++) {
#pragma unroll
            for (int r = 0; r < 2; r++) {
                int f = t + 256 * r;
                int m = f >> 2, ck = f & 3;
                const __nv_bfloat16* gp =
                    srcs[mt] + (size_t)(rowbase[mt] + m) * K + c * BK + ck * 8;
                uint32_t sa = sb + (uint32_t)((mt * MAT_ELE + m * KP + ck * 8) * 2);
                CPA16(sa, gp);
            }
        }
    };

    issue(0);
    CP_COMMIT();

    for (int c = 0; c < nch; c++) {
        if (c + 1 < nch) {
            issue(c + 1);
            CP_COMMIT();
            CP_WAIT1();
        } else {
            CP_WAIT0();
        }
        __syncthreads();

        uint32_t cb = smb + (uint32_t)((c & 1) * STAGE_ELE * 2);
        uint32_t aH = cb + aoff;
        uint32_t aL = cb + (uint32_t)(MAT_ELE * 2) + aoff;
        uint32_t bH = cb + (uint32_t)(2 * MAT_ELE * 2) + boff;
        uint32_t bL = cb + (uint32_t)(3 * MAT_ELE * 2) + boff;

#pragma unroll
        for (int ks = 0; ks < 2; ks++) {
            uint32_t koff = (uint32_t)(ks * 32);  // 16 bf16 = 32 bytes
            uint32_t ah[2][4], al[2][4];
#pragma unroll
            for (int mt = 0; mt < 2; mt++) {
                uint32_t ro = (uint32_t)(mt * 16 * KP * 2) + koff;
                LDSM4(ah[mt], aH + ro);
                LDSM4(al[mt], aL + ro);
            }
#pragma unroll
            for (int p = 0; p < 4; p++) {
                uint32_t po = (uint32_t)(p * 16 * KP * 2) + koff;
                uint32_t bh[4], bl[4];
                LDSM4(bh, bH + po);
                LDSM4(bl, bL + po);
#pragma unroll
                for (int mt = 0; mt < 2; mt++) {
                    mma16816(acc[mt][2 * p], ah[mt], bh);
                    mma16816(acc[mt][2 * p], ah[mt], bl);
                    mma16816(acc[mt][2 * p], al[mt], bh);
                    mma16816(acc[mt][2 * p + 1], ah[mt], bh + 2);
                    mma16816(acc[mt][2 * p + 1], ah[mt], bl + 2);
                    mma16816(acc[mt][2 * p + 1], al[mt], bh + 2);
                }
            }
        }
        __syncthreads();
    }

#pragma unroll
    for (int mt = 0; mt < 2; mt++) {
        int row = bm0 + wm * 32 + mt * 16;
#pragma unroll
        for (int nt = 0; nt < 8; nt++) {
            int coln = bn0 + wn * 64 + nt * 8 + tg * 2;
            float bx = bias[coln], by = bias[coln + 1];
            float v0 = acc[mt][nt][0] + bx;
            float v1 = acc[mt][nt][1] + by;
            float v2 = acc[mt][nt][2] + bx;
            float v3 = acc[mt][nt][3] + by;
            if (RELU) {
                v0 = fmaxf(v0, 0.f); v1 = fmaxf(v1, 0.f);
                v2 = fmaxf(v2, 0.f); v3 = fmaxf(v3, 0.f);
            }
            size_t o0 = (size_t)(row + g) * N + coln;
            size_t o1 = (size_t)(row + 8 + g) * N + coln;
            if (C) {
                float2 p0 = {v0, v1}, p1 = {v2, v3};
                *(float2*)&C[o0] = p0;
                *(float2*)&C[o1] = p1;
            } else {
                uint32_t h0 = pack_bf2(v0, v1), h1 = pack_bf2(v2, v3);
                *(uint32_t*)&Oh[o0] = h0;
                *(uint32_t*)&Oh[o1] = h1;
                __nv_bfloat162 hp0 = *(__nv_bfloat162*)&h0;
                __nv_bfloat162 hp1 = *(__nv_bfloat162*)&h1;
                *(uint32_t*)&Ol[o0] = pack_bf2(v0 - __bfloat162float(hp0.x),
                                               v1 - __bfloat162float(hp0.y));
                *(uint32_t*)&Ol[o1] = pack_bf2(v2 - __bfloat162float(hp1.x),
                                               v3 - __bfloat162float(hp1.y));
            }
        }
    }
}

// ---------------- column-wise (over queries) logsumexp of S = Q K^T / 8 (SIMT) -----
#define LSE_SMEM_FLOATS (2 * 64 * 132 + 2 * 128 * 17 + 256)
__global__ void __launch_bounds__(256) lse_kernel(const float* __restrict__ Q,
                                                  const float* __restrict__ K,
                                                  float* __restrict__ lse) {
    float* sm = (float*)dynsm;
    float* Ks = sm;
    float* Qs = Ks + 64 * 132;
    float* pm = Qs + 64 * 132;
    float* ps = pm + 128 * 17;
    float* Ms = ps + 128 * 17;
    float* Ls = Ms + 128;

    int h = blockIdx.y;
    int m0 = blockIdx.x * 128;
    const float* Kh = K + h * 64;
    const float* Qh = Q + h * 64;
    int t = threadIdx.x;

#pragma unroll
    for (int r = 0; r < 8; r++) {
        int f = t + 256 * r;
        int m = f >> 4, d4 = f & 15;
        float4 v = *(const float4*)(Kh + (size_t)(m0 + m) * QSTR + d4 * 4);
        Ks[(d4 * 4 + 0) * 132 + m] = v.x;
        Ks[(d4 * 4 + 1) * 132 + m] = v.y;
        Ks[(d4 * 4 + 2) * 132 + m] = v.z;
        Ks[(d4 * 4 + 3) * 132 + m] = v.w;
    }
    if (t < 128) { Ms[t] = -INFINITY; Ls[t] = 0.f; }
    __syncthreads();

    int ty = t >> 4, tx = t & 15;
    int row0 = ty * 8, col0 = tx * 8;

    for (int q0 = 0; q0 < N_; q0 += 128) {
#pragma unroll
        for (int r = 0; r < 8; r++) {
            int f = t + 256 * r;
            int m = f >> 4, d4 = f & 15;
            float4 v = *(const float4*)(Qh + (size_t)(q0 + m) * QSTR + d4 * 4);
            Qs[(d4 * 4 + 0) * 132 + m] = v.x;
            Qs[(d4 * 4 + 1) * 132 + m] = v.y;
            Qs[(d4 * 4 + 2) * 132 + m] = v.z;
            Qs[(d4 * 4 + 3) * 132 + m] = v.w;
        }
        __syncthreads();

        float c[8][8];
#pragma unroll
        for (int i = 0; i < 8; i++)
#pragma unroll
            for (int j = 0; j < 8; j++) c[i][j] = 0.f;

#pragma unroll 4
        for (int d = 0; d < 64; d++) {
            float4 a0 = *(float4*)&Qs[d * 132 + row0];
            float4 a1 = *(float4*)&Qs[d * 132 + row0 + 4];
            float4 b0 = *(float4*)&Ks[d * 132 + col0];
            float4 b1 = *(float4*)&Ks[d * 132 + col0 + 4];
            float aa[8] = {a0.x, a0.y, a0.z, a0.w, a1.x, a1.y, a1.z, a1.w};
            float bb[8] = {b0.x, b0.y, b0.z, b0.w, b1.x, b1.y, b1.z, b1.w};
#pragma unroll
            for (int i = 0; i < 8; i++)
#pragma unroll
                for (int j = 0; j < 8; j++) c[i][j] += aa[i] * bb[j];
        }

#pragma unroll
        for (int j = 0; j < 8; j++) {
            float mx = -INFINITY;
#pragma unroll
            for (int i = 0; i < 8; i++) mx = fmaxf(mx, c[i][j] * 0.125f);
            float s = 0.f;
#pragma unroll
            for (int i = 0; i < 8; i++) s += expf(c[i][j] * 0.125f - mx);
            pm[(col0 + j) * 17 + ty] = mx;
            ps[(col0 + j) * 17 + ty] = s;
        }
        __syncthreads();

        if (t < 128) {
            float M = Ms[t], Ll = Ls[t];
#pragma unroll
            for (int g = 0; g < 16; g++) {
                float m2 = fmaxf(M, pm[t * 17 + g]);
                Ll = Ll * expf(M - m2) + ps[t * 17 + g] * expf(pm[t * 17 + g] - m2);
                M = m2;
            }
            Ms[t] = M;
            Ls[t] = Ll;
        }
        __syncthreads();
    }

    if (t < 128) lse[(size_t)h * N_ + m0 + t] = Ms[t] + logf(Ls[t]);
}

// ---------------- KtV[h] = K[h]^T V[h], lseV[h] = lse[h]^T V[h] ------------
__global__ void zero_ktv(float* __restrict__ KtV, float* __restrict__ lseV) {
    int i = blockIdx.x * 256 + threadIdx.x;
    if (i < H_ * DK_ * DV_) KtV[i] = 0.f;
    if (i < H_ * DV_) lseV[i] = 0.f;
}

__global__ void __launch_bounds__(256) ktv_kernel(const float* __restrict__ K,
                                                  const float* __restrict__ V,
                                                  const float* __restrict__ lse,
                                                  float* __restrict__ KtV,
                                                  float* __restrict__ lseV) {
    __shared__ float Ks[64][64];
    __shared__ float Vs[64][64];
    __shared__ float ls[64];
    int h = blockIdx.y;
    int k0 = blockIdx.x * 256;
    const float* Kh = K + h * 64;
    const float* Vh = V + h * 64;
    const float* lh = lse + (size_t)h * N_;
    int t = threadIdx.x;
    int ty = t >> 4, tx = t & 15;

    float c[4][4];
#pragma unroll
    for (int i = 0; i < 4; i++)
#pragma unroll
        for (int j = 0; j < 4; j++) c[i][j] = 0.f;
    float lv[4] = {0.f, 0.f, 0.f, 0.f};

    for (int kc = k0; kc < k0 + 256; kc += 64) {
#pragma unroll
        for (int r = 0; r < 4; r++) {
            int f = t + 256 * r;
            int row = f >> 4, c4 = f & 15;
            *(float4*)&Ks[row][c4 * 4] = *(const float4*)(Kh + (size_t)(kc + row) * QSTR + c4 * 4);
            *(float4*)&Vs[row][c4 * 4] = *(const float4*)(Vh + (size_t)(kc + row) * QSTR + c4 * 4);
        }
        if (t < 64) ls[t] = lh[kc + t];
        __syncthreads();
#pragma unroll 8
        for (int kk = 0; kk < 64; kk++) {
            float4 a = *(float4*)&Ks[kk][ty * 4];
            float4 b = *(float4*)&Vs[kk][tx * 4];
            float aa[4] = {a.x, a.y, a.z, a.w};
            float bb[4] = {b.x, b.y, b.z, b.w};
#pragma unroll
            for (int i = 0; i < 4; i++)
#pragma unroll
                for (int j = 0; j < 4; j++) c[i][j] += aa[i] * bb[j];
            if (ty == 0) {
                float l = ls[kk];
#pragma unroll
                for (int j = 0; j < 4; j++) lv[j] += l * bb[j];
            }
        }
        __syncthreads();
    }
#pragma unroll
    for (int i = 0; i < 4; i++)
#pragma unroll
        for (int j = 0; j < 4; j++)
            atomicAdd(&KtV[(size_t)h * DK_ * DV_ + (ty * 4 + i) * DV_ + tx * 4 + j], c[i][j]);
    if (ty == 0) {
#pragma unroll
        for (int j = 0; j < 4; j++) atomicAdd(&lseV[(size_t)h * DV_ + tx * 4 + j], lv[j]);
    }
}

// ---------------- SIMT sgemm (small per-head attn GEMM) with bf16 hi/lo out -------
__global__ void __launch_bounds__(256) sgemm_kernel(
    const float* __restrict__ A, const float* __restrict__ B,
    __nv_bfloat16* __restrict__ Oh, __nv_bfloat16* __restrict__ Ol,
    const float* __restrict__ colsub,
    int M, int Nc, int Kd, int lda, int ldb, int ldc,
    long sA, long sB, long sC, long sSub, float alpha) {
    __shared__ float As[16][132];
    __shared__ float Bs[16][64];

    int b = blockIdx.z;
    A += (size_t)b * sA;
    B += (size_t)b * sB;
    Oh += (size_t)b * sC;
    Ol += (size_t)b * sC;
    colsub += (size_t)b * sSub;

    int bm0 = blockIdx.y * 128;
    int bn0 = blockIdx.x * 64;
    int t = threadIdx.x;
    int row0 = (t >> 4) * 8;
    int col0 = (t & 15) * 4;

    float acc[8][4];
#pragma unroll
    for (int i = 0; i < 8; i++)
#pragma unroll
        for (int j = 0; j < 4; j++) acc[i][j] = 0.f;

    for (int kt = 0; kt < Kd; kt += 16) {
#pragma unroll
        for (int r = 0; r < 2; r++) {
            int f = t + 256 * r;
            int m = f >> 2, k4 = f & 3;
            float4 av = *(const float4*)(A + (size_t)(bm0 + m) * lda + kt + k4 * 4);
            As[k4 * 4 + 0][m] = av.x;
            As[k4 * 4 + 1][m] = av.y;
            As[k4 * 4 + 2][m] = av.z;
            As[k4 * 4 + 3][m] = av.w;
        }
        {
            int kb = t >> 4, c4 = t & 15;
            *(float4*)&Bs[kb][c4 * 4] =
                *(const float4*)(B + (size_t)(kt + kb) * ldb + bn0 + c4 * 4);
        }
        __syncthreads();
#pragma unroll
        for (int kk = 0; kk < 16; kk++) {
            float4 b0 = *(float4*)&Bs[kk][col0];
            float4 a0 = *(float4*)&As[kk][row0];
            float4 a1 = *(float4*)&As[kk][row0 + 4];
            float aa[8] = {a0.x, a0.y, a0.z, a0.w, a1.x, a1.y, a1.z, a1.w};
            float bb[4] = {b0.x, b0.y, b0.z, b0.w};
#pragma unroll
            for (int i = 0; i < 8; i++)
#pragma unroll
                for (int j = 0; j < 4; j++) acc[i][j] += aa[i] * bb[j];
        }
        __syncthreads();
    }

    float sub[4];
#pragma unroll
    for (int j = 0; j < 4; j++) sub[j] = colsub[bn0 + col0 + j];
#pragma unroll
    for (int i = 0; i < 8; i++) {
        float v[4];
#pragma unroll
        for (int j = 0; j < 4; j++) v[j] = alpha * acc[i][j] - sub[j];
        uint32_t h0 = pack_bf2(v[0], v[1]), h1 = pack_bf2(v[2], v[3]);
        __nv_bfloat162 hp0 = *(__nv_bfloat162*)&h0;
        __nv_bfloat162 hp1 = *(__nv_bfloat162*)&h1;
        uint32_t l0 = pack_bf2(v[0] - __bfloat162float(hp0.x), v[1] - __bfloat162float(hp0.y));
        uint32_t l1 = pack_bf2(v[2] - __bfloat162float(hp1.x), v[3] - __bfloat162float(hp1.y));
        size_t o = (size_t)(bm0 + row0 + i) * ldc + bn0 + col0;
        uint2 ph = {h0, h1}, pl = {l0, l1};
        *(uint2*)&Oh[o] = ph;
        *(uint2*)&Ol[o] = pl;
    }
}

// ---------------- layernorm (ddof=1) with fused bf16 hi/lo output ----------------
__global__ void __launch_bounds__(256) ln_kernel(const float* __restrict__ a,
                                                 const float* __restrict__ b,
                                                 const float* __restrict__ g,
                                                 const float* __restrict__ be,
                                                 float* __restrict__ out,
                                                 __nv_bfloat16* __restrict__ oh,
                                                 __nv_bfloat16* __restrict__ ol) {
    __shared__ float red[256];
    int n = blockIdx.x;
    int t = threadIdx.x;
    size_t base = (size_t)n * DM_;
    float x[4];
    float s = 0.f;
#pragma unroll
    for (int k = 0; k < 4; k++) {
        int d = t + k * 256;
        x[k] = a[base + d] + b[base + d];
        s += x[k];
    }
    red[t] = s;
    __syncthreads();
    for (int o = 128; o > 0; o >>= 1) {
        if (t < o) red[t] += red[t + o];
        __syncthreads();
    }
    float mean = red[0] * (1.f / (float)DM_);
    __syncthreads();
    float s2 = 0.f;
#pragma unroll
    for (int k = 0; k < 4; k++) {
        float d = x[k] - mean;
        s2 += d * d;
    }
    red[t] = s2;
    __syncthreads();
    for (int o = 128; o > 0; o >>= 1) {
        if (t < o) red[t] += red[t + o];
        __syncthreads();
    }
    float var = red[0] * (1.f / (float)(DM_ - 1));
    float invstd = 1.f / sqrtf(var);
#pragma unroll
    for (int k = 0; k < 4; k++) {
        int d = t + k * 256;
        float v = g[base + d] * invstd * (x[k] - mean) + be[base + d];
        out[base + d] = v;
        if (oh) {
            __nv_bfloat16 hv = __float2bfloat16(v);
            oh[base + d] = hv;
            ol[base + d] = __float2bfloat16(v - __bfloat162float(hv));
        }
    }
}

// ---------------- launch ----------------
extern "C" void kernel_launch(void* const* d_in, const int* in_sizes, int n_in,
                              void* d_out, int out_size) {
    (void)in_sizes; (void)n_in; (void)out_size;
    const int*   X   = (const int*)d_in[0];
    const float* emb = (const float*)d_in[1];
    const float* WQ  = (const float*)d_in[2];
    const float* bQ  = (const float*)d_in[3];
    const float* WK  = (const float*)d_in[4];
    const float* bK  = (const float*)d_in[5];
    const float* WV  = (const float*)d_in[6];
    const float* bV  = (const float*)d_in[7];
    const float* WO  = (const float*)d_in[8];
    const float* bO  = (const float*)d_in[9];
    const float* W1  = (const float*)d_in[10];
    const float* b1  = (const float*)d_in[11];
    const float* W2  = (const float*)d_in[12];
    const float* b2  = (const float*)d_in[13];
    const float* g1  = (const float*)d_in[14];
    const float* be1 = (const float*)d_in[15];
    const float* g2  = (const float*)d_in[16];
    const float* be2 = (const float*)d_in[17];
    float* out = (float*)d_out;

    float *h, *Q, *K, *V, *lse, *KtV, *lseV, *Z, *h2, *R;
    __nv_bfloat16 *hh, *hl, *h2h, *h2l, *ath, *atl, *F1h, *F1l, *Wth, *Wtl;
    cudaGetSymbolAddress((void**)&h, g_h);
    cudaGetSymbolAddress((void**)&Q, g_Q);
    cudaGetSymbolAddress((void**)&K, g_K);
    cudaGetSymbolAddress((void**)&V, g_V);
    cudaGetSymbolAddress((void**)&lse, g_lse);
    cudaGetSymbolAddress((void**)&KtV, g_KtV);
    cudaGetSymbolAddress((void**)&lseV, g_lseV);
    cudaGetSymbolAddress((void**)&Z, g_Z);
    cudaGetSymbolAddress((void**)&h2, g_h2);
    cudaGetSymbolAddress((void**)&R, g_R);
    cudaGetSymbolAddress((void**)&hh, g_hh);
    cudaGetSymbolAddress((void**)&hl, g_hl);
    cudaGetSymbolAddress((void**)&h2h, g_h2h);
    cudaGetSymbolAddress((void**)&h2l, g_h2l);
    cudaGetSymbolAddress((void**)&ath, g_ath);
    cudaGetSymbolAddress((void**)&atl, g_atl);
    cudaGetSymbolAddress((void**)&F1h, g_F1h);
    cudaGetSymbolAddress((void**)&F1l, g_F1l);
    cudaGetSymbolAddress((void**)&Wth, g_Wth);
    cudaGetSymbolAddress((void**)&Wtl, g_Wtl);

    cudaFuncSetAttribute(lse_kernel, cudaFuncAttributeMaxDynamicSharedMemorySize,
                         LSE_SMEM_FLOATS * 4);
    cudaFuncSetAttribute(hmma_gemm<false>, cudaFuncAttributeMaxDynamicSharedMemorySize, HG_SMEM);
    cudaFuncSetAttribute(hmma_gemm<true>, cudaFuncAttributeMaxDynamicSharedMemorySize, HG_SMEM);

    embed_kernel<<<N_, 256>>>(X, emb, h, hh, hl);

    for (int l = 0; l < L_; l++) {
        const float* WQl = WQ + (size_t)l * H_ * DM_ * DK_;
        const float* WKl = WK + (size_t)l * H_ * DM_ * DK_;
        const float* WVl = WV + (size_t)l * H_ * DM_ * DV_;
        const float* bQl = bQ + (size_t)l * H_ * DK_;
        const float* bKl = bK + (size_t)l * H_ * DK_;
        const float* bVl = bV + (size_t)l * H_ * DV_;
        const float* WOl = WO + (size_t)l * (H_ * DV_) * DM_;
        const float* bOl = bO + (size_t)l * DM_;
        const float* W1l = W1 + (size_t)l * DM_ * DFF_;
        const float* b1l = b1 + (size_t)l * DFF_;
        const float* W2l = W2 + (size_t)l * DFF_ * DM_;
        const float* b2l = b2 + (size_t)l * DM_;
        const float* g1l = g1 + (size_t)l * N_ * DM_;
        const float* be1l = be1 + (size_t)l * N_ * DM_;
        const float* g2l = g2 + (size_t)l * N_ * DM_;
        const float* be2l = be2 + (size_t)l * N_ * DM_;

        // ---- Q/K/V projections (fp32 out only; lse/ktv/sgemm consume fp32)
        cvtT_kernel<<<dim3(DM_ / 32, DK_ / 32, H_), dim3(32, 8)>>>(WQl, Wth, Wtl, DM_, DK_);
        hmma_gemm<false><<<dim3(QSTR / 128, N_ / 128), 256, HG_SMEM>>>(
            hh, hl, Wth, Wtl, Q, nullptr, nullptr, bQl, N_, QSTR, DM_);
        cvtT_kernel<<<dim3(DM_ / 32, DK_ / 32, H_), dim3(32, 8)>>>(WKl, Wth, Wtl, DM_, DK_);
        hmma_gemm<false><<<dim3(QSTR / 128, N_ / 128), 256, HG_SMEM>>>(
            hh, hl, Wth, Wtl, K, nullptr, nullptr, bKl, N_, QSTR, DM_);
        cvtT_kernel<<<dim3(DM_ / 32, DV_ / 32, H_), dim3(32, 8)>>>(WVl, Wth, Wtl, DM_, DV_);
        hmma_gemm<false><<<dim3(QSTR / 128, N_ / 128), 256, HG_SMEM>>>(
            hh, hl, Wth, Wtl, V, nullptr, nullptr, bVl, N_, QSTR, DM_);

        // ---- attention: SIMT lse over queries, then Q@(K^T V)/8 - lse^T V (bf16 out)
        lse_kernel<<<dim3(N_ / 128, H_), 256, LSE_SMEM_FLOATS * 4>>>(Q, K, lse);
        zero_ktv<<<(H_ * DK_ * DV_ + 255) / 256, 256>>>(KtV, lseV);
        ktv_kernel<<<dim3(N_ / 256, H_), 256>>>(K, V, lse, KtV, lseV);
        sgemm_kernel<<<dim3(1, N_ / 128, H_), 256>>>(
            Q, KtV, ath, atl, lseV, N_, DV_, DK_, QSTR, DV_, DM_,
            64L, (long)DK_ * DV_, 64L, (long)DV_, 0.125f);

        // ---- Z = attn @ WO + bO
        cvtT_kernel<<<dim3((H_ * DV_) / 32, DM_ / 32, 1), dim3(32, 8)>>>(WOl, Wth, Wtl,
                                                                         H_ * DV_, DM_);
        hmma_gemm<false><<<dim3(DM_ / 128, N_ / 128), 256, HG_SMEM>>>(
            ath, atl, Wth, Wtl, Z, nullptr, nullptr, bOl, N_, DM_, DM_);

        // ---- h2 = LN(h + Z)
        ln_kernel<<<N_, 256>>>(h, Z, g1l, be1l, h2, h2h, h2l);

        // ---- F1 = relu(h2 @ W1 + b1) (bf16 hi/lo out only)
        cvtT_kernel<<<dim3(DM_ / 32, DFF_ / 32, 1), dim3(32, 8)>>>(W1l, Wth, Wtl, DM_, DFF_);
        hmma_gemm<true><<<dim3(DFF_ / 128, N_ / 128), 256, HG_SMEM>>>(
            h2h, h2l, Wth, Wtl, nullptr, F1h, F1l, b1l, N_, DFF_, DM_);

        // ---- R = F1 @ W2 + b2
        cvtT_kernel<<<dim3(DFF_ / 32, DM_ / 32, 1), dim3(32, 8)>>>(W2l, Wth, Wtl, DFF_, DM_);
        hmma_gemm<false><<<dim3(DM_ / 128, N_ / 128), 256, HG_SMEM>>>(
            F1h, F1l, Wth, Wtl, R, nullptr, nullptr, b2l, N_, DM_, DFF_);

        // ---- h = LN(h2 + R)
        if (l == L_ - 1) {
            ln_kernel<<<N_, 256>>>(h2, R, g2l, be2l, out, nullptr, nullptr);
        } else {
            ln_kernel<<<N_, 256>>>(h2, R, g2l, be2l, h, hh, hl);
        }
    }
}

// round 11
// speedup vs baseline: 1.6111x; 1.1945x over previous
#include <cuda_runtime.h>
#include <cuda_bf16.h>
#include <math.h>
#include <stdint.h>

#define L_ 6
#define H_ 16
#define N_ 2048
#define DM_ 1024
#define DK_ 64
#define DV_ 64
#define DFF_ 4096
#define QSTR (H_ * DK_)   // 1024, interleaved Q/K/V row stride

// ---------------- helpers ----------------
__device__ __forceinline__ uint32_t smem_u32(const void* p) {
    uint32_t a;
    asm("{ .reg .u64 t; cvta.to.shared.u64 t, %1; cvt.u32.u64 %0, t; }" : "=r"(a) : "l"(p));
    return a;
}
#define CPA16(saddr, gptr) \
    asm volatile("cp.async.cg.shared.global [%0], [%1], 16;" :: "r"(saddr), "l"(gptr) : "memory")
#define CP_COMMIT() asm volatile("cp.async.commit_group;" ::: "memory")
#define CP_WAIT0()  asm volatile("cp.async.wait_group 0;" ::: "memory")
#define CP_WAIT1()  asm volatile("cp.async.wait_group 1;" ::: "memory")

#define LDSM4(r, a)                                                                     \
    asm volatile("ldmatrix.sync.aligned.m8n8.x4.shared.b16 {%0,%1,%2,%3}, [%4];"        \
                 : "=r"((r)[0]), "=r"((r)[1]), "=r"((r)[2]), "=r"((r)[3]) : "r"(a))

__device__ __forceinline__ void mma16816(float* c, const uint32_t* a, const uint32_t* b) {
    asm volatile(
        "mma.sync.aligned.m16n8k16.row.col.f32.bf16.bf16.f32 "
        "{%0,%1,%2,%3}, {%4,%5,%6,%7}, {%8,%9}, {%0,%1,%2,%3};"
        : "+f"(c[0]), "+f"(c[1]), "+f"(c[2]), "+f"(c[3])
        : "r"(a[0]), "r"(a[1]), "r"(a[2]), "r"(a[3]), "r"(b[0]), "r"(b[1]));
}

__device__ __forceinline__ uint32_t pack_bf2(float a, float b) {
    __nv_bfloat162 p = {__float2bfloat16(a), __float2bfloat16(b)};
    return *(uint32_t*)&p;
}

// ---------------- scratch ----------------
__device__ float g_h[N_ * DM_];
__device__ float g_Q[N_ * QSTR];
__device__ float g_K[N_ * QSTR];
__device__ float g_V[N_ * QSTR];
__device__ float g_lse[H_ * N_];
__device__ float g_KtV[H_ * DK_ * DV_];
__device__ float g_lseV[H_ * DV_];
__device__ float g_Z[N_ * DM_];
__device__ float g_h2[N_ * DM_];
__device__ float g_R[N_ * DM_];
__device__ __nv_bfloat16 g_hh[N_ * DM_], g_hl[N_ * DM_];
__device__ __nv_bfloat16 g_Qh[N_ * QSTR], g_Ql[N_ * QSTR];
__device__ __nv_bfloat16 g_Kh[N_ * QSTR], g_Kl[N_ * QSTR];
__device__ __nv_bfloat16 g_h2h[N_ * DM_], g_h2l[N_ * DM_];
__device__ __nv_bfloat16 g_ath[N_ * DM_], g_atl[N_ * DM_];
__device__ __nv_bfloat16 g_F1h[N_ * DFF_], g_F1l[N_ * DFF_];
__device__ __nv_bfloat16 g_Wth[DFF_ * DM_], g_Wtl[DFF_ * DM_];

// one shared extern dynamic smem symbol for ALL kernels
extern __shared__ char dynsm[];

// ---------------- embedding + positional encoding (fused bf16 split) -------------
__global__ void embed_kernel(const int* __restrict__ X, const float* __restrict__ emb,
                             float* __restrict__ h, __nv_bfloat16* __restrict__ oh,
                             __nv_bfloat16* __restrict__ ol) {
    int n = blockIdx.x;
    int t = threadIdx.x;
    const float* e = emb + (size_t)X[n] * DM_;
    float pos = (float)(n + 1);
#pragma unroll
    for (int k = 0; k < 2; k++) {
        int i = t + k * 256;
        float a = (float)(2 * i) / (float)DM_ * -9.210340371976184f;
        float f = expf(a);
        float tt = pos * f;
        float v0 = e[2 * i] + sinf(tt);
        float v1 = e[2 * i + 1] + cosf(tt);
        h[(size_t)n * DM_ + 2 * i] = v0;
        h[(size_t)n * DM_ + 2 * i + 1] = v1;
        __nv_bfloat16 h0 = __float2bfloat16(v0), h1 = __float2bfloat16(v1);
        oh[(size_t)n * DM_ + 2 * i] = h0;
        oh[(size_t)n * DM_ + 2 * i + 1] = h1;
        ol[(size_t)n * DM_ + 2 * i] = __float2bfloat16(v0 - __bfloat162float(h0));
        ol[(size_t)n * DM_ + 2 * i + 1] = __float2bfloat16(v1 - __bfloat162float(h1));
    }
}

// ---------------- batched transpose + split: in [B][K][Nb] -> out [B*Nb][K] -------
__global__ void cvtT_kernel(const float* __restrict__ in, __nv_bfloat16* __restrict__ oh,
                            __nv_bfloat16* __restrict__ ol, int K, int Nb) {
    __shared__ float tile[32][33];
    int b = blockIdx.z;
    int k0 = blockIdx.x * 32, n0 = blockIdx.y * 32;
    int tx = threadIdx.x, ty = threadIdx.y;
    const float* W = in + (size_t)b * K * Nb;
#pragma unroll
    for (int r = 0; r < 4; r++)
        tile[ty + 8 * r][tx] = W[(size_t)(k0 + ty + 8 * r) * Nb + n0 + tx];
    __syncthreads();
#pragma unroll
    for (int r = 0; r < 4; r++) {
        float a = tile[tx][ty + 8 * r];
        size_t o = (size_t)(b * Nb + n0 + ty + 8 * r) * K + k0 + tx;
        __nv_bfloat16 h = __float2bfloat16(a);
        oh[o] = h;
        ol[o] = __float2bfloat16(a - __bfloat162float(h));
    }
}

// ---------------- HMMA GEMM (ldmatrix fragments): C = A @ Bt^T + bias, opt relu ---
// hi/lo split: C = Ah*Bh + Ah*Bl + Al*Bh. fp32 out C and/or bf16 hi/lo out Oh/Ol.
#define BM 128
#define BN 128
#define BK 32
#define KP 40
#define MAT_ELE (BM * KP)
#define STAGE_ELE (4 * MAT_ELE)
#define HG_SMEM (2 * STAGE_ELE * 2)
template <bool RELU>
__global__ void __launch_bounds__(256) hmma_gemm(
    const __nv_bfloat16* __restrict__ Ah, const __nv_bfloat16* __restrict__ Al,
    const __nv_bfloat16* __restrict__ Bh, const __nv_bfloat16* __restrict__ Bl,
    float* __restrict__ C, __nv_bfloat16* __restrict__ Oh, __nv_bfloat16* __restrict__ Ol,
    const float* __restrict__ bias, int M, int N, int K) {
    uint32_t smb = smem_u32(dynsm);

    int t = threadIdx.x;
    int warp = t >> 5, lane = t & 31;
    int wm = warp & 3, wn = warp >> 2;
    int g = lane >> 2, tg = lane & 3;
    int bn0 = blockIdx.x * BN, bm0 = blockIdx.y * BM;

    const __nv_bfloat16* srcs[4] = {Ah, Al, Bh, Bl};
    int rowbase[4] = {bm0, bm0, bn0, bn0};

    int lrow = lane & 15;
    int lko = (lane >> 4) * 8;
    uint32_t aoff = (uint32_t)(((wm * 32 + lrow) * KP + lko) * 2);
    int bn_off = (lane & 7) + ((lane >> 4) ? 8 : 0);
    int bk_off = ((lane >> 3) & 1) * 8;
    uint32_t boff = (uint32_t)(((wn * 64 + bn_off) * KP + bk_off) * 2);

    float acc[2][8][4];
#pragma unroll
    for (int i = 0; i < 2; i++)
#pragma unroll
        for (int j = 0; j < 8; j++)
#pragma unroll
            for (int k = 0; k < 4; k++) acc[i][j][k] = 0.f;

    const int nch = K / BK;

    auto issue = [&](int c) {
        uint32_t sb = smb + (uint32_t)((c & 1) * STAGE_ELE * 2);
#pragma unroll
        for (int mt = 0; mt < 4; mt++) {
#pragma unroll
            for (int r = 0; r < 2; r++) {
                int f = t + 256 * r;
                int m = f >> 2, ck = f & 3;
                const __nv_bfloat16* gp =
                    srcs[mt] + (size_t)(rowbase[mt] + m) * K + c * BK + ck * 8;
                uint32_t sa = sb + (uint32_t)((mt * MAT_ELE + m * KP + ck * 8) * 2);
                CPA16(sa, gp);
            }
        }
    };

    issue(0);
    CP_COMMIT();

    for (int c = 0; c < nch; c++) {
        if (c + 1 < nch) {
            issue(c + 1);
            CP_COMMIT();
            CP_WAIT1();
        } else {
            CP_WAIT0();
        }
        __syncthreads();

        uint32_t cb = smb + (uint32_t)((c & 1) * STAGE_ELE * 2);
        uint32_t aH = cb + aoff;
        uint32_t aL = cb + (uint32_t)(MAT_ELE * 2) + aoff;
        uint32_t bH = cb + (uint32_t)(2 * MAT_ELE * 2) + boff;
        uint32_t bL = cb + (uint32_t)(3 * MAT_ELE * 2) + boff;

#pragma unroll
        for (int ks = 0; ks < 2; ks++) {
            uint32_t koff = (uint32_t)(ks * 32);
            uint32_t ah[2][4], al[2][4];
#pragma unroll
            for (int mt = 0; mt < 2; mt++) {
                uint32_t ro = (uint32_t)(mt * 16 * KP * 2) + koff;
                LDSM4(ah[mt], aH + ro);
                LDSM4(al[mt], aL + ro);
            }
#pragma unroll
            for (int p = 0; p < 4; p++) {
                uint32_t po = (uint32_t)(p * 16 * KP * 2) + koff;
                uint32_t bh[4], bl[4];
                LDSM4(bh, bH + po);
                LDSM4(bl, bL + po);
#pragma unroll
                for (int mt = 0; mt < 2; mt++) {
                    mma16816(acc[mt][2 * p], ah[mt], bh);
                    mma16816(acc[mt][2 * p], ah[mt], bl);
                    mma16816(acc[mt][2 * p], al[mt], bh);
                    mma16816(acc[mt][2 * p + 1], ah[mt], bh + 2);
                    mma16816(acc[mt][2 * p + 1], ah[mt], bl + 2);
                    mma16816(acc[mt][2 * p + 1], al[mt], bh + 2);
                }
            }
        }
        __syncthreads();
    }

#pragma unroll
    for (int mt = 0; mt < 2; mt++) {
        int row = bm0 + wm * 32 + mt * 16;
#pragma unroll
        for (int nt = 0; nt < 8; nt++) {
            int coln = bn0 + wn * 64 + nt * 8 + tg * 2;
            float bx = bias[coln], by = bias[coln + 1];
            float v0 = acc[mt][nt][0] + bx;
            float v1 = acc[mt][nt][1] + by;
            float v2 = acc[mt][nt][2] + bx;
            float v3 = acc[mt][nt][3] + by;
            if (RELU) {
                v0 = fmaxf(v0, 0.f); v1 = fmaxf(v1, 0.f);
                v2 = fmaxf(v2, 0.f); v3 = fmaxf(v3, 0.f);
            }
            size_t o0 = (size_t)(row + g) * N + coln;
            size_t o1 = (size_t)(row + 8 + g) * N + coln;
            if (C) {
                float2 p0 = {v0, v1}, p1 = {v2, v3};
                *(float2*)&C[o0] = p0;
                *(float2*)&C[o1] = p1;
            }
            if (Oh) {
                uint32_t h0 = pack_bf2(v0, v1), h1 = pack_bf2(v2, v3);
                *(uint32_t*)&Oh[o0] = h0;
                *(uint32_t*)&Oh[o1] = h1;
                __nv_bfloat162 hp0 = *(__nv_bfloat162*)&h0;
                __nv_bfloat162 hp1 = *(__nv_bfloat162*)&h1;
                *(uint32_t*)&Ol[o0] = pack_bf2(v0 - __bfloat162float(hp0.x),
                                               v1 - __bfloat162float(hp0.y));
                *(uint32_t*)&Ol[o1] = pack_bf2(v2 - __bfloat162float(hp1.x),
                                               v3 - __bfloat162float(hp1.y));
            }
        }
    }
}

// ---------------- HMMA lse (transposed): T = K @ Q^T / 8, row-wise logsumexp -------
// grid (N/128 key tiles, H). K tile (128 keys) resident; stream 64-query tiles.
// Row reduction lives in one quad -> 2 shfls. 2 CTAs/SM (76.8KB smem).
#define LKP2 72
#define KMATB (128 * LKP2 * 2)          // 18432 B per K matrix
#define QMATB (64 * LKP2 * 2)           // 9216 B per Q matrix
#define LSE2_FBASE (2 * KMATB + 4 * QMATB)   // 73728
#define LSE2_SMEM (LSE2_FBASE + (128 * 2 * 2 + 256) * 4)
__global__ void __launch_bounds__(256) lse_hmma2(
    const __nv_bfloat16* __restrict__ Qh_, const __nv_bfloat16* __restrict__ Ql_,
    const __nv_bfloat16* __restrict__ Kh_, const __nv_bfloat16* __restrict__ Kl_,
    float* __restrict__ lse) {
    uint32_t smb = smem_u32(dynsm);
    float* part_m = (float*)(dynsm + LSE2_FBASE);   // [128][2]
    float* part_s = part_m + 128 * 2;               // [128][2]
    float* Ms = part_s + 128 * 2;                   // [128]
    float* Ls = Ms + 128;                           // [128]

    int h = blockIdx.y;
    int m0 = blockIdx.x * 128;
    const __nv_bfloat16* Kh = Kh_ + h * 64;
    const __nv_bfloat16* Kl = Kl_ + h * 64;
    const __nv_bfloat16* Qh = Qh_ + h * 64;
    const __nv_bfloat16* Ql = Ql_ + h * 64;

    int t = threadIdx.x;
    int warp = t >> 5, lane = t & 31;
    int wm = warp & 3, wn = warp >> 2;   // wm: 32-key slice, wn: 32-query slice
    int g = lane >> 2, tg = lane & 3;

    int lrow = lane & 15;
    int lko = (lane >> 4) * 8;
    uint32_t aoff = (uint32_t)(((wm * 32 + lrow) * LKP2 + lko) * 2);
    int bn_off = (lane & 7) + ((lane >> 4) ? 8 : 0);
    int bk_off = ((lane >> 3) & 1) * 8;
    uint32_t boff = (uint32_t)(((wn * 32 + bn_off) * LKP2 + bk_off) * 2);

    // K tile: 2048 16B chunks (hi mat 0, lo mat 1)
#pragma unroll
    for (int r = 0; r < 8; r++) {
        int idx = t + 256 * r;
        int mat = idx >> 10, rem = idx & 1023, m = rem >> 3, ck = rem & 7;
        const __nv_bfloat16* gp = (mat ? Kl : Kh) + (size_t)(m0 + m) * QSTR + ck * 8;
        uint32_t sa = smb + (uint32_t)(mat * KMATB + (m * LKP2 + ck * 8) * 2);
        CPA16(sa, gp);
    }
    // Q tile (64 rows): 1024 chunks per stage
    auto issueQ = [&](int q) {
        uint32_t qb = smb + (uint32_t)(2 * KMATB + (q & 1) * 2 * QMATB);
#pragma unroll
        for (int r = 0; r < 4; r++) {
            int idx = t + 256 * r;
            int mat = idx >> 9, rem = idx & 511, m = rem >> 3, ck = rem & 7;
            const __nv_bfloat16* gp = (mat ? Ql : Qh) + (size_t)(q * 64 + m) * QSTR + ck * 8;
            uint32_t sa = qb + (uint32_t)(mat * QMATB + (m * LKP2 + ck * 8) * 2);
            CPA16(sa, gp);
        }
    };

    issueQ(0);
    CP_COMMIT();
    if (t < 128) { Ms[t] = -INFINITY; Ls[t] = 0.f; }
    __syncthreads();

    const int nq = N_ / 64;
    for (int q = 0; q < nq; q++) {
        if (q + 1 < nq) {
            issueQ(q + 1);
            CP_COMMIT();
            CP_WAIT1();
        } else {
            CP_WAIT0();
        }
        __syncthreads();

        uint32_t aH = smb + aoff;
        uint32_t aL = smb + (uint32_t)KMATB + aoff;
        uint32_t qb = smb + (uint32_t)(2 * KMATB + (q & 1) * 2 * QMATB);
        uint32_t bH = qb + boff;
        uint32_t bL = qb + (uint32_t)QMATB + boff;

        float acc[2][4][4];
#pragma unroll
        for (int i = 0; i < 2; i++)
#pragma unroll
            for (int j = 0; j < 4; j++)
#pragma unroll
                for (int k = 0; k < 4; k++) acc[i][j][k] = 0.f;

#pragma unroll
        for (int ks = 0; ks < 4; ks++) {
            uint32_t koff = (uint32_t)(ks * 32);
            uint32_t ah[2][4], al[2][4];
#pragma unroll
            for (int mt = 0; mt < 2; mt++) {
                uint32_t ro = (uint32_t)(mt * 16 * LKP2 * 2) + koff;
                LDSM4(ah[mt], aH + ro);
                LDSM4(al[mt], aL + ro);
            }
#pragma unroll
            for (int p = 0; p < 2; p++) {
                uint32_t po = (uint32_t)(p * 16 * LKP2 * 2) + koff;
                uint32_t bh[4], bl[4];
                LDSM4(bh, bH + po);
                LDSM4(bl, bL + po);
#pragma unroll
                for (int mt = 0; mt < 2; mt++) {
                    mma16816(acc[mt][2 * p], ah[mt], bh);
                    mma16816(acc[mt][2 * p], ah[mt], bl);
                    mma16816(acc[mt][2 * p], al[mt], bh);
                    mma16816(acc[mt][2 * p + 1], ah[mt], bh + 2);
                    mma16816(acc[mt][2 * p + 1], ah[mt], bl + 2);
                    mma16816(acc[mt][2 * p + 1], al[mt], bh + 2);
                }
            }
        }

        // row-wise max & expsum over this warp's 32 queries (quad reduction)
#pragma unroll
        for (int mt = 0; mt < 2; mt++) {
#pragma unroll
            for (int half = 0; half < 2; half++) {
                float v[8];
#pragma unroll
                for (int nt = 0; nt < 4; nt++) {
                    v[2 * nt] = acc[mt][nt][half * 2] * 0.125f;
                    v[2 * nt + 1] = acc[mt][nt][half * 2 + 1] * 0.125f;
                }
                float m = v[0];
#pragma unroll
                for (int i = 1; i < 8; i++) m = fmaxf(m, v[i]);
                m = fmaxf(m, __shfl_xor_sync(0xFFFFFFFFu, m, 1));
                m = fmaxf(m, __shfl_xor_sync(0xFFFFFFFFu, m, 2));
                float s = 0.f;
#pragma unroll
                for (int i = 0; i < 8; i++) s += __expf(v[i] - m);
                s += __shfl_xor_sync(0xFFFFFFFFu, s, 1);
                s += __shfl_xor_sync(0xFFFFFFFFu, s, 2);
                if (tg == 0) {
                    int row = wm * 32 + mt * 16 + half * 8 + g;
                    part_m[row * 2 + wn] = m;
                    part_s[row * 2 + wn] = s;
                }
            }
        }
        __syncthreads();
        if (t < 128) {
            float ma = part_m[t * 2], mb = part_m[t * 2 + 1];
            float m2 = fmaxf(ma, mb);
            float s2 = part_s[t * 2] * __expf(ma - m2) + part_s[t * 2 + 1] * __expf(mb - m2);
            float M = Ms[t], Ll = Ls[t];
            float mn = fmaxf(M, m2);
            Ls[t] = Ll * __expf(M - mn) + s2 * __expf(m2 - mn);
            Ms[t] = mn;
        }
        __syncthreads();
    }

    if (t < 128) lse[(size_t)h * N_ + m0 + t] = Ms[t] + logf(Ls[t]);
}

// ---------------- KtV[h] = K[h]^T V[h], lseV[h] = lse[h]^T V[h] ------------
__global__ void zero_ktv(float* __restrict__ KtV, float* __restrict__ lseV) {
    int i = blockIdx.x * 256 + threadIdx.x;
    if (i < H_ * DK_ * DV_) KtV[i] = 0.f;
    if (i < H_ * DV_) lseV[i] = 0.f;
}

__global__ void __launch_bounds__(256) ktv_kernel(const float* __restrict__ K,
                                                  const float* __restrict__ V,
                                                  const float* __restrict__ lse,
                                                  float* __restrict__ KtV,
                                                  float* __restrict__ lseV) {
    __shared__ float Ks[64][64];
    __shared__ float Vs[64][64];
    __shared__ float ls[64];
    int h = blockIdx.y;
    int k0 = blockIdx.x * 256;
    const float* Kh = K + h * 64;
    const float* Vh = V + h * 64;
    const float* lh = lse + (size_t)h * N_;
    int t = threadIdx.x;
    int ty = t >> 4, tx = t & 15;

    float c[4][4];
#pragma unroll
    for (int i = 0; i < 4; i++)
#pragma unroll
        for (int j = 0; j < 4; j++) c[i][j] = 0.f;
    float lv[4] = {0.f, 0.f, 0.f, 0.f};

    for (int kc = k0; kc < k0 + 256; kc += 64) {
#pragma unroll
        for (int r = 0; r < 4; r++) {
            int f = t + 256 * r;
            int row = f >> 4, c4 = f & 15;
            *(float4*)&Ks[row][c4 * 4] = *(const float4*)(Kh + (size_t)(kc + row) * QSTR + c4 * 4);
            *(float4*)&Vs[row][c4 * 4] = *(const float4*)(Vh + (size_t)(kc + row) * QSTR + c4 * 4);
        }
        if (t < 64) ls[t] = lh[kc + t];
        __syncthreads();
#pragma unroll 8
        for (int kk = 0; kk < 64; kk++) {
            float4 a = *(float4*)&Ks[kk][ty * 4];
            float4 b = *(float4*)&Vs[kk][tx * 4];
            float aa[4] = {a.x, a.y, a.z, a.w};
            float bb[4] = {b.x, b.y, b.z, b.w};
#pragma unroll
            for (int i = 0; i < 4; i++)
#pragma unroll
                for (int j = 0; j < 4; j++) c[i][j] += aa[i] * bb[j];
            if (ty == 0) {
                float l = ls[kk];
#pragma unroll
                for (int j = 0; j < 4; j++) lv[j] += l * bb[j];
            }
        }
        __syncthreads();
    }
#pragma unroll
    for (int i = 0; i < 4; i++)
#pragma unroll
        for (int j = 0; j < 4; j++)
            atomicAdd(&KtV[(size_t)h * DK_ * DV_ + (ty * 4 + i) * DV_ + tx * 4 + j], c[i][j]);
    if (ty == 0) {
#pragma unroll
        for (int j = 0; j < 4; j++) atomicAdd(&lseV[(size_t)h * DV_ + tx * 4 + j], lv[j]);
    }
}

// ---------------- SIMT sgemm (small per-head attn GEMM) with bf16 hi/lo out -------
__global__ void __launch_bounds__(256) sgemm_kernel(
    const float* __restrict__ A, const float* __restrict__ B,
    __nv_bfloat16* __restrict__ Oh, __nv_bfloat16* __restrict__ Ol,
    const float* __restrict__ colsub,
    int M, int Nc, int Kd, int lda, int ldb, int ldc,
    long sA, long sB, long sC, long sSub, float alpha) {
    __shared__ float As[16][132];
    __shared__ float Bs[16][64];

    int b = blockIdx.z;
    A += (size_t)b * sA;
    B += (size_t)b * sB;
    Oh += (size_t)b * sC;
    Ol += (size_t)b * sC;
    colsub += (size_t)b * sSub;

    int bm0 = blockIdx.y * 128;
    int bn0 = blockIdx.x * 64;
    int t = threadIdx.x;
    int row0 = (t >> 4) * 8;
    int col0 = (t & 15) * 4;

    float acc[8][4];
#pragma unroll
    for (int i = 0; i < 8; i++)
#pragma unroll
        for (int j = 0; j < 4; j++) acc[i][j] = 0.f;

    for (int kt = 0; kt < Kd; kt += 16) {
#pragma unroll
        for (int r = 0; r < 2; r++) {
            int f = t + 256 * r;
            int m = f >> 2, k4 = f & 3;
            float4 av = *(const float4*)(A + (size_t)(bm0 + m) * lda + kt + k4 * 4);
            As[k4 * 4 + 0][m] = av.x;
            As[k4 * 4 + 1][m] = av.y;
            As[k4 * 4 + 2][m] = av.z;
            As[k4 * 4 + 3][m] = av.w;
        }
        {
            int kb = t >> 4, c4 = t & 15;
            *(float4*)&Bs[kb][c4 * 4] =
                *(const float4*)(B + (size_t)(kt + kb) * ldb + bn0 + c4 * 4);
        }
        __syncthreads();
#pragma unroll
        for (int kk = 0; kk < 16; kk++) {
            float4 b0 = *(float4*)&Bs[kk][col0];
            float4 a0 = *(float4*)&As[kk][row0];
            float4 a1 = *(float4*)&As[kk][row0 + 4];
            float aa[8] = {a0.x, a0.y, a0.z, a0.w, a1.x, a1.y, a1.z, a1.w};
            float bb[4] = {b0.x, b0.y, b0.z, b0.w};
#pragma unroll
            for (int i = 0; i < 8; i++)
#pragma unroll
                for (int j = 0; j < 4; j++) acc[i][j] += aa[i] * bb[j];
        }
        __syncthreads();
    }

    float sub[4];
#pragma unroll
    for (int j = 0; j < 4; j++) sub[j] = colsub[bn0 + col0 + j];
#pragma unroll
    for (int i = 0; i < 8; i++) {
        float v[4];
#pragma unroll
        for (int j = 0; j < 4; j++) v[j] = alpha * acc[i][j] - sub[j];
        uint32_t h0 = pack_bf2(v[0], v[1]), h1 = pack_bf2(v[2], v[3]);
        __nv_bfloat162 hp0 = *(__nv_bfloat162*)&h0;
        __nv_bfloat162 hp1 = *(__nv_bfloat162*)&h1;
        uint32_t l0 = pack_bf2(v[0] - __bfloat162float(hp0.x), v[1] - __bfloat162float(hp0.y));
        uint32_t l1 = pack_bf2(v[2] - __bfloat162float(hp1.x), v[3] - __bfloat162float(hp1.y));
        size_t o = (size_t)(bm0 + row0 + i) * ldc + bn0 + col0;
        uint2 ph = {h0, h1}, pl = {l0, l1};
        *(uint2*)&Oh[o] = ph;
        *(uint2*)&Ol[o] = pl;
    }
}

// ---------------- layernorm (ddof=1) with fused bf16 hi/lo output ----------------
__global__ void __launch_bounds__(256) ln_kernel(const float* __restrict__ a,
                                                 const float* __restrict__ b,
                                                 const float* __restrict__ g,
                                                 const float* __restrict__ be,
                                                 float* __restrict__ out,
                                                 __nv_bfloat16* __restrict__ oh,
                                                 __nv_bfloat16* __restrict__ ol) {
    __shared__ float red[256];
    int n = blockIdx.x;
    int t = threadIdx.x;
    size_t base = (size_t)n * DM_;
    float x[4];
    float s = 0.f;
#pragma unroll
    for (int k = 0; k < 4; k++) {
        int d = t + k * 256;
        x[k] = a[base + d] + b[base + d];
        s += x[k];
    }
    red[t] = s;
    __syncthreads();
    for (int o = 128; o > 0; o >>= 1) {
        if (t < o) red[t] += red[t + o];
        __syncthreads();
    }
    float mean = red[0] * (1.f / (float)DM_);
    __syncthreads();
    float s2 = 0.f;
#pragma unroll
    for (int k = 0; k < 4; k++) {
        float d = x[k] - mean;
        s2 += d * d;
    }
    red[t] = s2;
    __syncthreads();
    for (int o = 128; o > 0; o >>= 1) {
        if (t < o) red[t] += red[t + o];
        __syncthreads();
    }
    float var = red[0] * (1.f / (float)(DM_ - 1));
    float invstd = 1.f / sqrtf(var);
#pragma unroll
    for (int k = 0; k < 4; k++) {
        int d = t + k * 256;
        float v = g[base + d] * invstd * (x[k] - mean) + be[base + d];
        out[base + d] = v;
        if (oh) {
            __nv_bfloat16 hv = __float2bfloat16(v);
            oh[base + d] = hv;
            ol[base + d] = __float2bfloat16(v - __bfloat162float(hv));
        }
    }
}

// ---------------- launch ----------------
extern "C" void kernel_launch(void* const* d_in, const int* in_sizes, int n_in,
                              void* d_out, int out_size) {
    (void)in_sizes; (void)n_in; (void)out_size;
    const int*   X   = (const int*)d_in[0];
    const float* emb = (const float*)d_in[1];
    const float* WQ  = (const float*)d_in[2];
    const float* bQ  = (const float*)d_in[3];
    const float* WK  = (const float*)d_in[4];
    const float* bK  = (const float*)d_in[5];
    const float* WV  = (const float*)d_in[6];
    const float* bV  = (const float*)d_in[7];
    const float* WO  = (const float*)d_in[8];
    const float* bO  = (const float*)d_in[9];
    const float* W1  = (const float*)d_in[10];
    const float* b1  = (const float*)d_in[11];
    const float* W2  = (const float*)d_in[12];
    const float* b2  = (const float*)d_in[13];
    const float* g1  = (const float*)d_in[14];
    const float* be1 = (const float*)d_in[15];
    const float* g2  = (const float*)d_in[16];
    const float* be2 = (const float*)d_in[17];
    float* out = (float*)d_out;

    float *h, *Q, *K, *V, *lse, *KtV, *lseV, *Z, *h2, *R;
    __nv_bfloat16 *hh, *hl, *Qh, *Ql, *Kh, *Kl, *h2h, *h2l, *ath, *atl, *F1h, *F1l, *Wth, *Wtl;
    cudaGetSymbolAddress((void**)&h, g_h);
    cudaGetSymbolAddress((void**)&Q, g_Q);
    cudaGetSymbolAddress((void**)&K, g_K);
    cudaGetSymbolAddress((void**)&V, g_V);
    cudaGetSymbolAddress((void**)&lse, g_lse);
    cudaGetSymbolAddress((void**)&KtV, g_KtV);
    cudaGetSymbolAddress((void**)&lseV, g_lseV);
    cudaGetSymbolAddress((void**)&Z, g_Z);
    cudaGetSymbolAddress((void**)&h2, g_h2);
    cudaGetSymbolAddress((void**)&R, g_R);
    cudaGetSymbolAddress((void**)&hh, g_hh);
    cudaGetSymbolAddress((void**)&hl, g_hl);
    cudaGetSymbolAddress((void**)&Qh, g_Qh);
    cudaGetSymbolAddress((void**)&Ql, g_Ql);
    cudaGetSymbolAddress((void**)&Kh, g_Kh);
    cudaGetSymbolAddress((void**)&Kl, g_Kl);
    cudaGetSymbolAddress((void**)&h2h, g_h2h);
    cudaGetSymbolAddress((void**)&h2l, g_h2l);
    cudaGetSymbolAddress((void**)&ath, g_ath);
    cudaGetSymbolAddress((void**)&atl, g_atl);
    cudaGetSymbolAddress((void**)&F1h, g_F1h);
    cudaGetSymbolAddress((void**)&F1l, g_F1l);
    cudaGetSymbolAddress((void**)&Wth, g_Wth);
    cudaGetSymbolAddress((void**)&Wtl, g_Wtl);

    cudaFuncSetAttribute(lse_hmma2, cudaFuncAttributeMaxDynamicSharedMemorySize, LSE2_SMEM);
    cudaFuncSetAttribute(hmma_gemm<false>, cudaFuncAttributeMaxDynamicSharedMemorySize, HG_SMEM);
    cudaFuncSetAttribute(hmma_gemm<true>, cudaFuncAttributeMaxDynamicSharedMemorySize, HG_SMEM);

    embed_kernel<<<N_, 256>>>(X, emb, h, hh, hl);

    for (int l = 0; l < L_; l++) {
        const float* WQl = WQ + (size_t)l * H_ * DM_ * DK_;
        const float* WKl = WK + (size_t)l * H_ * DM_ * DK_;
        const float* WVl = WV + (size_t)l * H_ * DM_ * DV_;
        const float* bQl = bQ + (size_t)l * H_ * DK_;
        const float* bKl = bK + (size_t)l * H_ * DK_;
        const float* bVl = bV + (size_t)l * H_ * DV_;
        const float* WOl = WO + (size_t)l * (H_ * DV_) * DM_;
        const float* bOl = bO + (size_t)l * DM_;
        const float* W1l = W1 + (size_t)l * DM_ * DFF_;
        const float* b1l = b1 + (size_t)l * DFF_;
        const float* W2l = W2 + (size_t)l * DFF_ * DM_;
        const float* b2l = b2 + (size_t)l * DM_;
        const float* g1l = g1 + (size_t)l * N_ * DM_;
        const float* be1l = be1 + (size_t)l * N_ * DM_;
        const float* g2l = g2 + (size_t)l * N_ * DM_;
        const float* be2l = be2 + (size_t)l * N_ * DM_;

        // ---- Q/K/V projections (Q,K: fp32 + bf16 hi/lo; V: fp32 only)
        cvtT_kernel<<<dim3(DM_ / 32, DK_ / 32, H_), dim3(32, 8)>>>(WQl, Wth, Wtl, DM_, DK_);
        hmma_gemm<false><<<dim3(QSTR / 128, N_ / 128), 256, HG_SMEM>>>(
            hh, hl, Wth, Wtl, Q, Qh, Ql, bQl, N_, QSTR, DM_);
        cvtT_kernel<<<dim3(DM_ / 32, DK_ / 32, H_), dim3(32, 8)>>>(WKl, Wth, Wtl, DM_, DK_);
        hmma_gemm<false><<<dim3(QSTR / 128, N_ / 128), 256, HG_SMEM>>>(
            hh, hl, Wth, Wtl, K, Kh, Kl, bKl, N_, QSTR, DM_);
        cvtT_kernel<<<dim3(DM_ / 32, DV_ / 32, H_), dim3(32, 8)>>>(WVl, Wth, Wtl, DM_, DV_);
        hmma_gemm<false><<<dim3(QSTR / 128, N_ / 128), 256, HG_SMEM>>>(
            hh, hl, Wth, Wtl, V, nullptr, nullptr, bVl, N_, QSTR, DM_);

        // ---- attention: HMMA row-wise lse, then Q@(K^T V)/8 - lse^T V (bf16 out)
        lse_hmma2<<<dim3(N_ / 128, H_), 256, LSE2_SMEM>>>(Qh, Ql, Kh, Kl, lse);
        zero_ktv<<<(H_ * DK_ * DV_ + 255) / 256, 256>>>(KtV, lseV);
        ktv_kernel<<<dim3(N_ / 256, H_), 256>>>(K, V, lse, KtV, lseV);
        sgemm_kernel<<<dim3(1, N_ / 128, H_), 256>>>(
            Q, KtV, ath, atl, lseV, N_, DV_, DK_, QSTR, DV_, DM_,
            64L, (long)DK_ * DV_, 64L, (long)DV_, 0.125f);

        // ---- Z = attn @ WO + bO
        cvtT_kernel<<<dim3((H_ * DV_) / 32, DM_ / 32, 1), dim3(32, 8)>>>(WOl, Wth, Wtl,
                                                                         H_ * DV_, DM_);
        hmma_gemm<false><<<dim3(DM_ / 128, N_ / 128), 256, HG_SMEM>>>(
            ath, atl, Wth, Wtl, Z, nullptr, nullptr, bOl, N_, DM_, DM_);

        // ---- h2 = LN(h + Z)
        ln_kernel<<<N_, 256>>>(h, Z, g1l, be1l, h2, h2h, h2l);

        // ---- F1 = relu(h2 @ W1 + b1) (bf16 hi/lo out only)
        cvtT_kernel<<<dim3(DM_ / 32, DFF_ / 32, 1), dim3(32, 8)>>>(W1l, Wth, Wtl, DM_, DFF_);
        hmma_gemm<true><<<dim3(DFF_ / 128, N_ / 128), 256, HG_SMEM>>>(
            h2h, h2l, Wth, Wtl, nullptr, F1h, F1l, b1l, N_, DFF_, DM_);

        // ---- R = F1 @ W2 + b2
        cvtT_kernel<<<dim3(DFF_ / 32, DM_ / 32, 1), dim3(32, 8)>>>(W2l, Wth, Wtl, DFF_, DM_);
        hmma_gemm<false><<<dim3(DM_ / 128, N_ / 128), 256, HG_SMEM>>>(
            F1h, F1l, Wth, Wtl, R, nullptr, nullptr, b2l, N_, DM_, DFF_);

        // ---- h = LN(h2 + R)
        if (l == L_ - 1) {
            ln_kernel<<<N_, 256>>>(h2, R, g2l, be2l, out, nullptr, nullptr);
        } else {
            ln_kernel<<<N_, 256>>>(h2, R, g2l, be2l, h, hh, hl);
        }
    }
}

// round 12
// speedup vs baseline: 1.6209x; 1.0061x over previous
#include <cuda_runtime.h>
#include <cuda_bf16.h>
#include <math.h>
#include <stdint.h>

#define L_ 6
#define H_ 16
#define N_ 2048
#define DM_ 1024
#define DK_ 64
#define DV_ 64
#define DFF_ 4096
#define SSTR 3072   // combined QKV row stride

// ---------------- helpers ----------------
__device__ __forceinline__ uint32_t smem_u32(const void* p) {
    uint32_t a;
    asm("{ .reg .u64 t; cvta.to.shared.u64 t, %1; cvt.u32.u64 %0, t; }" : "=r"(a) : "l"(p));
    return a;
}
#define CPA16(saddr, gptr) \
    asm volatile("cp.async.cg.shared.global [%0], [%1], 16;" :: "r"(saddr), "l"(gptr) : "memory")
#define CP_COMMIT() asm volatile("cp.async.commit_group;" ::: "memory")
#define CP_WAIT0()  asm volatile("cp.async.wait_group 0;" ::: "memory")
#define CP_WAIT1()  asm volatile("cp.async.wait_group 1;" ::: "memory")

#define LDSM4(r, a)                                                                     \
    asm volatile("ldmatrix.sync.aligned.m8n8.x4.shared.b16 {%0,%1,%2,%3}, [%4];"        \
                 : "=r"((r)[0]), "=r"((r)[1]), "=r"((r)[2]), "=r"((r)[3]) : "r"(a))

__device__ __forceinline__ void mma16816(float* c, const uint32_t* a, const uint32_t* b) {
    asm volatile(
        "mma.sync.aligned.m16n8k16.row.col.f32.bf16.bf16.f32 "
        "{%0,%1,%2,%3}, {%4,%5,%6,%7}, {%8,%9}, {%0,%1,%2,%3};"
        : "+f"(c[0]), "+f"(c[1]), "+f"(c[2]), "+f"(c[3])
        : "r"(a[0]), "r"(a[1]), "r"(a[2]), "r"(a[3]), "r"(b[0]), "r"(b[1]));
}

__device__ __forceinline__ uint32_t pack_bf2(float a, float b) {
    __nv_bfloat162 p = {__float2bfloat16(a), __float2bfloat16(b)};
    return *(uint32_t*)&p;
}

// ---------------- scratch ----------------
__device__ float g_h[N_ * DM_];
__device__ float g_QKV[N_ * SSTR];
__device__ float g_lse[H_ * N_];
__device__ float g_KtV[H_ * DK_ * DV_];
__device__ float g_lseV[H_ * DV_];
__device__ float g_Z[N_ * DM_];
__device__ float g_h2[N_ * DM_];
__device__ float g_R[N_ * DM_];
__device__ float g_bQKV[L_ * SSTR];
__device__ __nv_bfloat16 g_hh[N_ * DM_], g_hl[N_ * DM_];
__device__ __nv_bfloat16 g_QKVh[N_ * SSTR], g_QKVl[N_ * SSTR];
__device__ __nv_bfloat16 g_h2h[N_ * DM_], g_h2l[N_ * DM_];
__device__ __nv_bfloat16 g_ath[N_ * DM_], g_atl[N_ * DM_];
__device__ __nv_bfloat16 g_F1h[N_ * DFF_], g_F1l[N_ * DFF_];
// pre-converted transposed weights, all layers
__device__ __nv_bfloat16 g_Wqkvh[L_ * SSTR * DM_], g_Wqkvl[L_ * SSTR * DM_];
__device__ __nv_bfloat16 g_WOth[L_ * DM_ * DM_],  g_WOtl[L_ * DM_ * DM_];
__device__ __nv_bfloat16 g_W1th[L_ * DFF_ * DM_], g_W1tl[L_ * DFF_ * DM_];
__device__ __nv_bfloat16 g_W2th[L_ * DM_ * DFF_], g_W2tl[L_ * DM_ * DFF_];

// one shared extern dynamic smem symbol for ALL kernels
extern __shared__ char dynsm[];

// ---------------- embedding + positional encoding (fused bf16 split) -------------
__global__ void embed_kernel(const int* __restrict__ X, const float* __restrict__ emb,
                             float* __restrict__ h, __nv_bfloat16* __restrict__ oh,
                             __nv_bfloat16* __restrict__ ol) {
    int n = blockIdx.x;
    int t = threadIdx.x;
    const float* e = emb + (size_t)X[n] * DM_;
    float pos = (float)(n + 1);
#pragma unroll
    for (int k = 0; k < 2; k++) {
        int i = t + k * 256;
        float a = (float)(2 * i) / (float)DM_ * -9.210340371976184f;
        float f = expf(a);
        float tt = pos * f;
        float v0 = e[2 * i] + sinf(tt);
        float v1 = e[2 * i + 1] + cosf(tt);
        h[(size_t)n * DM_ + 2 * i] = v0;
        h[(size_t)n * DM_ + 2 * i + 1] = v1;
        __nv_bfloat16 h0 = __float2bfloat16(v0), h1 = __float2bfloat16(v1);
        oh[(size_t)n * DM_ + 2 * i] = h0;
        oh[(size_t)n * DM_ + 2 * i + 1] = h1;
        ol[(size_t)n * DM_ + 2 * i] = __float2bfloat16(v0 - __bfloat162float(h0));
        ol[(size_t)n * DM_ + 2 * i + 1] = __float2bfloat16(v1 - __bfloat162float(h1));
    }
}

// ---- bias concat: bQKV[l][0:1024)=bQ, [1024:2048)=bK, [2048:3072)=bV ----
__global__ void pack_bias(const float* __restrict__ bQ, const float* __restrict__ bK,
                          const float* __restrict__ bV, float* __restrict__ o) {
    int i = blockIdx.x * 256 + threadIdx.x;
    if (i >= L_ * SSTR) return;
    int l = i / SSTR, c = i % SSTR;
    float v;
    if (c < 1024) v = bQ[l * 1024 + c];
    else if (c < 2048) v = bK[l * 1024 + c - 1024];
    else v = bV[l * 1024 + c - 2048];
    o[i] = v;
}

// ---------------- batched transpose + split: in [b][K][Nb] -> rows (b/perl)*lstride+(b%perl)*Nb+n
__global__ void cvtT_kernel(const float* __restrict__ in, __nv_bfloat16* __restrict__ oh,
                            __nv_bfloat16* __restrict__ ol, int K, int Nb,
                            int perl, int lstride) {
    __shared__ float tile[32][33];
    int b = blockIdx.z;
    size_t rowbase = (size_t)(b / perl) * lstride + (size_t)(b % perl) * Nb;
    int k0 = blockIdx.x * 32, n0 = blockIdx.y * 32;
    int tx = threadIdx.x, ty = threadIdx.y;
    const float* W = in + (size_t)b * K * Nb;
#pragma unroll
    for (int r = 0; r < 4; r++)
        tile[ty + 8 * r][tx] = W[(size_t)(k0 + ty + 8 * r) * Nb + n0 + tx];
    __syncthreads();
#pragma unroll
    for (int r = 0; r < 4; r++) {
        float a = tile[tx][ty + 8 * r];
        size_t o = (rowbase + n0 + ty + 8 * r) * K + k0 + tx;
        __nv_bfloat16 h = __float2bfloat16(a);
        oh[o] = h;
        ol[o] = __float2bfloat16(a - __bfloat162float(h));
    }
}

// ---------------- HMMA GEMM (ldmatrix fragments): C = A @ Bt^T + bias, opt relu ---
// hi/lo split: C = Ah*Bh + Ah*Bl + Al*Bh. fp32 out C and/or bf16 hi/lo out Oh/Ol.
#define BM 128
#define BN 128
#define BK 32
#define KP 40
#define MAT_ELE (BM * KP)
#define STAGE_ELE (4 * MAT_ELE)
#define HG_SMEM (2 * STAGE_ELE * 2)
template <bool RELU>
__global__ void __launch_bounds__(256) hmma_gemm(
    const __nv_bfloat16* __restrict__ Ah, const __nv_bfloat16* __restrict__ Al,
    const __nv_bfloat16* __restrict__ Bh, const __nv_bfloat16* __restrict__ Bl,
    float* __restrict__ C, __nv_bfloat16* __restrict__ Oh, __nv_bfloat16* __restrict__ Ol,
    const float* __restrict__ bias, int M, int N, int K) {
    uint32_t smb = smem_u32(dynsm);

    int t = threadIdx.x;
    int warp = t >> 5, lane = t & 31;
    int wm = warp & 3, wn = warp >> 2;
    int g = lane >> 2, tg = lane & 3;
    int bn0 = blockIdx.x * BN, bm0 = blockIdx.y * BM;

    const __nv_bfloat16* srcs[4] = {Ah, Al, Bh, Bl};
    int rowbase[4] = {bm0, bm0, bn0, bn0};

    int lrow = lane & 15;
    int lko = (lane >> 4) * 8;
    uint32_t aoff = (uint32_t)(((wm * 32 + lrow) * KP + lko) * 2);
    int bn_off = (lane & 7) + ((lane >> 4) ? 8 : 0);
    int bk_off = ((lane >> 3) & 1) * 8;
    uint32_t boff = (uint32_t)(((wn * 64 + bn_off) * KP + bk_off) * 2);

    float acc[2][8][4];
#pragma unroll
    for (int i = 0; i < 2; i++)
#pragma unroll
        for (int j = 0; j < 8; j++)
#pragma unroll
            for (int k = 0; k < 4; k++) acc[i][j][k] = 0.f;

    const int nch = K / BK;

    auto issue = [&](int c) {
        uint32_t sb = smb + (uint32_t)((c & 1) * STAGE_ELE * 2);
#pragma unroll
        for (int mt = 0; mt < 4; mt++) {
#pragma unroll
            for (int r = 0; r < 2; r++) {
                int f = t + 256 * r;
                int m = f >> 2, ck = f & 3;
                const __nv_bfloat16* gp =
                    srcs[mt] + (size_t)(rowbase[mt] + m) * K + c * BK + ck * 8;
                uint32_t sa = sb + (uint32_t)((mt * MAT_ELE + m * KP + ck * 8) * 2);
                CPA16(sa, gp);
            }
        }
    };

    issue(0);
    CP_COMMIT();

    for (int c = 0; c < nch; c++) {
        if (c + 1 < nch) {
            issue(c + 1);
            CP_COMMIT();
            CP_WAIT1();
        } else {
            CP_WAIT0();
        }
        __syncthreads();

        uint32_t cb = smb + (uint32_t)((c & 1) * STAGE_ELE * 2);
        uint32_t aH = cb + aoff;
        uint32_t aL = cb + (uint32_t)(MAT_ELE * 2) + aoff;
        uint32_t bH = cb + (uint32_t)(2 * MAT_ELE * 2) + boff;
        uint32_t bL = cb + (uint32_t)(3 * MAT_ELE * 2) + boff;

#pragma unroll
        for (int ks = 0; ks < 2; ks++) {
            uint32_t koff = (uint32_t)(ks * 32);
            uint32_t ah[2][4], al[2][4];
#pragma unroll
            for (int mt = 0; mt < 2; mt++) {
                uint32_t ro = (uint32_t)(mt * 16 * KP * 2) + koff;
                LDSM4(ah[mt], aH + ro);
                LDSM4(al[mt], aL + ro);
            }
#pragma unroll
            for (int p = 0; p < 4; p++) {
                uint32_t po = (uint32_t)(p * 16 * KP * 2) + koff;
                uint32_t bh[4], bl[4];
                LDSM4(bh, bH + po);
                LDSM4(bl, bL + po);
#pragma unroll
                for (int mt = 0; mt < 2; mt++) {
                    mma16816(acc[mt][2 * p], ah[mt], bh);
                    mma16816(acc[mt][2 * p], ah[mt], bl);
                    mma16816(acc[mt][2 * p], al[mt], bh);
                    mma16816(acc[mt][2 * p + 1], ah[mt], bh + 2);
                    mma16816(acc[mt][2 * p + 1], ah[mt], bl + 2);
                    mma16816(acc[mt][2 * p + 1], al[mt], bh + 2);
                }
            }
        }
        __syncthreads();
    }

#pragma unroll
    for (int mt = 0; mt < 2; mt++) {
        int row = bm0 + wm * 32 + mt * 16;
#pragma unroll
        for (int nt = 0; nt < 8; nt++) {
            int coln = bn0 + wn * 64 + nt * 8 + tg * 2;
            float bx = bias[coln], by = bias[coln + 1];
            float v0 = acc[mt][nt][0] + bx;
            float v1 = acc[mt][nt][1] + by;
            float v2 = acc[mt][nt][2] + bx;
            float v3 = acc[mt][nt][3] + by;
            if (RELU) {
                v0 = fmaxf(v0, 0.f); v1 = fmaxf(v1, 0.f);
                v2 = fmaxf(v2, 0.f); v3 = fmaxf(v3, 0.f);
            }
            size_t o0 = (size_t)(row + g) * N + coln;
            size_t o1 = (size_t)(row + 8 + g) * N + coln;
            if (C) {
                float2 p0 = {v0, v1}, p1 = {v2, v3};
                *(float2*)&C[o0] = p0;
                *(float2*)&C[o1] = p1;
            }
            if (Oh) {
                uint32_t h0 = pack_bf2(v0, v1), h1 = pack_bf2(v2, v3);
                *(uint32_t*)&Oh[o0] = h0;
                *(uint32_t*)&Oh[o1] = h1;
                __nv_bfloat162 hp0 = *(__nv_bfloat162*)&h0;
                __nv_bfloat162 hp1 = *(__nv_bfloat162*)&h1;
                *(uint32_t*)&Ol[o0] = pack_bf2(v0 - __bfloat162float(hp0.x),
                                               v1 - __bfloat162float(hp0.y));
                *(uint32_t*)&Ol[o1] = pack_bf2(v2 - __bfloat162float(hp1.x),
                                               v3 - __bfloat162float(hp1.y));
            }
        }
    }
}

// ---------------- HMMA lse (transposed): T = K @ Q^T / 8, row-wise logsumexp -------
#define LKP2 72
#define KMATB (128 * LKP2 * 2)
#define QMATB (64 * LKP2 * 2)
#define LSE2_FBASE (2 * KMATB + 4 * QMATB)
#define LSE2_SMEM (LSE2_FBASE + (128 * 2 * 2 + 256) * 4)
__global__ void __launch_bounds__(256) lse_hmma2(
    const __nv_bfloat16* __restrict__ Qh_, const __nv_bfloat16* __restrict__ Ql_,
    const __nv_bfloat16* __restrict__ Kh_, const __nv_bfloat16* __restrict__ Kl_,
    float* __restrict__ lse) {
    uint32_t smb = smem_u32(dynsm);
    float* part_m = (float*)(dynsm + LSE2_FBASE);
    float* part_s = part_m + 128 * 2;
    float* Ms = part_s + 128 * 2;
    float* Ls = Ms + 128;

    int h = blockIdx.y;
    int m0 = blockIdx.x * 128;
    const __nv_bfloat16* Kh = Kh_ + h * 64;
    const __nv_bfloat16* Kl = Kl_ + h * 64;
    const __nv_bfloat16* Qh = Qh_ + h * 64;
    const __nv_bfloat16* Ql = Ql_ + h * 64;

    int t = threadIdx.x;
    int warp = t >> 5, lane = t & 31;
    int wm = warp & 3, wn = warp >> 2;
    int g = lane >> 2, tg = lane & 3;

    int lrow = lane & 15;
    int lko = (lane >> 4) * 8;
    uint32_t aoff = (uint32_t)(((wm * 32 + lrow) * LKP2 + lko) * 2);
    int bn_off = (lane & 7) + ((lane >> 4) ? 8 : 0);
    int bk_off = ((lane >> 3) & 1) * 8;
    uint32_t boff = (uint32_t)(((wn * 32 + bn_off) * LKP2 + bk_off) * 2);

#pragma unroll
    for (int r = 0; r < 8; r++) {
        int idx = t + 256 * r;
        int mat = idx >> 10, rem = idx & 1023, m = rem >> 3, ck = rem & 7;
        const __nv_bfloat16* gp = (mat ? Kl : Kh) + (size_t)(m0 + m) * SSTR + ck * 8;
        uint32_t sa = smb + (uint32_t)(mat * KMATB + (m * LKP2 + ck * 8) * 2);
        CPA16(sa, gp);
    }
    auto issueQ = [&](int q) {
        uint32_t qb = smb + (uint32_t)(2 * KMATB + (q & 1) * 2 * QMATB);
#pragma unroll
        for (int r = 0; r < 4; r++) {
            int idx = t + 256 * r;
            int mat = idx >> 9, rem = idx & 511, m = rem >> 3, ck = rem & 7;
            const __nv_bfloat16* gp = (mat ? Ql : Qh) + (size_t)(q * 64 + m) * SSTR + ck * 8;
            uint32_t sa = qb + (uint32_t)(mat * QMATB + (m * LKP2 + ck * 8) * 2);
            CPA16(sa, gp);
        }
    };

    issueQ(0);
    CP_COMMIT();
    if (t < 128) { Ms[t] = -INFINITY; Ls[t] = 0.f; }
    __syncthreads();

    const int nq = N_ / 64;
    for (int q = 0; q < nq; q++) {
        if (q + 1 < nq) {
            issueQ(q + 1);
            CP_COMMIT();
            CP_WAIT1();
        } else {
            CP_WAIT0();
        }
        __syncthreads();

        uint32_t aH = smb + aoff;
        uint32_t aL = smb + (uint32_t)KMATB + aoff;
        uint32_t qb = smb + (uint32_t)(2 * KMATB + (q & 1) * 2 * QMATB);
        uint32_t bH = qb + boff;
        uint32_t bL = qb + (uint32_t)QMATB + boff;

        float acc[2][4][4];
#pragma unroll
        for (int i = 0; i < 2; i++)
#pragma unroll
            for (int j = 0; j < 4; j++)
#pragma unroll
                for (int k = 0; k < 4; k++) acc[i][j][k] = 0.f;

#pragma unroll
        for (int ks = 0; ks < 4; ks++) {
            uint32_t koff = (uint32_t)(ks * 32);
            uint32_t ah[2][4], al[2][4];
#pragma unroll
            for (int mt = 0; mt < 2; mt++) {
                uint32_t ro = (uint32_t)(mt * 16 * LKP2 * 2) + koff;
                LDSM4(ah[mt], aH + ro);
                LDSM4(al[mt], aL + ro);
            }
#pragma unroll
            for (int p = 0; p < 2; p++) {
                uint32_t po = (uint32_t)(p * 16 * LKP2 * 2) + koff;
                uint32_t bh[4], bl[4];
                LDSM4(bh, bH + po);
                LDSM4(bl, bL + po);
#pragma unroll
                for (int mt = 0; mt < 2; mt++) {
                    mma16816(acc[mt][2 * p], ah[mt], bh);
                    mma16816(acc[mt][2 * p], ah[mt], bl);
                    mma16816(acc[mt][2 * p], al[mt], bh);
                    mma16816(acc[mt][2 * p + 1], ah[mt], bh + 2);
                    mma16816(acc[mt][2 * p + 1], ah[mt], bl + 2);
                    mma16816(acc[mt][2 * p + 1], al[mt], bh + 2);
                }
            }
        }

#pragma unroll
        for (int mt = 0; mt < 2; mt++) {
#pragma unroll
            for (int half = 0; half < 2; half++) {
                float v[8];
#pragma unroll
                for (int nt = 0; nt < 4; nt++) {
                    v[2 * nt] = acc[mt][nt][half * 2] * 0.125f;
                    v[2 * nt + 1] = acc[mt][nt][half * 2 + 1] * 0.125f;
                }
                float m = v[0];
#pragma unroll
                for (int i = 1; i < 8; i++) m = fmaxf(m, v[i]);
                m = fmaxf(m, __shfl_xor_sync(0xFFFFFFFFu, m, 1));
                m = fmaxf(m, __shfl_xor_sync(0xFFFFFFFFu, m, 2));
                float s = 0.f;
#pragma unroll
                for (int i = 0; i < 8; i++) s += __expf(v[i] - m);
                s += __shfl_xor_sync(0xFFFFFFFFu, s, 1);
                s += __shfl_xor_sync(0xFFFFFFFFu, s, 2);
                if (tg == 0) {
                    int row = wm * 32 + mt * 16 + half * 8 + g;
                    part_m[row * 2 + wn] = m;
                    part_s[row * 2 + wn] = s;
                }
            }
        }
        __syncthreads();
        if (t < 128) {
            float ma = part_m[t * 2], mb = part_m[t * 2 + 1];
            float m2 = fmaxf(ma, mb);
            float s2 = part_s[t * 2] * __expf(ma - m2) + part_s[t * 2 + 1] * __expf(mb - m2);
            float M = Ms[t], Ll = Ls[t];
            float mn = fmaxf(M, m2);
            Ls[t] = Ll * __expf(M - mn) + s2 * __expf(m2 - mn);
            Ms[t] = mn;
        }
        __syncthreads();
    }

    if (t < 128) lse[(size_t)h * N_ + m0 + t] = Ms[t] + logf(Ls[t]);
}

// ---------------- KtV[h] = K[h]^T V[h], lseV[h] = lse[h]^T V[h] ------------
__global__ void zero_ktv(float* __restrict__ KtV, float* __restrict__ lseV) {
    int i = blockIdx.x * 256 + threadIdx.x;
    if (i < H_ * DK_ * DV_) KtV[i] = 0.f;
    if (i < H_ * DV_) lseV[i] = 0.f;
}

__global__ void __launch_bounds__(256) ktv_kernel(const float* __restrict__ K,
                                                  const float* __restrict__ V,
                                                  const float* __restrict__ lse,
                                                  float* __restrict__ KtV,
                                                  float* __restrict__ lseV) {
    __shared__ float Ks[64][64];
    __shared__ float Vs[64][64];
    __shared__ float ls[64];
    int h = blockIdx.y;
    int k0 = blockIdx.x * 256;
    const float* Kh = K + h * 64;
    const float* Vh = V + h * 64;
    const float* lh = lse + (size_t)h * N_;
    int t = threadIdx.x;
    int ty = t >> 4, tx = t & 15;

    float c[4][4];
#pragma unroll
    for (int i = 0; i < 4; i++)
#pragma unroll
        for (int j = 0; j < 4; j++) c[i][j] = 0.f;
    float lv[4] = {0.f, 0.f, 0.f, 0.f};

    for (int kc = k0; kc < k0 + 256; kc += 64) {
#pragma unroll
        for (int r = 0; r < 4; r++) {
            int f = t + 256 * r;
            int row = f >> 4, c4 = f & 15;
            *(float4*)&Ks[row][c4 * 4] = *(const float4*)(Kh + (size_t)(kc + row) * SSTR + c4 * 4);
            *(float4*)&Vs[row][c4 * 4] = *(const float4*)(Vh + (size_t)(kc + row) * SSTR + c4 * 4);
        }
        if (t < 64) ls[t] = lh[kc + t];
        __syncthreads();
#pragma unroll 8
        for (int kk = 0; kk < 64; kk++) {
            float4 a = *(float4*)&Ks[kk][ty * 4];
            float4 b = *(float4*)&Vs[kk][tx * 4];
            float aa[4] = {a.x, a.y, a.z, a.w};
            float bb[4] = {b.x, b.y, b.z, b.w};
#pragma unroll
            for (int i = 0; i < 4; i++)
#pragma unroll
                for (int j = 0; j < 4; j++) c[i][j] += aa[i] * bb[j];
            if (ty == 0) {
                float l = ls[kk];
#pragma unroll
                for (int j = 0; j < 4; j++) lv[j] += l * bb[j];
            }
        }
        __syncthreads();
    }
#pragma unroll
    for (int i = 0; i < 4; i++)
#pragma unroll
        for (int j = 0; j < 4; j++)
            atomicAdd(&KtV[(size_t)h * DK_ * DV_ + (ty * 4 + i) * DV_ + tx * 4 + j], c[i][j]);
    if (ty == 0) {
#pragma unroll
        for (int j = 0; j < 4; j++) atomicAdd(&lseV[(size_t)h * DV_ + tx * 4 + j], lv[j]);
    }
}

// ---------------- SIMT sgemm (small per-head attn GEMM) with bf16 hi/lo out -------
__global__ void __launch_bounds__(256) sgemm_kernel(
    const float* __restrict__ A, const float* __restrict__ B,
    __nv_bfloat16* __restrict__ Oh, __nv_bfloat16* __restrict__ Ol,
    const float* __restrict__ colsub,
    int M, int Nc, int Kd, int lda, int ldb, int ldc,
    long sA, long sB, long sC, long sSub, float alpha) {
    __shared__ float As[16][132];
    __shared__ float Bs[16][64];

    int b = blockIdx.z;
    A += (size_t)b * sA;
    B += (size_t)b * sB;
    Oh += (size_t)b * sC;
    Ol += (size_t)b * sC;
    colsub += (size_t)b * sSub;

    int bm0 = blockIdx.y * 128;
    int bn0 = blockIdx.x * 64;
    int t = threadIdx.x;
    int row0 = (t >> 4) * 8;
    int col0 = (t & 15) * 4;

    float acc[8][4];
#pragma unroll
    for (int i = 0; i < 8; i++)
#pragma unroll
        for (int j = 0; j < 4; j++) acc[i][j] = 0.f;

    for (int kt = 0; kt < Kd; kt += 16) {
#pragma unroll
        for (int r = 0; r < 2; r++) {
            int f = t + 256 * r;
            int m = f >> 2, k4 = f & 3;
            float4 av = *(const float4*)(A + (size_t)(bm0 + m) * lda + kt + k4 * 4);
            As[k4 * 4 + 0][m] = av.x;
            As[k4 * 4 + 1][m] = av.y;
            As[k4 * 4 + 2][m] = av.z;
            As[k4 * 4 + 3][m] = av.w;
        }
        {
            int kb = t >> 4, c4 = t & 15;
            *(float4*)&Bs[kb][c4 * 4] =
                *(const float4*)(B + (size_t)(kt + kb) * ldb + bn0 + c4 * 4);
        }
        __syncthreads();
#pragma unroll
        for (int kk = 0; kk < 16; kk++) {
            float4 b0 = *(float4*)&Bs[kk][col0];
            float4 a0 = *(float4*)&As[kk][row0];
            float4 a1 = *(float4*)&As[kk][row0 + 4];
            float aa[8] = {a0.x, a0.y, a0.z, a0.w, a1.x, a1.y, a1.z, a1.w};
            float bb[4] = {b0.x, b0.y, b0.z, b0.w};
#pragma unroll
            for (int i = 0; i < 8; i++)
#pragma unroll
                for (int j = 0; j < 4; j++) acc[i][j] += aa[i] * bb[j];
        }
        __syncthreads();
    }

    float sub[4];
#pragma unroll
    for (int j = 0; j < 4; j++) sub[j] = colsub[bn0 + col0 + j];
#pragma unroll
    for (int i = 0; i < 8; i++) {
        float v[4];
#pragma unroll
        for (int j = 0; j < 4; j++) v[j] = alpha * acc[i][j] - sub[j];
        uint32_t h0 = pack_bf2(v[0], v[1]), h1 = pack_bf2(v[2], v[3]);
        __nv_bfloat162 hp0 = *(__nv_bfloat162*)&h0;
        __nv_bfloat162 hp1 = *(__nv_bfloat162*)&h1;
        uint32_t l0 = pack_bf2(v[0] - __bfloat162float(hp0.x), v[1] - __bfloat162float(hp0.y));
        uint32_t l1 = pack_bf2(v[2] - __bfloat162float(hp1.x), v[3] - __bfloat162float(hp1.y));
        size_t o = (size_t)(bm0 + row0 + i) * ldc + bn0 + col0;
        uint2 ph = {h0, h1}, pl = {l0, l1};
        *(uint2*)&Oh[o] = ph;
        *(uint2*)&Ol[o] = pl;
    }
}

// ---------------- layernorm (ddof=1) with fused bf16 hi/lo output ----------------
__global__ void __launch_bounds__(256) ln_kernel(const float* __restrict__ a,
                                                 const float* __restrict__ b,
                                                 const float* __restrict__ g,
                                                 const float* __restrict__ be,
                                                 float* __restrict__ out,
                                                 __nv_bfloat16* __restrict__ oh,
                                                 __nv_bfloat16* __restrict__ ol) {
    __shared__ float red[256];
    int n = blockIdx.x;
    int t = threadIdx.x;
    size_t base = (size_t)n * DM_;
    float x[4];
    float s = 0.f;
#pragma unroll
    for (int k = 0; k < 4; k++) {
        int d = t + k * 256;
        x[k] = a[base + d] + b[base + d];
        s += x[k];
    }
    red[t] = s;
    __syncthreads();
    for (int o = 128; o > 0; o >>= 1) {
        if (t < o) red[t] += red[t + o];
        __syncthreads();
    }
    float mean = red[0] * (1.f / (float)DM_);
    __syncthreads();
    float s2 = 0.f;
#pragma unroll
    for (int k = 0; k < 4; k++) {
        float d = x[k] - mean;
        s2 += d * d;
    }
    red[t] = s2;
    __syncthreads();
    for (int o = 128; o > 0; o >>= 1) {
        if (t < o) red[t] += red[t + o];
        __syncthreads();
    }
    float var = red[0] * (1.f / (float)(DM_ - 1));
    float invstd = 1.f / sqrtf(var);
#pragma unroll
    for (int k = 0; k < 4; k++) {
        int d = t + k * 256;
        float v = g[base + d] * invstd * (x[k] - mean) + be[base + d];
        out[base + d] = v;
        if (oh) {
            __nv_bfloat16 hv = __float2bfloat16(v);
            oh[base + d] = hv;
            ol[base + d] = __float2bfloat16(v - __bfloat162float(hv));
        }
    }
}

// ---------------- launch ----------------
extern "C" void kernel_launch(void* const* d_in, const int* in_sizes, int n_in,
                              void* d_out, int out_size) {
    (void)in_sizes; (void)n_in; (void)out_size;
    const int*   X   = (const int*)d_in[0];
    const float* emb = (const float*)d_in[1];
    const float* WQ  = (const float*)d_in[2];
    const float* bQ  = (const float*)d_in[3];
    const float* WK  = (const float*)d_in[4];
    const float* bK  = (const float*)d_in[5];
    const float* WV  = (const float*)d_in[6];
    const float* bV  = (const float*)d_in[7];
    const float* WO  = (const float*)d_in[8];
    const float* bO  = (const float*)d_in[9];
    const float* W1  = (const float*)d_in[10];
    const float* b1  = (const float*)d_in[11];
    const float* W2  = (const float*)d_in[12];
    const float* b2  = (const float*)d_in[13];
    const float* g1  = (const float*)d_in[14];
    const float* be1 = (const float*)d_in[15];
    const float* g2  = (const float*)d_in[16];
    const float* be2 = (const float*)d_in[17];
    float* out = (float*)d_out;

    float *h, *QKV, *lse, *KtV, *lseV, *Z, *h2, *R, *bQKV;
    __nv_bfloat16 *hh, *hl, *QKVh, *QKVl, *h2h, *h2l, *ath, *atl, *F1h, *F1l;
    __nv_bfloat16 *Wqkvh, *Wqkvl, *WOth, *WOtl, *W1th, *W1tl, *W2th, *W2tl;
    cudaGetSymbolAddress((void**)&h, g_h);
    cudaGetSymbolAddress((void**)&QKV, g_QKV);
    cudaGetSymbolAddress((void**)&lse, g_lse);
    cudaGetSymbolAddress((void**)&KtV, g_KtV);
    cudaGetSymbolAddress((void**)&lseV, g_lseV);
    cudaGetSymbolAddress((void**)&Z, g_Z);
    cudaGetSymbolAddress((void**)&h2, g_h2);
    cudaGetSymbolAddress((void**)&R, g_R);
    cudaGetSymbolAddress((void**)&bQKV, g_bQKV);
    cudaGetSymbolAddress((void**)&hh, g_hh);
    cudaGetSymbolAddress((void**)&hl, g_hl);
    cudaGetSymbolAddress((void**)&QKVh, g_QKVh);
    cudaGetSymbolAddress((void**)&QKVl, g_QKVl);
    cudaGetSymbolAddress((void**)&h2h, g_h2h);
    cudaGetSymbolAddress((void**)&h2l, g_h2l);
    cudaGetSymbolAddress((void**)&ath, g_ath);
    cudaGetSymbolAddress((void**)&atl, g_atl);
    cudaGetSymbolAddress((void**)&F1h, g_F1h);
    cudaGetSymbolAddress((void**)&F1l, g_F1l);
    cudaGetSymbolAddress((void**)&Wqkvh, g_Wqkvh);
    cudaGetSymbolAddress((void**)&Wqkvl, g_Wqkvl);
    cudaGetSymbolAddress((void**)&WOth, g_WOth);
    cudaGetSymbolAddress((void**)&WOtl, g_WOtl);
    cudaGetSymbolAddress((void**)&W1th, g_W1th);
    cudaGetSymbolAddress((void**)&W1tl, g_W1tl);
    cudaGetSymbolAddress((void**)&W2th, g_W2th);
    cudaGetSymbolAddress((void**)&W2tl, g_W2tl);

    cudaFuncSetAttribute(lse_hmma2, cudaFuncAttributeMaxDynamicSharedMemorySize, LSE2_SMEM);
    cudaFuncSetAttribute(hmma_gemm<false>, cudaFuncAttributeMaxDynamicSharedMemorySize, HG_SMEM);
    cudaFuncSetAttribute(hmma_gemm<true>, cudaFuncAttributeMaxDynamicSharedMemorySize, HG_SMEM);

    // ---- one-time (per launch) weight conversions, batched across all layers ----
    cvtT_kernel<<<dim3(DM_ / 32, DK_ / 32, L_ * H_), dim3(32, 8)>>>(
        WQ, Wqkvh, Wqkvl, DM_, DK_, H_, SSTR);
    cvtT_kernel<<<dim3(DM_ / 32, DK_ / 32, L_ * H_), dim3(32, 8)>>>(
        WK, Wqkvh + (size_t)1024 * DM_, Wqkvl + (size_t)1024 * DM_, DM_, DK_, H_, SSTR);
    cvtT_kernel<<<dim3(DM_ / 32, DK_ / 32, L_ * H_), dim3(32, 8)>>>(
        WV, Wqkvh + (size_t)2048 * DM_, Wqkvl + (size_t)2048 * DM_, DM_, DK_, H_, SSTR);
    cvtT_kernel<<<dim3(DM_ / 32, DM_ / 32, L_), dim3(32, 8)>>>(
        WO, WOth, WOtl, DM_, DM_, 1, DM_);
    cvtT_kernel<<<dim3(DM_ / 32, DFF_ / 32, L_), dim3(32, 8)>>>(
        W1, W1th, W1tl, DM_, DFF_, 1, DFF_);
    cvtT_kernel<<<dim3(DFF_ / 32, DM_ / 32, L_), dim3(32, 8)>>>(
        W2, W2th, W2tl, DFF_, DM_, 1, DM_);
    pack_bias<<<(L_ * SSTR + 255) / 256, 256>>>(bQ, bK, bV, bQKV);

    embed_kernel<<<N_, 256>>>(X, emb, h, hh, hl);

    for (int l = 0; l < L_; l++) {
        const __nv_bfloat16* Wqh = Wqkvh + (size_t)l * SSTR * DM_;
        const __nv_bfloat16* Wql = Wqkvl + (size_t)l * SSTR * DM_;
        const __nv_bfloat16* WOh = WOth + (size_t)l * DM_ * DM_;
        const __nv_bfloat16* WOl_ = WOtl + (size_t)l * DM_ * DM_;
        const __nv_bfloat16* W1h = W1th + (size_t)l * DFF_ * DM_;
        const __nv_bfloat16* W1l_ = W1tl + (size_t)l * DFF_ * DM_;
        const __nv_bfloat16* W2h = W2th + (size_t)l * DM_ * DFF_;
        const __nv_bfloat16* W2l_ = W2tl + (size_t)l * DM_ * DFF_;
        const float* bOl = bO + (size_t)l * DM_;
        const float* b1l = b1 + (size_t)l * DFF_;
        const float* b2l = b2 + (size_t)l * DM_;
        const float* g1l = g1 + (size_t)l * N_ * DM_;
        const float* be1l = be1 + (size_t)l * N_ * DM_;
        const float* g2l = g2 + (size_t)l * N_ * DM_;
        const float* be2l = be2 + (size_t)l * N_ * DM_;

        // ---- fused QKV projection: [2048 x 3072] = h @ [Wq|Wk|Wv]
        hmma_gemm<false><<<dim3(SSTR / 128, N_ / 128), 256, HG_SMEM>>>(
            hh, hl, Wqh, Wql, QKV, QKVh, QKVl, bQKV + (size_t)l * SSTR, N_, SSTR, DM_);

        // ---- attention: HMMA row-wise lse, then Q@(K^T V)/8 - lse^T V (bf16 out)
        lse_hmma2<<<dim3(N_ / 128, H_), 256, LSE2_SMEM>>>(
            QKVh, QKVl, QKVh + 1024, QKVl + 1024, lse);
        zero_ktv<<<(H_ * DK_ * DV_ + 255) / 256, 256>>>(KtV, lseV);
        ktv_kernel<<<dim3(N_ / 256, H_), 256>>>(QKV + 1024, QKV + 2048, lse, KtV, lseV);
        sgemm_kernel<<<dim3(1, N_ / 128, H_), 256>>>(
            QKV, KtV, ath, atl, lseV, N_, DV_, DK_, SSTR, DV_, DM_,
            64L, (long)DK_ * DV_, 64L, (long)DV_, 0.125f);

        // ---- Z = attn @ WO + bO
        hmma_gemm<false><<<dim3(DM_ / 128, N_ / 128), 256, HG_SMEM>>>(
            ath, atl, WOh, WOl_, Z, nullptr, nullptr, bOl, N_, DM_, DM_);

        // ---- h2 = LN(h + Z)
        ln_kernel<<<N_, 256>>>(h, Z, g1l, be1l, h2, h2h, h2l);

        // ---- F1 = relu(h2 @ W1 + b1) (bf16 hi/lo out only)
        hmma_gemm<true><<<dim3(DFF_ / 128, N_ / 128), 256, HG_SMEM>>>(
            h2h, h2l, W1h, W1l_, nullptr, F1h, F1l, b1l, N_, DFF_, DM_);

        // ---- R = F1 @ W2 + b2
        hmma_gemm<false><<<dim3(DM_ / 128, N_ / 128), 256, HG_SMEM>>>(
            F1h, F1l, W2h, W2l_, R, nullptr, nullptr, b2l, N_, DM_, DFF_);

        // ---- h = LN(h2 + R)
        if (l == L_ - 1) {
            ln_kernel<<<N_, 256>>>(h2, R, g2l, be2l, out, nullptr, nullptr);
        } else {
            ln_kernel<<<N_, 256>>>(h2, R, g2l, be2l, h, hh, hl);
        }
    }
}

// round 13
// speedup vs baseline: 1.7062x; 1.0526x over previous
#include <cuda_runtime.h>
#include <cuda_bf16.h>
#include <math.h>
#include <stdint.h>

#define L_ 6
#define H_ 16
#define N_ 2048
#define DM_ 1024
#define DK_ 64
#define DV_ 64
#define DFF_ 4096
#define SSTR 3072   // combined QKV row stride

// ---------------- helpers ----------------
__device__ __forceinline__ uint32_t smem_u32(const void* p) {
    uint32_t a;
    asm("{ .reg .u64 t; cvta.to.shared.u64 t, %1; cvt.u32.u64 %0, t; }" : "=r"(a) : "l"(p));
    return a;
}
#define CPA16(saddr, gptr) \
    asm volatile("cp.async.cg.shared.global [%0], [%1], 16;" :: "r"(saddr), "l"(gptr) : "memory")
#define CP_COMMIT() asm volatile("cp.async.commit_group;" ::: "memory")
#define CP_WAIT0()  asm volatile("cp.async.wait_group 0;" ::: "memory")
#define CP_WAIT1()  asm volatile("cp.async.wait_group 1;" ::: "memory")

#define LDSM4(r, a)                                                                     \
    asm volatile("ldmatrix.sync.aligned.m8n8.x4.shared.b16 {%0,%1,%2,%3}, [%4];"        \
                 : "=r"((r)[0]), "=r"((r)[1]), "=r"((r)[2]), "=r"((r)[3]) : "r"(a))

__device__ __forceinline__ void mma16816(float* c, const uint32_t* a, const uint32_t* b) {
    asm volatile(
        "mma.sync.aligned.m16n8k16.row.col.f32.bf16.bf16.f32 "
        "{%0,%1,%2,%3}, {%4,%5,%6,%7}, {%8,%9}, {%0,%1,%2,%3};"
        : "+f"(c[0]), "+f"(c[1]), "+f"(c[2]), "+f"(c[3])
        : "r"(a[0]), "r"(a[1]), "r"(a[2]), "r"(a[3]), "r"(b[0]), "r"(b[1]));
}

__device__ __forceinline__ uint32_t pack_bf2(float a, float b) {
    __nv_bfloat162 p = {__float2bfloat16(a), __float2bfloat16(b)};
    return *(uint32_t*)&p;
}

// ---------------- scratch ----------------
__device__ float g_h[N_ * DM_];
__device__ float g_QKV[N_ * SSTR];
__device__ float g_lse[H_ * N_];
__device__ float g_KtV[H_ * DK_ * DV_];
__device__ float g_lseV[H_ * DV_];
__device__ float g_Z[N_ * DM_];
__device__ float g_h2[N_ * DM_];
__device__ float g_R[N_ * DM_];
__device__ float g_bQKV[L_ * SSTR];
__device__ float g_bZ[DM_];
__device__ __nv_bfloat16 g_hh[N_ * DM_], g_hl[N_ * DM_];
__device__ __nv_bfloat16 g_QKVh[N_ * SSTR], g_QKVl[N_ * SSTR];
__device__ __nv_bfloat16 g_h2h[N_ * DM_], g_h2l[N_ * DM_];
__device__ __nv_bfloat16 g_F1h[N_ * DFF_], g_F1l[N_ * DFF_];
__device__ __nv_bfloat16 g_Gth[DM_ * DM_], g_Gtl[DM_ * DM_];
// pre-converted transposed weights, all layers
__device__ __nv_bfloat16 g_Wqkvh[L_ * SSTR * DM_], g_Wqkvl[L_ * SSTR * DM_];
__device__ __nv_bfloat16 g_W1th[L_ * DFF_ * DM_], g_W1tl[L_ * DFF_ * DM_];
__device__ __nv_bfloat16 g_W2th[L_ * DM_ * DFF_], g_W2tl[L_ * DM_ * DFF_];

// one shared extern dynamic smem symbol for ALL kernels
extern __shared__ char dynsm[];

// ---------------- embedding + positional encoding (fused bf16 split) -------------
__global__ void embed_kernel(const int* __restrict__ X, const float* __restrict__ emb,
                             float* __restrict__ h, __nv_bfloat16* __restrict__ oh,
                             __nv_bfloat16* __restrict__ ol) {
    int n = blockIdx.x;
    int t = threadIdx.x;
    const float* e = emb + (size_t)X[n] * DM_;
    float pos = (float)(n + 1);
#pragma unroll
    for (int k = 0; k < 2; k++) {
        int i = t + k * 256;
        float a = (float)(2 * i) / (float)DM_ * -9.210340371976184f;
        float f = expf(a);
        float tt = pos * f;
        float v0 = e[2 * i] + sinf(tt);
        float v1 = e[2 * i + 1] + cosf(tt);
        h[(size_t)n * DM_ + 2 * i] = v0;
        h[(size_t)n * DM_ + 2 * i + 1] = v1;
        __nv_bfloat16 h0 = __float2bfloat16(v0), h1 = __float2bfloat16(v1);
        oh[(size_t)n * DM_ + 2 * i] = h0;
        oh[(size_t)n * DM_ + 2 * i + 1] = h1;
        ol[(size_t)n * DM_ + 2 * i] = __float2bfloat16(v0 - __bfloat162float(h0));
        ol[(size_t)n * DM_ + 2 * i + 1] = __float2bfloat16(v1 - __bfloat162float(h1));
    }
}

// ---- bias concat: bQKV[l][0:1024)=bQ, [1024:2048)=bK, [2048:3072)=bV ----
__global__ void pack_bias(const float* __restrict__ bQ, const float* __restrict__ bK,
                          const float* __restrict__ bV, float* __restrict__ o) {
    int i = blockIdx.x * 256 + threadIdx.x;
    if (i >= L_ * SSTR) return;
    int l = i / SSTR, c = i % SSTR;
    float v;
    if (c < 1024) v = bQ[l * 1024 + c];
    else if (c < 2048) v = bK[l * 1024 + c - 1024];
    else v = bV[l * 1024 + c - 2048];
    o[i] = v;
}

// ---------------- batched transpose + split: in [b][K][Nb] -> rows (b/perl)*lstride+(b%perl)*Nb+n
__global__ void cvtT_kernel(const float* __restrict__ in, __nv_bfloat16* __restrict__ oh,
                            __nv_bfloat16* __restrict__ ol, int K, int Nb,
                            int perl, int lstride) {
    __shared__ float tile[32][33];
    int b = blockIdx.z;
    size_t rowbase = (size_t)(b / perl) * lstride + (size_t)(b % perl) * Nb;
    int k0 = blockIdx.x * 32, n0 = blockIdx.y * 32;
    int tx = threadIdx.x, ty = threadIdx.y;
    const float* W = in + (size_t)b * K * Nb;
#pragma unroll
    for (int r = 0; r < 4; r++)
        tile[ty + 8 * r][tx] = W[(size_t)(k0 + ty + 8 * r) * Nb + n0 + tx];
    __syncthreads();
#pragma unroll
    for (int r = 0; r < 4; r++) {
        float a = tile[tx][ty + 8 * r];
        size_t o = (rowbase + n0 + ty + 8 * r) * K + k0 + tx;
        __nv_bfloat16 h = __float2bfloat16(a);
        oh[o] = h;
        ol[o] = __float2bfloat16(a - __bfloat162float(h));
    }
}

// ---------------- HMMA GEMM (ldmatrix): C = A @ Bt^T + bias, opt relu, opt split-K -
// hi/lo split: C = Ah*Bh + Ah*Bl + Al*Bh. split-K via gridDim.z (atomicAdd, fp32 C).
#define BM 128
#define BN 128
#define BK 32
#define KP 40
#define MAT_ELE (BM * KP)
#define STAGE_ELE (4 * MAT_ELE)
#define HG_SMEM (2 * STAGE_ELE * 2)
template <bool RELU>
__global__ void __launch_bounds__(256) hmma_gemm(
    const __nv_bfloat16* __restrict__ Ah, const __nv_bfloat16* __restrict__ Al,
    const __nv_bfloat16* __restrict__ Bh, const __nv_bfloat16* __restrict__ Bl,
    float* __restrict__ C, __nv_bfloat16* __restrict__ Oh, __nv_bfloat16* __restrict__ Ol,
    const float* __restrict__ bias, int M, int N, int K, int lda, int ldb) {
    uint32_t smb = smem_u32(dynsm);

    int t = threadIdx.x;
    int warp = t >> 5, lane = t & 31;
    int wm = warp & 3, wn = warp >> 2;
    int g = lane >> 2, tg = lane & 3;
    int bn0 = blockIdx.x * BN, bm0 = blockIdx.y * BM;

    int nz = gridDim.z;
    const int nch = K / nz / BK;
    int chunk0 = blockIdx.z * nch;

    const __nv_bfloat16* srcs[4] = {Ah, Al, Bh, Bl};
    int rowbase[4] = {bm0, bm0, bn0, bn0};
    int lds[4] = {lda, lda, ldb, ldb};

    int lrow = lane & 15;
    int lko = (lane >> 4) * 8;
    uint32_t aoff = (uint32_t)(((wm * 32 + lrow) * KP + lko) * 2);
    int bn_off = (lane & 7) + ((lane >> 4) ? 8 : 0);
    int bk_off = ((lane >> 3) & 1) * 8;
    uint32_t boff = (uint32_t)(((wn * 64 + bn_off) * KP + bk_off) * 2);

    float acc[2][8][4];
#pragma unroll
    for (int i = 0; i < 2; i++)
#pragma unroll
        for (int j = 0; j < 8; j++)
#pragma unroll
            for (int k = 0; k < 4; k++) acc[i][j][k] = 0.f;

    auto issue = [&](int c) {
        uint32_t sb = smb + (uint32_t)((c & 1) * STAGE_ELE * 2);
#pragma unroll
        for (int mt = 0; mt < 4; mt++) {
#pragma unroll
            for (int r = 0; r < 2; r++) {
                int f = t + 256 * r;
                int m = f >> 2, ck = f & 3;
                const __nv_bfloat16* gp =
                    srcs[mt] + (size_t)(rowbase[mt] + m) * lds[mt] + (chunk0 + c) * BK + ck * 8;
                uint32_t sa = sb + (uint32_t)((mt * MAT_ELE + m * KP + ck * 8) * 2);
                CPA16(sa, gp);
            }
        }
    };

    issue(0);
    CP_COMMIT();

    for (int c = 0; c < nch; c++) {
        if (c + 1 < nch) {
            issue(c + 1);
            CP_COMMIT();
            CP_WAIT1();
        } else {
            CP_WAIT0();
        }
        __syncthreads();

        uint32_t cb = smb + (uint32_t)((c & 1) * STAGE_ELE * 2);
        uint32_t aH = cb + aoff;
        uint32_t aL = cb + (uint32_t)(MAT_ELE * 2) + aoff;
        uint32_t bH = cb + (uint32_t)(2 * MAT_ELE * 2) + boff;
        uint32_t bL = cb + (uint32_t)(3 * MAT_ELE * 2) + boff;

#pragma unroll
        for (int ks = 0; ks < 2; ks++) {
            uint32_t koff = (uint32_t)(ks * 32);
            uint32_t ah[2][4], al[2][4];
#pragma unroll
            for (int mt = 0; mt < 2; mt++) {
                uint32_t ro = (uint32_t)(mt * 16 * KP * 2) + koff;
                LDSM4(ah[mt], aH + ro);
                LDSM4(al[mt], aL + ro);
            }
#pragma unroll
            for (int p = 0; p < 4; p++) {
                uint32_t po = (uint32_t)(p * 16 * KP * 2) + koff;
                uint32_t bh[4], bl[4];
                LDSM4(bh, bH + po);
                LDSM4(bl, bL + po);
#pragma unroll
                for (int mt = 0; mt < 2; mt++) {
                    mma16816(acc[mt][2 * p], ah[mt], bh);
                    mma16816(acc[mt][2 * p], ah[mt], bl);
                    mma16816(acc[mt][2 * p], al[mt], bh);
                    mma16816(acc[mt][2 * p + 1], ah[mt], bh + 2);
                    mma16816(acc[mt][2 * p + 1], ah[mt], bl + 2);
                    mma16816(acc[mt][2 * p + 1], al[mt], bh + 2);
                }
            }
        }
        __syncthreads();
    }

    bool zi0 = (blockIdx.z == 0);
#pragma unroll
    for (int mt = 0; mt < 2; mt++) {
        int row = bm0 + wm * 32 + mt * 16;
#pragma unroll
        for (int nt = 0; nt < 8; nt++) {
            int coln = bn0 + wn * 64 + nt * 8 + tg * 2;
            float bx = zi0 ? bias[coln] : 0.f;
            float by = zi0 ? bias[coln + 1] : 0.f;
            float v0 = acc[mt][nt][0] + bx;
            float v1 = acc[mt][nt][1] + by;
            float v2 = acc[mt][nt][2] + bx;
            float v3 = acc[mt][nt][3] + by;
            if (RELU) {
                v0 = fmaxf(v0, 0.f); v1 = fmaxf(v1, 0.f);
                v2 = fmaxf(v2, 0.f); v3 = fmaxf(v3, 0.f);
            }
            size_t o0 = (size_t)(row + g) * N + coln;
            size_t o1 = (size_t)(row + 8 + g) * N + coln;
            if (nz > 1) {
                atomicAdd(&C[o0], v0);
                atomicAdd(&C[o0 + 1], v1);
                atomicAdd(&C[o1], v2);
                atomicAdd(&C[o1 + 1], v3);
            } else {
                if (C) {
                    float2 p0 = {v0, v1}, p1 = {v2, v3};
                    *(float2*)&C[o0] = p0;
                    *(float2*)&C[o1] = p1;
                }
                if (Oh) {
                    uint32_t h0 = pack_bf2(v0, v1), h1 = pack_bf2(v2, v3);
                    *(uint32_t*)&Oh[o0] = h0;
                    *(uint32_t*)&Oh[o1] = h1;
                    __nv_bfloat162 hp0 = *(__nv_bfloat162*)&h0;
                    __nv_bfloat162 hp1 = *(__nv_bfloat162*)&h1;
                    *(uint32_t*)&Ol[o0] = pack_bf2(v0 - __bfloat162float(hp0.x),
                                                   v1 - __bfloat162float(hp0.y));
                    *(uint32_t*)&Ol[o1] = pack_bf2(v2 - __bfloat162float(hp1.x),
                                                   v3 - __bfloat162float(hp1.y));
                }
            }
        }
    }
}

// ---------------- HMMA lse (transposed): T = K @ Q^T / 8, row-wise logsumexp -------
#define LKP2 72
#define KMATB (128 * LKP2 * 2)
#define QMATB (64 * LKP2 * 2)
#define LSE2_FBASE (2 * KMATB + 4 * QMATB)
#define LSE2_SMEM (LSE2_FBASE + (128 * 2 * 2 + 256) * 4)
__global__ void __launch_bounds__(256) lse_hmma2(
    const __nv_bfloat16* __restrict__ Qh_, const __nv_bfloat16* __restrict__ Ql_,
    const __nv_bfloat16* __restrict__ Kh_, const __nv_bfloat16* __restrict__ Kl_,
    float* __restrict__ lse) {
    uint32_t smb = smem_u32(dynsm);
    float* part_m = (float*)(dynsm + LSE2_FBASE);
    float* part_s = part_m + 128 * 2;
    float* Ms = part_s + 128 * 2;
    float* Ls = Ms + 128;

    int h = blockIdx.y;
    int m0 = blockIdx.x * 128;
    const __nv_bfloat16* Kh = Kh_ + h * 64;
    const __nv_bfloat16* Kl = Kl_ + h * 64;
    const __nv_bfloat16* Qh = Qh_ + h * 64;
    const __nv_bfloat16* Ql = Ql_ + h * 64;

    int t = threadIdx.x;
    int warp = t >> 5, lane = t & 31;
    int wm = warp & 3, wn = warp >> 2;
    int g = lane >> 2, tg = lane & 3;

    int lrow = lane & 15;
    int lko = (lane >> 4) * 8;
    uint32_t aoff = (uint32_t)(((wm * 32 + lrow) * LKP2 + lko) * 2);
    int bn_off = (lane & 7) + ((lane >> 4) ? 8 : 0);
    int bk_off = ((lane >> 3) & 1) * 8;
    uint32_t boff = (uint32_t)(((wn * 32 + bn_off) * LKP2 + bk_off) * 2);

#pragma unroll
    for (int r = 0; r < 8; r++) {
        int idx = t + 256 * r;
        int mat = idx >> 10, rem = idx & 1023, m = rem >> 3, ck = rem & 7;
        const __nv_bfloat16* gp = (mat ? Kl : Kh) + (size_t)(m0 + m) * SSTR + ck * 8;
        uint32_t sa = smb + (uint32_t)(mat * KMATB + (m * LKP2 + ck * 8) * 2);
        CPA16(sa, gp);
    }
    auto issueQ = [&](int q) {
        uint32_t qb = smb + (uint32_t)(2 * KMATB + (q & 1) * 2 * QMATB);
#pragma unroll
        for (int r = 0; r < 4; r++) {
            int idx = t + 256 * r;
            int mat = idx >> 9, rem = idx & 511, m = rem >> 3, ck = rem & 7;
            const __nv_bfloat16* gp = (mat ? Ql : Qh) + (size_t)(q * 64 + m) * SSTR + ck * 8;
            uint32_t sa = qb + (uint32_t)(mat * QMATB + (m * LKP2 + ck * 8) * 2);
            CPA16(sa, gp);
        }
    };

    issueQ(0);
    CP_COMMIT();
    if (t < 128) { Ms[t] = -INFINITY; Ls[t] = 0.f; }
    __syncthreads();

    const int nq = N_ / 64;
    for (int q = 0; q < nq; q++) {
        if (q + 1 < nq) {
            issueQ(q + 1);
            CP_COMMIT();
            CP_WAIT1();
        } else {
            CP_WAIT0();
        }
        __syncthreads();

        uint32_t aH = smb + aoff;
        uint32_t aL = smb + (uint32_t)KMATB + aoff;
        uint32_t qb = smb + (uint32_t)(2 * KMATB + (q & 1) * 2 * QMATB);
        uint32_t bH = qb + boff;
        uint32_t bL = qb + (uint32_t)QMATB + boff;

        float acc[2][4][4];
#pragma unroll
        for (int i = 0; i < 2; i++)
#pragma unroll
            for (int j = 0; j < 4; j++)
#pragma unroll
                for (int k = 0; k < 4; k++) acc[i][j][k] = 0.f;

#pragma unroll
        for (int ks = 0; ks < 4; ks++) {
            uint32_t koff = (uint32_t)(ks * 32);
            uint32_t ah[2][4], al[2][4];
#pragma unroll
            for (int mt = 0; mt < 2; mt++) {
                uint32_t ro = (uint32_t)(mt * 16 * LKP2 * 2) + koff;
                LDSM4(ah[mt], aH + ro);
                LDSM4(al[mt], aL + ro);
            }
#pragma unroll
            for (int p = 0; p < 2; p++) {
                uint32_t po = (uint32_t)(p * 16 * LKP2 * 2) + koff;
                uint32_t bh[4], bl[4];
                LDSM4(bh, bH + po);
                LDSM4(bl, bL + po);
#pragma unroll
                for (int mt = 0; mt < 2; mt++) {
                    mma16816(acc[mt][2 * p], ah[mt], bh);
                    mma16816(acc[mt][2 * p], ah[mt], bl);
                    mma16816(acc[mt][2 * p], al[mt], bh);
                    mma16816(acc[mt][2 * p + 1], ah[mt], bh + 2);
                    mma16816(acc[mt][2 * p + 1], ah[mt], bl + 2);
                    mma16816(acc[mt][2 * p + 1], al[mt], bh + 2);
                }
            }
        }

#pragma unroll
        for (int mt = 0; mt < 2; mt++) {
#pragma unroll
            for (int half = 0; half < 2; half++) {
                float v[8];
#pragma unroll
                for (int nt = 0; nt < 4; nt++) {
                    v[2 * nt] = acc[mt][nt][half * 2] * 0.125f;
                    v[2 * nt + 1] = acc[mt][nt][half * 2 + 1] * 0.125f;
                }
                float m = v[0];
#pragma unroll
                for (int i = 1; i < 8; i++) m = fmaxf(m, v[i]);
                m = fmaxf(m, __shfl_xor_sync(0xFFFFFFFFu, m, 1));
                m = fmaxf(m, __shfl_xor_sync(0xFFFFFFFFu, m, 2));
                float s = 0.f;
#pragma unroll
                for (int i = 0; i < 8; i++) s += __expf(v[i] - m);
                s += __shfl_xor_sync(0xFFFFFFFFu, s, 1);
                s += __shfl_xor_sync(0xFFFFFFFFu, s, 2);
                if (tg == 0) {
                    int row = wm * 32 + mt * 16 + half * 8 + g;
                    part_m[row * 2 + wn] = m;
                    part_s[row * 2 + wn] = s;
                }
            }
        }
        __syncthreads();
        if (t < 128) {
            float ma = part_m[t * 2], mb = part_m[t * 2 + 1];
            float m2 = fmaxf(ma, mb);
            float s2 = part_s[t * 2] * __expf(ma - m2) + part_s[t * 2 + 1] * __expf(mb - m2);
            float M = Ms[t], Ll = Ls[t];
            float mn = fmaxf(M, m2);
            Ls[t] = Ll * __expf(M - mn) + s2 * __expf(m2 - mn);
            Ms[t] = mn;
        }
        __syncthreads();
    }

    if (t < 128) lse[(size_t)h * N_ + m0 + t] = Ms[t] + logf(Ls[t]);
}

// ---------------- KtV[h] = K[h]^T V[h], lseV[h] = lse[h]^T V[h] ------------
__global__ void __launch_bounds__(256) ktv_kernel(const float* __restrict__ K,
                                                  const float* __restrict__ V,
                                                  const float* __restrict__ lse,
                                                  float* __restrict__ KtV,
                                                  float* __restrict__ lseV) {
    __shared__ float Ks[64][64];
    __shared__ float Vs[64][64];
    __shared__ float ls[64];
    int h = blockIdx.y;
    int k0 = blockIdx.x * 256;
    const float* Kh = K + h * 64;
    const float* Vh = V + h * 64;
    const float* lh = lse + (size_t)h * N_;
    int t = threadIdx.x;
    int ty = t >> 4, tx = t & 15;

    float c[4][4];
#pragma unroll
    for (int i = 0; i < 4; i++)
#pragma unroll
        for (int j = 0; j < 4; j++) c[i][j] = 0.f;
    float lv[4] = {0.f, 0.f, 0.f, 0.f};

    for (int kc = k0; kc < k0 + 256; kc += 64) {
#pragma unroll
        for (int r = 0; r < 4; r++) {
            int f = t + 256 * r;
            int row = f >> 4, c4 = f & 15;
            *(float4*)&Ks[row][c4 * 4] = *(const float4*)(Kh + (size_t)(kc + row) * SSTR + c4 * 4);
            *(float4*)&Vs[row][c4 * 4] = *(const float4*)(Vh + (size_t)(kc + row) * SSTR + c4 * 4);
        }
        if (t < 64) ls[t] = lh[kc + t];
        __syncthreads();
#pragma unroll 8
        for (int kk = 0; kk < 64; kk++) {
            float4 a = *(float4*)&Ks[kk][ty * 4];
            float4 b = *(float4*)&Vs[kk][tx * 4];
            float aa[4] = {a.x, a.y, a.z, a.w};
            float bb[4] = {b.x, b.y, b.z, b.w};
#pragma unroll
            for (int i = 0; i < 4; i++)
#pragma unroll
                for (int j = 0; j < 4; j++) c[i][j] += aa[i] * bb[j];
            if (ty == 0) {
                float l = ls[kk];
#pragma unroll
                for (int j = 0; j < 4; j++) lv[j] += l * bb[j];
            }
        }
        __syncthreads();
    }
#pragma unroll
    for (int i = 0; i < 4; i++)
#pragma unroll
        for (int j = 0; j < 4; j++)
            atomicAdd(&KtV[(size_t)h * DK_ * DV_ + (ty * 4 + i) * DV_ + tx * 4 + j], c[i][j]);
    if (ty == 0) {
#pragma unroll
        for (int j = 0; j < 4; j++) atomicAdd(&lseV[(size_t)h * DV_ + tx * 4 + j], lv[j]);
    }
}

// ---- G^T[c][h*64+d] = (1/8) sum_v KtV[h][d][v] * WO[h*64+v][c];  bZ -= lseV@WO ----
// grid (16 c-tiles, 16 h), block 256.
__global__ void __launch_bounds__(256) ktv_wo(const float* __restrict__ KtV,
                                              const float* __restrict__ lseV,
                                              const float* __restrict__ WO,
                                              __nv_bfloat16* __restrict__ Gth,
                                              __nv_bfloat16* __restrict__ Gtl,
                                              float* __restrict__ bZ) {
    __shared__ float kt[64 * 65];
    __shared__ float wos[64 * 64];
    __shared__ float lv[64];
    int h = blockIdx.y;
    int c0 = blockIdx.x * 64;
    int t = threadIdx.x;
    for (int i = t; i < 4096; i += 256) {
        kt[(i >> 6) * 65 + (i & 63)] = KtV[(size_t)h * 4096 + i] * 0.125f;
        wos[i] = WO[(size_t)(h * 64 + (i >> 6)) * DM_ + c0 + (i & 63)];
    }
    if (t < 64) lv[t] = lseV[h * 64 + t];
    __syncthreads();

    int td = t & 63;    // d index
    int tcg = t >> 6;   // c = c0 + tcg + 4*i
    float acc[16];
#pragma unroll
    for (int i = 0; i < 16; i++) acc[i] = 0.f;
#pragma unroll 8
    for (int v = 0; v < 64; v++) {
        float kv = kt[td * 65 + v];
        const float* wr = &wos[v * 64 + tcg];
#pragma unroll
        for (int i = 0; i < 16; i++) acc[i] += kv * wr[4 * i];
    }
#pragma unroll
    for (int i = 0; i < 16; i++) {
        int c = c0 + tcg + 4 * i;
        size_t o = (size_t)c * DM_ + h * 64 + td;
        __nv_bfloat16 hv = __float2bfloat16(acc[i]);
        Gth[o] = hv;
        Gtl[o] = __float2bfloat16(acc[i] - __bfloat162float(hv));
    }
    if (td == 0) {
        float bacc[16];
#pragma unroll
        for (int i = 0; i < 16; i++) bacc[i] = 0.f;
        for (int v = 0; v < 64; v++) {
            float l = lv[v];
#pragma unroll
            for (int i = 0; i < 16; i++) bacc[i] += l * wos[v * 64 + tcg + 4 * i];
        }
#pragma unroll
        for (int i = 0; i < 16; i++) atomicAdd(&bZ[c0 + tcg + 4 * i], -bacc[i]);
    }
}

// ---------------- layernorm (ddof=1) with fused bf16 hi/lo output ----------------
__global__ void __launch_bounds__(256) ln_kernel(const float* __restrict__ a,
                                                 const float* __restrict__ b,
                                                 const float* __restrict__ g,
                                                 const float* __restrict__ be,
                                                 float* __restrict__ out,
                                                 __nv_bfloat16* __restrict__ oh,
                                                 __nv_bfloat16* __restrict__ ol) {
    __shared__ float red[256];
    int n = blockIdx.x;
    int t = threadIdx.x;
    size_t base = (size_t)n * DM_;
    float x[4];
    float s = 0.f;
#pragma unroll
    for (int k = 0; k < 4; k++) {
        int d = t + k * 256;
        x[k] = a[base + d] + b[base + d];
        s += x[k];
    }
    red[t] = s;
    __syncthreads();
    for (int o = 128; o > 0; o >>= 1) {
        if (t < o) red[t] += red[t + o];
        __syncthreads();
    }
    float mean = red[0] * (1.f / (float)DM_);
    __syncthreads();
    float s2 = 0.f;
#pragma unroll
    for (int k = 0; k < 4; k++) {
        float d = x[k] - mean;
        s2 += d * d;
    }
    red[t] = s2;
    __syncthreads();
    for (int o = 128; o > 0; o >>= 1) {
        if (t < o) red[t] += red[t + o];
        __syncthreads();
    }
    float var = red[0] * (1.f / (float)(DM_ - 1));
    float invstd = 1.f / sqrtf(var);
#pragma unroll
    for (int k = 0; k < 4; k++) {
        int d = t + k * 256;
        float v = g[base + d] * invstd * (x[k] - mean) + be[base + d];
        out[base + d] = v;
        if (oh) {
            __nv_bfloat16 hv = __float2bfloat16(v);
            oh[base + d] = hv;
            ol[base + d] = __float2bfloat16(v - __bfloat162float(hv));
        }
    }
}

// ---------------- launch ----------------
extern "C" void kernel_launch(void* const* d_in, const int* in_sizes, int n_in,
                              void* d_out, int out_size) {
    (void)in_sizes; (void)n_in; (void)out_size;
    const int*   X   = (const int*)d_in[0];
    const float* emb = (const float*)d_in[1];
    const float* WQ  = (const float*)d_in[2];
    const float* bQ  = (const float*)d_in[3];
    const float* WK  = (const float*)d_in[4];
    const float* bK  = (const float*)d_in[5];
    const float* WV  = (const float*)d_in[6];
    const float* bV  = (const float*)d_in[7];
    const float* WO  = (const float*)d_in[8];
    const float* bO  = (const float*)d_in[9];
    const float* W1  = (const float*)d_in[10];
    const float* b1  = (const float*)d_in[11];
    const float* W2  = (const float*)d_in[12];
    const float* b2  = (const float*)d_in[13];
    const float* g1  = (const float*)d_in[14];
    const float* be1 = (const float*)d_in[15];
    const float* g2  = (const float*)d_in[16];
    const float* be2 = (const float*)d_in[17];
    float* out = (float*)d_out;

    float *h, *QKV, *lse, *KtV, *lseV, *Z, *h2, *R, *bQKV, *bZ;
    __nv_bfloat16 *hh, *hl, *QKVh, *QKVl, *h2h, *h2l, *F1h, *F1l, *Gth, *Gtl;
    __nv_bfloat16 *Wqkvh, *Wqkvl, *W1th, *W1tl, *W2th, *W2tl;
    cudaGetSymbolAddress((void**)&h, g_h);
    cudaGetSymbolAddress((void**)&QKV, g_QKV);
    cudaGetSymbolAddress((void**)&lse, g_lse);
    cudaGetSymbolAddress((void**)&KtV, g_KtV);
    cudaGetSymbolAddress((void**)&lseV, g_lseV);
    cudaGetSymbolAddress((void**)&Z, g_Z);
    cudaGetSymbolAddress((void**)&h2, g_h2);
    cudaGetSymbolAddress((void**)&R, g_R);
    cudaGetSymbolAddress((void**)&bQKV, g_bQKV);
    cudaGetSymbolAddress((void**)&bZ, g_bZ);
    cudaGetSymbolAddress((void**)&hh, g_hh);
    cudaGetSymbolAddress((void**)&hl, g_hl);
    cudaGetSymbolAddress((void**)&QKVh, g_QKVh);
    cudaGetSymbolAddress((void**)&QKVl, g_QKVl);
    cudaGetSymbolAddress((void**)&h2h, g_h2h);
    cudaGetSymbolAddress((void**)&h2l, g_h2l);
    cudaGetSymbolAddress((void**)&F1h, g_F1h);
    cudaGetSymbolAddress((void**)&F1l, g_F1l);
    cudaGetSymbolAddress((void**)&Gth, g_Gth);
    cudaGetSymbolAddress((void**)&Gtl, g_Gtl);
    cudaGetSymbolAddress((void**)&Wqkvh, g_Wqkvh);
    cudaGetSymbolAddress((void**)&Wqkvl, g_Wqkvl);
    cudaGetSymbolAddress((void**)&W1th, g_W1th);
    cudaGetSymbolAddress((void**)&W1tl, g_W1tl);
    cudaGetSymbolAddress((void**)&W2th, g_W2th);
    cudaGetSymbolAddress((void**)&W2tl, g_W2tl);

    cudaFuncSetAttribute(lse_hmma2, cudaFuncAttributeMaxDynamicSharedMemorySize, LSE2_SMEM);
    cudaFuncSetAttribute(hmma_gemm<false>, cudaFuncAttributeMaxDynamicSharedMemorySize, HG_SMEM);
    cudaFuncSetAttribute(hmma_gemm<true>, cudaFuncAttributeMaxDynamicSharedMemorySize, HG_SMEM);

    // ---- one-time (per launch) weight conversions, batched across all layers ----
    cvtT_kernel<<<dim3(DM_ / 32, DK_ / 32, L_ * H_), dim3(32, 8)>>>(
        WQ, Wqkvh, Wqkvl, DM_, DK_, H_, SSTR);
    cvtT_kernel<<<dim3(DM_ / 32, DK_ / 32, L_ * H_), dim3(32, 8)>>>(
        WK, Wqkvh + (size_t)1024 * DM_, Wqkvl + (size_t)1024 * DM_, DM_, DK_, H_, SSTR);
    cvtT_kernel<<<dim3(DM_ / 32, DK_ / 32, L_ * H_), dim3(32, 8)>>>(
        WV, Wqkvh + (size_t)2048 * DM_, Wqkvl + (size_t)2048 * DM_, DM_, DK_, H_, SSTR);
    cvtT_kernel<<<dim3(DM_ / 32, DFF_ / 32, L_), dim3(32, 8)>>>(
        W1, W1th, W1tl, DM_, DFF_, 1, DFF_);
    cvtT_kernel<<<dim3(DFF_ / 32, DM_ / 32, L_), dim3(32, 8)>>>(
        W2, W2th, W2tl, DFF_, DM_, 1, DM_);
    pack_bias<<<(L_ * SSTR + 255) / 256, 256>>>(bQ, bK, bV, bQKV);

    embed_kernel<<<N_, 256>>>(X, emb, h, hh, hl);

    for (int l = 0; l < L_; l++) {
        const __nv_bfloat16* Wqh = Wqkvh + (size_t)l * SSTR * DM_;
        const __nv_bfloat16* Wql = Wqkvl + (size_t)l * SSTR * DM_;
        const __nv_bfloat16* W1h = W1th + (size_t)l * DFF_ * DM_;
        const __nv_bfloat16* W1l_ = W1tl + (size_t)l * DFF_ * DM_;
        const __nv_bfloat16* W2h = W2th + (size_t)l * DM_ * DFF_;
        const __nv_bfloat16* W2l_ = W2tl + (size_t)l * DM_ * DFF_;
        const float* WOl_ = WO + (size_t)l * DM_ * DM_;
        const float* bOl = bO + (size_t)l * DM_;
        const float* b1l = b1 + (size_t)l * DFF_;
        const float* b2l = b2 + (size_t)l * DM_;
        const float* g1l = g1 + (size_t)l * N_ * DM_;
        const float* be1l = be1 + (size_t)l * N_ * DM_;
        const float* g2l = g2 + (size_t)l * N_ * DM_;
        const float* be2l = be2 + (size_t)l * N_ * DM_;

        // ---- fused QKV projection: [2048 x 3072] = h @ [Wq|Wk|Wv]
        hmma_gemm<false><<<dim3(SSTR / 128, N_ / 128, 1), 256, HG_SMEM>>>(
            hh, hl, Wqh, Wql, QKV, QKVh, QKVl, bQKV + (size_t)l * SSTR,
            N_, SSTR, DM_, DM_, DM_);

        // ---- attention reductions
        cudaMemsetAsync(KtV, 0, H_ * DK_ * DV_ * sizeof(float));
        cudaMemsetAsync(lseV, 0, H_ * DV_ * sizeof(float));
        lse_hmma2<<<dim3(N_ / 128, H_), 256, LSE2_SMEM>>>(
            QKVh, QKVl, QKVh + 1024, QKVl + 1024, lse);
        ktv_kernel<<<dim3(N_ / 256, H_), 256>>>(QKV + 1024, QKV + 2048, lse, KtV, lseV);

        // ---- fold attn@WO: G = KtV@WO/8 (bf16 hi/lo, transposed), bZ = bO - lseV@WO
        cudaMemcpyAsync(bZ, bOl, DM_ * sizeof(float), cudaMemcpyDeviceToDevice);
        ktv_wo<<<dim3(DM_ / 64, H_), 256>>>(KtV, lseV, WOl_, Gth, Gtl, bZ);

        // ---- Z = Q @ G + bZ  (split-K=2, atomic)
        cudaMemsetAsync(Z, 0, (size_t)N_ * DM_ * sizeof(float));
        hmma_gemm<false><<<dim3(DM_ / 128, N_ / 128, 2), 256, HG_SMEM>>>(
            QKVh, QKVl, Gth, Gtl, Z, nullptr, nullptr, bZ, N_, DM_, 1024, SSTR, 1024);

        // ---- h2 = LN(h + Z)
        ln_kernel<<<N_, 256>>>(h, Z, g1l, be1l, h2, h2h, h2l);

        // ---- F1 = relu(h2 @ W1 + b1) (bf16 hi/lo out only)
        hmma_gemm<true><<<dim3(DFF_ / 128, N_ / 128, 1), 256, HG_SMEM>>>(
            h2h, h2l, W1h, W1l_, nullptr, F1h, F1l, b1l, N_, DFF_, DM_, DM_, DM_);

        // ---- R = F1 @ W2 + b2  (split-K=4, atomic)
        cudaMemsetAsync(R, 0, (size_t)N_ * DM_ * sizeof(float));
        hmma_gemm<false><<<dim3(DM_ / 128, N_ / 128, 4), 256, HG_SMEM>>>(
            F1h, F1l, W2h, W2l_, R, nullptr, nullptr, b2l, N_, DM_, DFF_, DFF_, DFF_);

        // ---- h = LN(h2 + R)
        if (l == L_ - 1) {
            ln_kernel<<<N_, 256>>>(h2, R, g2l, be2l, out, nullptr, nullptr);
        } else {
            ln_kernel<<<N_, 256>>>(h2, R, g2l, be2l, h, hh, hl);
        }
    }
}

// round 15
// speedup vs baseline: 1.7336x; 1.0160x over previous
#include <cuda_runtime.h>
#include <cuda_bf16.h>
#include <math.h>
#include <stdint.h>

#define L_ 6
#define H_ 16
#define N_ 2048
#define DM_ 1024
#define DK_ 64
#define DV_ 64
#define DFF_ 4096
#define SSTR 3072   // combined QKV row stride

// ---------------- helpers ----------------
__device__ __forceinline__ uint32_t smem_u32(const void* p) {
    uint32_t a;
    asm("{ .reg .u64 t; cvta.to.shared.u64 t, %1; cvt.u32.u64 %0, t; }" : "=r"(a) : "l"(p));
    return a;
}
#define CPA16(saddr, gptr) \
    asm volatile("cp.async.cg.shared.global [%0], [%1], 16;" :: "r"(saddr), "l"(gptr) : "memory")
#define CP_COMMIT() asm volatile("cp.async.commit_group;" ::: "memory")
#define CP_WAIT0()  asm volatile("cp.async.wait_group 0;" ::: "memory")
#define CP_WAIT1()  asm volatile("cp.async.wait_group 1;" ::: "memory")

#define LDSM4(r, a)                                                                     \
    asm volatile("ldmatrix.sync.aligned.m8n8.x4.shared.b16 {%0,%1,%2,%3}, [%4];"        \
                 : "=r"((r)[0]), "=r"((r)[1]), "=r"((r)[2]), "=r"((r)[3]) : "r"(a))

__device__ __forceinline__ void mma16816(float* c, const uint32_t* a, const uint32_t* b) {
    asm volatile(
        "mma.sync.aligned.m16n8k16.row.col.f32.bf16.bf16.f32 "
        "{%0,%1,%2,%3}, {%4,%5,%6,%7}, {%8,%9}, {%0,%1,%2,%3};"
        : "+f"(c[0]), "+f"(c[1]), "+f"(c[2]), "+f"(c[3])
        : "r"(a[0]), "r"(a[1]), "r"(a[2]), "r"(a[3]), "r"(b[0]), "r"(b[1]));
}

__device__ __forceinline__ uint32_t pack_bf2(float a, float b) {
    __nv_bfloat162 p = {__float2bfloat16(a), __float2bfloat16(b)};
    return *(uint32_t*)&p;
}

// ---------------- scratch ----------------
__device__ float g_h[N_ * DM_];
__device__ float g_lse[H_ * N_];
__device__ float g_KtV[H_ * DK_ * DV_];
__device__ float g_lseV[H_ * DV_];
__device__ float g_Z[N_ * DM_];
__device__ float g_h2[N_ * DM_];
__device__ float g_R[N_ * DM_];
__device__ float g_bQKV[L_ * SSTR];
__device__ float g_bZ[DM_];
__device__ __nv_bfloat16 g_hh[N_ * DM_], g_hl[N_ * DM_];
__device__ __nv_bfloat16 g_QKVh[N_ * SSTR], g_QKVl[N_ * SSTR];
__device__ __nv_bfloat16 g_h2h[N_ * DM_], g_h2l[N_ * DM_];
__device__ __nv_bfloat16 g_F1h[N_ * DFF_], g_F1l[N_ * DFF_];
__device__ __nv_bfloat16 g_Gth[DM_ * DM_], g_Gtl[DM_ * DM_];
// pre-converted transposed weights, all layers
__device__ __nv_bfloat16 g_Wqkvh[L_ * SSTR * DM_], g_Wqkvl[L_ * SSTR * DM_];
__device__ __nv_bfloat16 g_W1th[L_ * DFF_ * DM_], g_W1tl[L_ * DFF_ * DM_];
__device__ __nv_bfloat16 g_W2th[L_ * DM_ * DFF_], g_W2tl[L_ * DM_ * DFF_];

// one shared extern dynamic smem symbol for ALL kernels
extern __shared__ char dynsm[];

// ---------------- embedding + positional encoding (fused bf16 split) -------------
__global__ void embed_kernel(const int* __restrict__ X, const float* __restrict__ emb,
                             float* __restrict__ h, __nv_bfloat16* __restrict__ oh,
                             __nv_bfloat16* __restrict__ ol) {
    int n = blockIdx.x;
    int t = threadIdx.x;
    const float* e = emb + (size_t)X[n] * DM_;
    float pos = (float)(n + 1);
#pragma unroll
    for (int k = 0; k < 2; k++) {
        int i = t + k * 256;
        float a = (float)(2 * i) / (float)DM_ * -9.210340371976184f;
        float f = expf(a);
        float tt = pos * f;
        float v0 = e[2 * i] + sinf(tt);
        float v1 = e[2 * i + 1] + cosf(tt);
        h[(size_t)n * DM_ + 2 * i] = v0;
        h[(size_t)n * DM_ + 2 * i + 1] = v1;
        __nv_bfloat16 h0 = __float2bfloat16(v0), h1 = __float2bfloat16(v1);
        oh[(size_t)n * DM_ + 2 * i] = h0;
        oh[(size_t)n * DM_ + 2 * i + 1] = h1;
        ol[(size_t)n * DM_ + 2 * i] = __float2bfloat16(v0 - __bfloat162float(h0));
        ol[(size_t)n * DM_ + 2 * i + 1] = __float2bfloat16(v1 - __bfloat162float(h1));
    }
}

// ---- bias concat: bQKV[l][0:1024)=bQ, [1024:2048)=bK, [2048:3072)=bV ----
__global__ void pack_bias(const float* __restrict__ bQ, const float* __restrict__ bK,
                          const float* __restrict__ bV, float* __restrict__ o) {
    int i = blockIdx.x * 256 + threadIdx.x;
    if (i >= L_ * SSTR) return;
    int l = i / SSTR, c = i % SSTR;
    float v;
    if (c < 1024) v = bQ[l * 1024 + c];
    else if (c < 2048) v = bK[l * 1024 + c - 1024];
    else v = bV[l * 1024 + c - 2048];
    o[i] = v;
}

// ---------------- batched transpose + split: in [b][K][Nb] -> rows (b/perl)*lstride+(b%perl)*Nb+n
__global__ void cvtT_kernel(const float* __restrict__ in, __nv_bfloat16* __restrict__ oh,
                            __nv_bfloat16* __restrict__ ol, int K, int Nb,
                            int perl, int lstride) {
    __shared__ float tile[32][33];
    int b = blockIdx.z;
    size_t rowbase = (size_t)(b / perl) * lstride + (size_t)(b % perl) * Nb;
    int k0 = blockIdx.x * 32, n0 = blockIdx.y * 32;
    int tx = threadIdx.x, ty = threadIdx.y;
    const float* W = in + (size_t)b * K * Nb;
#pragma unroll
    for (int r = 0; r < 4; r++)
        tile[ty + 8 * r][tx] = W[(size_t)(k0 + ty + 8 * r) * Nb + n0 + tx];
    __syncthreads();
#pragma unroll
    for (int r = 0; r < 4; r++) {
        float a = tile[tx][ty + 8 * r];
        size_t o = (rowbase + n0 + ty + 8 * r) * K + k0 + tx;
        __nv_bfloat16 h = __float2bfloat16(a);
        oh[o] = h;
        ol[o] = __float2bfloat16(a - __bfloat162float(h));
    }
}

// ---------------- HMMA GEMM (ldmatrix): C = A @ Bt^T + bias, opt relu, opt split-K -
// hi/lo split: C = Ah*Bh + Ah*Bl + Al*Bh. split-K via gridDim.z (atomicAdd, fp32 C).
#define BM 128
#define BN 128
#define BK 32
#define KP 40
#define MAT_ELE (BM * KP)
#define STAGE_ELE (4 * MAT_ELE)
#define HG_SMEM (2 * STAGE_ELE * 2)
template <bool RELU>
__global__ void __launch_bounds__(256) hmma_gemm(
    const __nv_bfloat16* __restrict__ Ah, const __nv_bfloat16* __restrict__ Al,
    const __nv_bfloat16* __restrict__ Bh, const __nv_bfloat16* __restrict__ Bl,
    float* __restrict__ C, __nv_bfloat16* __restrict__ Oh, __nv_bfloat16* __restrict__ Ol,
    const float* __restrict__ bias, int M, int N, int K, int lda, int ldb) {
    uint32_t smb = smem_u32(dynsm);

    int t = threadIdx.x;
    int warp = t >> 5, lane = t & 31;
    int wm = warp & 3, wn = warp >> 2;
    int g = lane >> 2, tg = lane & 3;
    int bn0 = blockIdx.x * BN, bm0 = blockIdx.y * BM;

    int nz = gridDim.z;
    const int nch = K / nz / BK;
    int chunk0 = blockIdx.z * nch;

    const __nv_bfloat16* srcs[4] = {Ah, Al, Bh, Bl};
    int rowbase[4] = {bm0, bm0, bn0, bn0};
    int lds[4] = {lda, lda, ldb, ldb};

    int lrow = lane & 15;
    int lko = (lane >> 4) * 8;
    uint32_t aoff = (uint32_t)(((wm * 32 + lrow) * KP + lko) * 2);
    int bn_off = (lane & 7) + ((lane >> 4) ? 8 : 0);
    int bk_off = ((lane >> 3) & 1) * 8;
    uint32_t boff = (uint32_t)(((wn * 64 + bn_off) * KP + bk_off) * 2);

    float acc[2][8][4];
#pragma unroll
    for (int i = 0; i < 2; i++)
#pragma unroll
        for (int j = 0; j < 8; j++)
#pragma unroll
            for (int k = 0; k < 4; k++) acc[i][j][k] = 0.f;

    auto issue = [&](int c) {
        uint32_t sb = smb + (uint32_t)((c & 1) * STAGE_ELE * 2);
#pragma unroll
        for (int mt = 0; mt < 4; mt++) {
#pragma unroll
            for (int r = 0; r < 2; r++) {
                int f = t + 256 * r;
                int m = f >> 2, ck = f & 3;
                const __nv_bfloat16* gp =
                    srcs[mt] + (size_t)(rowbase[mt] + m) * lds[mt] + (chunk0 + c) * BK + ck * 8;
                uint32_t sa = sb + (uint32_t)((mt * MAT_ELE + m * KP + ck * 8) * 2);
                CPA16(sa, gp);
            }
        }
    };

    issue(0);
    CP_COMMIT();

    for (int c = 0; c < nch; c++) {
        if (c + 1 < nch) {
            issue(c + 1);
            CP_COMMIT();
            CP_WAIT1();
        } else {
            CP_WAIT0();
        }
        __syncthreads();

        uint32_t cb = smb + (uint32_t)((c & 1) * STAGE_ELE * 2);
        uint32_t aH = cb + aoff;
        uint32_t aL = cb + (uint32_t)(MAT_ELE * 2) + aoff;
        uint32_t bH = cb + (uint32_t)(2 * MAT_ELE * 2) + boff;
        uint32_t bL = cb + (uint32_t)(3 * MAT_ELE * 2) + boff;

#pragma unroll
        for (int ks = 0; ks < 2; ks++) {
            uint32_t koff = (uint32_t)(ks * 32);
            uint32_t ah[2][4], al[2][4];
#pragma unroll
            for (int mt = 0; mt < 2; mt++) {
                uint32_t ro = (uint32_t)(mt * 16 * KP * 2) + koff;
                LDSM4(ah[mt], aH + ro);
                LDSM4(al[mt], aL + ro);
            }
#pragma unroll
            for (int p = 0; p < 4; p++) {
                uint32_t po = (uint32_t)(p * 16 * KP * 2) + koff;
                uint32_t bh[4], bl[4];
                LDSM4(bh, bH + po);
                LDSM4(bl, bL + po);
#pragma unroll
                for (int mt = 0; mt < 2; mt++) {
                    mma16816(acc[mt][2 * p], ah[mt], bh);
                    mma16816(acc[mt][2 * p], ah[mt], bl);
                    mma16816(acc[mt][2 * p], al[mt], bh);
                    mma16816(acc[mt][2 * p + 1], ah[mt], bh + 2);
                    mma16816(acc[mt][2 * p + 1], ah[mt], bl + 2);
                    mma16816(acc[mt][2 * p + 1], al[mt], bh + 2);
                }
            }
        }
        __syncthreads();
    }

    bool zi0 = (blockIdx.z == 0);
#pragma unroll
    for (int mt = 0; mt < 2; mt++) {
        int row = bm0 + wm * 32 + mt * 16;
#pragma unroll
        for (int nt = 0; nt < 8; nt++) {
            int coln = bn0 + wn * 64 + nt * 8 + tg * 2;
            float bx = zi0 ? bias[coln] : 0.f;
            float by = zi0 ? bias[coln + 1] : 0.f;
            float v0 = acc[mt][nt][0] + bx;
            float v1 = acc[mt][nt][1] + by;
            float v2 = acc[mt][nt][2] + bx;
            float v3 = acc[mt][nt][3] + by;
            if (RELU) {
                v0 = fmaxf(v0, 0.f); v1 = fmaxf(v1, 0.f);
                v2 = fmaxf(v2, 0.f); v3 = fmaxf(v3, 0.f);
            }
            size_t o0 = (size_t)(row + g) * N + coln;
            size_t o1 = (size_t)(row + 8 + g) * N + coln;
            if (nz > 1) {
                atomicAdd(&C[o0], v0);
                atomicAdd(&C[o0 + 1], v1);
                atomicAdd(&C[o1], v2);
                atomicAdd(&C[o1 + 1], v3);
            } else {
                if (C) {
                    float2 p0 = {v0, v1}, p1 = {v2, v3};
                    *(float2*)&C[o0] = p0;
                    *(float2*)&C[o1] = p1;
                }
                if (Oh) {
                    uint32_t h0 = pack_bf2(v0, v1), h1 = pack_bf2(v2, v3);
                    *(uint32_t*)&Oh[o0] = h0;
                    *(uint32_t*)&Oh[o1] = h1;
                    __nv_bfloat162 hp0 = *(__nv_bfloat162*)&h0;
                    __nv_bfloat162 hp1 = *(__nv_bfloat162*)&h1;
                    *(uint32_t*)&Ol[o0] = pack_bf2(v0 - __bfloat162float(hp0.x),
                                                   v1 - __bfloat162float(hp0.y));
                    *(uint32_t*)&Ol[o1] = pack_bf2(v2 - __bfloat162float(hp1.x),
                                                   v3 - __bfloat162float(hp1.y));
                }
            }
        }
    }
}

// ---------------- HMMA lse (transposed): T = K @ Q^T / 8, row-wise logsumexp -------
#define LKP2 72
#define KMATB (128 * LKP2 * 2)
#define QMATB (64 * LKP2 * 2)
#define LSE2_FBASE (2 * KMATB + 4 * QMATB)
#define LSE2_SMEM (LSE2_FBASE + (128 * 2 * 2 + 256) * 4)
__global__ void __launch_bounds__(256) lse_hmma2(
    const __nv_bfloat16* __restrict__ Qh_, const __nv_bfloat16* __restrict__ Ql_,
    const __nv_bfloat16* __restrict__ Kh_, const __nv_bfloat16* __restrict__ Kl_,
    float* __restrict__ lse) {
    uint32_t smb = smem_u32(dynsm);
    float* part_m = (float*)(dynsm + LSE2_FBASE);
    float* part_s = part_m + 128 * 2;
    float* Ms = part_s + 128 * 2;
    float* Ls = Ms + 128;

    int h = blockIdx.y;
    int m0 = blockIdx.x * 128;
    const __nv_bfloat16* Kh = Kh_ + h * 64;
    const __nv_bfloat16* Kl = Kl_ + h * 64;
    const __nv_bfloat16* Qh = Qh_ + h * 64;
    const __nv_bfloat16* Ql = Ql_ + h * 64;

    int t = threadIdx.x;
    int warp = t >> 5, lane = t & 31;
    int wm = warp & 3, wn = warp >> 2;
    int g = lane >> 2, tg = lane & 3;

    int lrow = lane & 15;
    int lko = (lane >> 4) * 8;
    uint32_t aoff = (uint32_t)(((wm * 32 + lrow) * LKP2 + lko) * 2);
    int bn_off = (lane & 7) + ((lane >> 4) ? 8 : 0);
    int bk_off = ((lane >> 3) & 1) * 8;
    uint32_t boff = (uint32_t)(((wn * 32 + bn_off) * LKP2 + bk_off) * 2);

#pragma unroll
    for (int r = 0; r < 8; r++) {
        int idx = t + 256 * r;
        int mat = idx >> 10, rem = idx & 1023, m = rem >> 3, ck = rem & 7;
        const __nv_bfloat16* gp = (mat ? Kl : Kh) + (size_t)(m0 + m) * SSTR + ck * 8;
        uint32_t sa = smb + (uint32_t)(mat * KMATB + (m * LKP2 + ck * 8) * 2);
        CPA16(sa, gp);
    }
    auto issueQ = [&](int q) {
        uint32_t qb = smb + (uint32_t)(2 * KMATB + (q & 1) * 2 * QMATB);
#pragma unroll
        for (int r = 0; r < 4; r++) {
            int idx = t + 256 * r;
            int mat = idx >> 9, rem = idx & 511, m = rem >> 3, ck = rem & 7;
            const __nv_bfloat16* gp = (mat ? Ql : Qh) + (size_t)(q * 64 + m) * SSTR + ck * 8;
            uint32_t sa = qb + (uint32_t)(mat * QMATB + (m * LKP2 + ck * 8) * 2);
            CPA16(sa, gp);
        }
    };

    issueQ(0);
    CP_COMMIT();
    if (t < 128) { Ms[t] = -INFINITY; Ls[t] = 0.f; }
    __syncthreads();

    const int nq = N_ / 64;
    for (int q = 0; q < nq; q++) {
        if (q + 1 < nq) {
            issueQ(q + 1);
            CP_COMMIT();
            CP_WAIT1();
        } else {
            CP_WAIT0();
        }
        __syncthreads();

        uint32_t aH = smb + aoff;
        uint32_t aL = smb + (uint32_t)KMATB + aoff;
        uint32_t qb = smb + (uint32_t)(2 * KMATB + (q & 1) * 2 * QMATB);
        uint32_t bH = qb + boff;
        uint32_t bL = qb + (uint32_t)QMATB + boff;

        float acc[2][4][4];
#pragma unroll
        for (int i = 0; i < 2; i++)
#pragma unroll
            for (int j = 0; j < 4; j++)
#pragma unroll
                for (int k = 0; k < 4; k++) acc[i][j][k] = 0.f;

#pragma unroll
        for (int ks = 0; ks < 4; ks++) {
            uint32_t koff = (uint32_t)(ks * 32);
            uint32_t ah[2][4], al[2][4];
#pragma unroll
            for (int mt = 0; mt < 2; mt++) {
                uint32_t ro = (uint32_t)(mt * 16 * LKP2 * 2) + koff;
                LDSM4(ah[mt], aH + ro);
                LDSM4(al[mt], aL + ro);
            }
#pragma unroll
            for (int p = 0; p < 2; p++) {
                uint32_t po = (uint32_t)(p * 16 * LKP2 * 2) + koff;
                uint32_t bh[4], bl[4];
                LDSM4(bh, bH + po);
                LDSM4(bl, bL + po);
#pragma unroll
                for (int mt = 0; mt < 2; mt++) {
                    mma16816(acc[mt][2 * p], ah[mt], bh);
                    mma16816(acc[mt][2 * p], ah[mt], bl);
                    mma16816(acc[mt][2 * p], al[mt], bh);
                    mma16816(acc[mt][2 * p + 1], ah[mt], bh + 2);
                    mma16816(acc[mt][2 * p + 1], ah[mt], bl + 2);
                    mma16816(acc[mt][2 * p + 1], al[mt], bh + 2);
                }
            }
        }

#pragma unroll
        for (int mt = 0; mt < 2; mt++) {
#pragma unroll
            for (int half = 0; half < 2; half++) {
                float v[8];
#pragma unroll
                for (int nt = 0; nt < 4; nt++) {
                    v[2 * nt] = acc[mt][nt][half * 2] * 0.125f;
                    v[2 * nt + 1] = acc[mt][nt][half * 2 + 1] * 0.125f;
                }
                float m = v[0];
#pragma unroll
                for (int i = 1; i < 8; i++) m = fmaxf(m, v[i]);
                m = fmaxf(m, __shfl_xor_sync(0xFFFFFFFFu, m, 1));
                m = fmaxf(m, __shfl_xor_sync(0xFFFFFFFFu, m, 2));
                float s = 0.f;
#pragma unroll
                for (int i = 0; i < 8; i++) s += __expf(v[i] - m);
                s += __shfl_xor_sync(0xFFFFFFFFu, s, 1);
                s += __shfl_xor_sync(0xFFFFFFFFu, s, 2);
                if (tg == 0) {
                    int row = wm * 32 + mt * 16 + half * 8 + g;
                    part_m[row * 2 + wn] = m;
                    part_s[row * 2 + wn] = s;
                }
            }
        }
        __syncthreads();
        if (t < 128) {
            float ma = part_m[t * 2], mb = part_m[t * 2 + 1];
            float m2 = fmaxf(ma, mb);
            float s2 = part_s[t * 2] * __expf(ma - m2) + part_s[t * 2 + 1] * __expf(mb - m2);
            float M = Ms[t], Ll = Ls[t];
            float mn = fmaxf(M, m2);
            Ls[t] = Ll * __expf(M - mn) + s2 * __expf(m2 - mn);
            Ms[t] = mn;
        }
        __syncthreads();
    }

    if (t < 128) lse[(size_t)h * N_ + m0 + t] = Ms[t] + logf(Ls[t]);
}

// ---------------- KtV[h] = K[h]^T V[h], lseV[h] = lse[h]^T V[h]  (bf16 hi+lo in) ---
__global__ void __launch_bounds__(256) ktv_kernel(const __nv_bfloat16* __restrict__ QKVh,
                                                  const __nv_bfloat16* __restrict__ QKVl,
                                                  const float* __restrict__ lse,
                                                  float* __restrict__ KtV,
                                                  float* __restrict__ lseV) {
    __shared__ float Ks[64][64];
    __shared__ float Vs[64][64];
    __shared__ float ls[64];
    int h = blockIdx.y;
    int k0 = blockIdx.x * 256;
    const __nv_bfloat16* Khb = QKVh + h * 64 + 1024;
    const __nv_bfloat16* Klb = QKVl + h * 64 + 1024;
    const __nv_bfloat16* Vhb = QKVh + h * 64 + 2048;
    const __nv_bfloat16* Vlb = QKVl + h * 64 + 2048;
    const float* lh = lse + (size_t)h * N_;
    int t = threadIdx.x;
    int ty = t >> 4, tx = t & 15;

    float c[4][4];
#pragma unroll
    for (int i = 0; i < 4; i++)
#pragma unroll
        for (int j = 0; j < 4; j++) c[i][j] = 0.f;
    float lv[4] = {0.f, 0.f, 0.f, 0.f};

    for (int kc = k0; kc < k0 + 256; kc += 64) {
#pragma unroll
        for (int r = 0; r < 4; r++) {
            int f = t + 256 * r;
            int row = f >> 4, c4 = f & 15;
            size_t off = (size_t)(kc + row) * SSTR + c4 * 4;
            uint2 kh = *(const uint2*)(Khb + off);
            uint2 kl = *(const uint2*)(Klb + off);
            uint2 vh = *(const uint2*)(Vhb + off);
            uint2 vl = *(const uint2*)(Vlb + off);
            __nv_bfloat162 kh0 = *(__nv_bfloat162*)&kh.x, kh1 = *(__nv_bfloat162*)&kh.y;
            __nv_bfloat162 kl0 = *(__nv_bfloat162*)&kl.x, kl1 = *(__nv_bfloat162*)&kl.y;
            __nv_bfloat162 vh0 = *(__nv_bfloat162*)&vh.x, vh1 = *(__nv_bfloat162*)&vh.y;
            __nv_bfloat162 vl0 = *(__nv_bfloat162*)&vl.x, vl1 = *(__nv_bfloat162*)&vl.y;
            float4 kv, vv;
            kv.x = __bfloat162float(kh0.x) + __bfloat162float(kl0.x);
            kv.y = __bfloat162float(kh0.y) + __bfloat162float(kl0.y);
            kv.z = __bfloat162float(kh1.x) + __bfloat162float(kl1.x);
            kv.w = __bfloat162float(kh1.y) + __bfloat162float(kl1.y);
            vv.x = __bfloat162float(vh0.x) + __bfloat162float(vl0.x);
            vv.y = __bfloat162float(vh0.y) + __bfloat162float(vl0.y);
            vv.z = __bfloat162float(vh1.x) + __bfloat162float(vl1.x);
            vv.w = __bfloat162float(vh1.y) + __bfloat162float(vl1.y);
            *(float4*)&Ks[row][c4 * 4] = kv;
            *(float4*)&Vs[row][c4 * 4] = vv;
        }
        if (t < 64) ls[t] = lh[kc + t];
        __syncthreads();
#pragma unroll 8
        for (int kk = 0; kk < 64; kk++) {
            float4 a = *(float4*)&Ks[kk][ty * 4];
            float4 b = *(float4*)&Vs[kk][tx * 4];
            float aa[4] = {a.x, a.y, a.z, a.w};
            float bb[4] = {b.x, b.y, b.z, b.w};
#pragma unroll
            for (int i = 0; i < 4; i++)
#pragma unroll
                for (int j = 0; j < 4; j++) c[i][j] += aa[i] * bb[j];
            if (ty == 0) {
                float l = ls[kk];
#pragma unroll
                for (int j = 0; j < 4; j++) lv[j] += l * bb[j];
            }
        }
        __syncthreads();
    }
#pragma unroll
    for (int i = 0; i < 4; i++)
#pragma unroll
        for (int j = 0; j < 4; j++)
            atomicAdd(&KtV[(size_t)h * DK_ * DV_ + (ty * 4 + i) * DV_ + tx * 4 + j], c[i][j]);
    if (ty == 0) {
#pragma unroll
        for (int j = 0; j < 4; j++) atomicAdd(&lseV[(size_t)h * DV_ + tx * 4 + j], lv[j]);
    }
}

// ---- G^T[c][h*64+d] = (1/8) sum_v KtV[h][d][v] * WO[h*64+v][c];  bZ -= lseV@WO ----
__global__ void __launch_bounds__(256) ktv_wo(const float* __restrict__ KtV,
                                              const float* __restrict__ lseV,
                                              const float* __restrict__ WO,
                                              __nv_bfloat16* __restrict__ Gth,
                                              __nv_bfloat16* __restrict__ Gtl,
                                              float* __restrict__ bZ) {
    __shared__ float kt[64 * 65];
    __shared__ float wos[64 * 64];
    __shared__ float lv[64];
    int h = blockIdx.y;
    int c0 = blockIdx.x * 64;
    int t = threadIdx.x;
    for (int i = t; i < 4096; i += 256) {
        kt[(i >> 6) * 65 + (i & 63)] = KtV[(size_t)h * 4096 + i] * 0.125f;
        wos[i] = WO[(size_t)(h * 64 + (i >> 6)) * DM_ + c0 + (i & 63)];
    }
    if (t < 64) lv[t] = lseV[h * 64 + t];
    __syncthreads();

    int td = t & 63;
    int tcg = t >> 6;
    float acc[16];
#pragma unroll
    for (int i = 0; i < 16; i++) acc[i] = 0.f;
#pragma unroll 8
    for (int v = 0; v < 64; v++) {
        float kv = kt[td * 65 + v];
        const float* wr = &wos[v * 64 + tcg];
#pragma unroll
        for (int i = 0; i < 16; i++) acc[i] += kv * wr[4 * i];
    }
#pragma unroll
    for (int i = 0; i < 16; i++) {
        int c = c0 + tcg + 4 * i;
        size_t o = (size_t)c * DM_ + h * 64 + td;
        __nv_bfloat16 hv = __float2bfloat16(acc[i]);
        Gth[o] = hv;
        Gtl[o] = __float2bfloat16(acc[i] - __bfloat162float(hv));
    }
    if (td == 0) {
        float bacc[16];
#pragma unroll
        for (int i = 0; i < 16; i++) bacc[i] = 0.f;
        for (int v = 0; v < 64; v++) {
            float l = lv[v];
#pragma unroll
            for (int i = 0; i < 16; i++) bacc[i] += l * wos[v * 64 + tcg + 4 * i];
        }
#pragma unroll
        for (int i = 0; i < 16; i++) atomicAdd(&bZ[c0 + tcg + 4 * i], -bacc[i]);
    }
}

// ---------------- layernorm (ddof=1), shuffle reductions, vectorized ----------------
__global__ void __launch_bounds__(256) ln_kernel(const float* __restrict__ a,
                                                 const float* __restrict__ b,
                                                 const float* __restrict__ g,
                                                 const float* __restrict__ be,
                                                 float* __restrict__ out,
                                                 __nv_bfloat16* __restrict__ oh,
                                                 __nv_bfloat16* __restrict__ ol) {
    __shared__ float red[8];
    int n = blockIdx.x;
    int t = threadIdx.x;
    int lane = t & 31, warp = t >> 5;
    size_t base = (size_t)n * DM_ + t * 4;

    float4 va = *(const float4*)(a + base);
    float4 vb = *(const float4*)(b + base);
    float x0 = va.x + vb.x, x1 = va.y + vb.y, x2 = va.z + vb.z, x3 = va.w + vb.w;

    float s = x0 + x1 + x2 + x3;
#pragma unroll
    for (int o = 16; o > 0; o >>= 1) s += __shfl_xor_sync(0xFFFFFFFFu, s, o);
    if (lane == 0) red[warp] = s;
    __syncthreads();
    float tot = red[0] + red[1] + red[2] + red[3] + red[4] + red[5] + red[6] + red[7];
    float mean = tot * (1.f / (float)DM_);

    float d0 = x0 - mean, d1 = x1 - mean, d2 = x2 - mean, d3 = x3 - mean;
    float s2 = d0 * d0 + d1 * d1 + d2 * d2 + d3 * d3;
#pragma unroll
    for (int o = 16; o > 0; o >>= 1) s2 += __shfl_xor_sync(0xFFFFFFFFu, s2, o);
    __syncthreads();
    if (lane == 0) red[warp] = s2;
    __syncthreads();
    float tot2 = red[0] + red[1] + red[2] + red[3] + red[4] + red[5] + red[6] + red[7];
    float invstd = rsqrtf(tot2 * (1.f / (float)(DM_ - 1)));

    float4 vg = *(const float4*)(g + base);
    float4 ve = *(const float4*)(be + base);
    float v0 = vg.x * invstd * d0 + ve.x;
    float v1 = vg.y * invstd * d1 + ve.y;
    float v2 = vg.z * invstd * d2 + ve.z;
    float v3 = vg.w * invstd * d3 + ve.w;

    float4 vo = {v0, v1, v2, v3};
    *(float4*)(out + base) = vo;
    if (oh) {
        uint32_t h0 = pack_bf2(v0, v1), h1 = pack_bf2(v2, v3);
        uint2 ph = {h0, h1};
        *(uint2*)(oh + base) = ph;
        __nv_bfloat162 hp0 = *(__nv_bfloat162*)&h0;
        __nv_bfloat162 hp1 = *(__nv_bfloat162*)&h1;
        uint2 pl = {pack_bf2(v0 - __bfloat162float(hp0.x), v1 - __bfloat162float(hp0.y)),
                    pack_bf2(v2 - __bfloat162float(hp1.x), v3 - __bfloat162float(hp1.y))};
        *(uint2*)(ol + base) = pl;
    }
}

// ---------------- launch ----------------
extern "C" void kernel_launch(void* const* d_in, const int* in_sizes, int n_in,
                              void* d_out, int out_size) {
    (void)in_sizes; (void)n_in; (void)out_size;
    const int*   X   = (const int*)d_in[0];
    const float* emb = (const float*)d_in[1];
    const float* WQ  = (const float*)d_in[2];
    const float* bQ  = (const float*)d_in[3];
    const float* WK  = (const float*)d_in[4];
    const float* bK  = (const float*)d_in[5];
    const float* WV  = (const float*)d_in[6];
    const float* bV  = (const float*)d_in[7];
    const float* WO  = (const float*)d_in[8];
    const float* bO  = (const float*)d_in[9];
    const float* W1  = (const float*)d_in[10];
    const float* b1  = (const float*)d_in[11];
    const float* W2  = (const float*)d_in[12];
    const float* b2  = (const float*)d_in[13];
    const float* g1  = (const float*)d_in[14];
    const float* be1 = (const float*)d_in[15];
    const float* g2  = (const float*)d_in[16];
    const float* be2 = (const float*)d_in[17];
    float* out = (float*)d_out;

    float *h, *lse, *KtV, *lseV, *Z, *h2, *R, *bQKV, *bZ;
    __nv_bfloat16 *hh, *hl, *QKVh, *QKVl, *h2h, *h2l, *F1h, *F1l, *Gth, *Gtl;
    __nv_bfloat16 *Wqkvh, *Wqkvl, *W1th, *W1tl, *W2th, *W2tl;
    cudaGetSymbolAddress((void**)&h, g_h);
    cudaGetSymbolAddress((void**)&lse, g_lse);
    cudaGetSymbolAddress((void**)&KtV, g_KtV);
    cudaGetSymbolAddress((void**)&lseV, g_lseV);
    cudaGetSymbolAddress((void**)&Z, g_Z);
    cudaGetSymbolAddress((void**)&h2, g_h2);
    cudaGetSymbolAddress((void**)&R, g_R);
    cudaGetSymbolAddress((void**)&bQKV, g_bQKV);
    cudaGetSymbolAddress((void**)&bZ, g_bZ);
    cudaGetSymbolAddress((void**)&hh, g_hh);
    cudaGetSymbolAddress((void**)&hl, g_hl);
    cudaGetSymbolAddress((void**)&QKVh, g_QKVh);
    cudaGetSymbolAddress((void**)&QKVl, g_QKVl);
    cudaGetSymbolAddress((void**)&h2h, g_h2h);
    cudaGetSymbolAddress((void**)&h2l, g_h2l);
    cudaGetSymbolAddress((void**)&F1h, g_F1h);
    cudaGetSymbolAddress((void**)&F1l, g_F1l);
    cudaGetSymbolAddress((void**)&Gth, g_Gth);
    cudaGetSymbolAddress((void**)&Gtl, g_Gtl);
    cudaGetSymbolAddress((void**)&Wqkvh, g_Wqkvh);
    cudaGetSymbolAddress((void**)&Wqkvl, g_Wqkvl);
    cudaGetSymbolAddress((void**)&W1th, g_W1th);
    cudaGetSymbolAddress((void**)&W1tl, g_W1tl);
    cudaGetSymbolAddress((void**)&W2th, g_W2th);
    cudaGetSymbolAddress((void**)&W2tl, g_W2tl);

    cudaFuncSetAttribute(lse_hmma2, cudaFuncAttributeMaxDynamicSharedMemorySize, LSE2_SMEM);
    cudaFuncSetAttribute(hmma_gemm<false>, cudaFuncAttributeMaxDynamicSharedMemorySize, HG_SMEM);
    cudaFuncSetAttribute(hmma_gemm<true>, cudaFuncAttributeMaxDynamicSharedMemorySize, HG_SMEM);

    // ---- one-time (per launch) weight conversions, batched across all layers ----
    cvtT_kernel<<<dim3(DM_ / 32, DK_ / 32, L_ * H_), dim3(32, 8)>>>(
        WQ, Wqkvh, Wqkvl, DM_, DK_, H_, SSTR);
    cvtT_kernel<<<dim3(DM_ / 32, DK_ / 32, L_ * H_), dim3(32, 8)>>>(
        WK, Wqkvh + (size_t)1024 * DM_, Wqkvl + (size_t)1024 * DM_, DM_, DK_, H_, SSTR);
    cvtT_kernel<<<dim3(DM_ / 32, DK_ / 32, L_ * H_), dim3(32, 8)>>>(
        WV, Wqkvh + (size_t)2048 * DM_, Wqkvl + (size_t)2048 * DM_, DM_, DK_, H_, SSTR);
    cvtT_kernel<<<dim3(DM_ / 32, DFF_ / 32, L_), dim3(32, 8)>>>(
        W1, W1th, W1tl, DM_, DFF_, 1, DFF_);
    cvtT_kernel<<<dim3(DFF_ / 32, DM_ / 32, L_), dim3(32, 8)>>>(
        W2, W2th, W2tl, DFF_, DM_, 1, DM_);
    pack_bias<<<(L_ * SSTR + 255) / 256, 256>>>(bQ, bK, bV, bQKV);

    embed_kernel<<<N_, 256>>>(X, emb, h, hh, hl);

    for (int l = 0; l < L_; l++) {
        const __nv_bfloat16* Wqh = Wqkvh + (size_t)l * SSTR * DM_;
        const __nv_bfloat16* Wql = Wqkvl + (size_t)l * SSTR * DM_;
        const __nv_bfloat16* W1h = W1th + (size_t)l * DFF_ * DM_;
        const __nv_bfloat16* W1l_ = W1tl + (size_t)l * DFF_ * DM_;
        const __nv_bfloat16* W2h = W2th + (size_t)l * DM_ * DFF_;
        const __nv_bfloat16* W2l_ = W2tl + (size_t)l * DM_ * DFF_;
        const float* WOl_ = WO + (size_t)l * DM_ * DM_;
        const float* bOl = bO + (size_t)l * DM_;
        const float* b1l = b1 + (size_t)l * DFF_;
        const float* b2l = b2 + (size_t)l * DM_;
        const float* g1l = g1 + (size_t)l * N_ * DM_;
        const float* be1l = be1 + (size_t)l * N_ * DM_;
        const float* g2l = g2 + (size_t)l * N_ * DM_;
        const float* be2l = be2 + (size_t)l * N_ * DM_;

        // ---- fused QKV projection (bf16 hi/lo out only)
        hmma_gemm<false><<<dim3(SSTR / 128, N_ / 128, 1), 256, HG_SMEM>>>(
            hh, hl, Wqh, Wql, nullptr, QKVh, QKVl, bQKV + (size_t)l * SSTR,
            N_, SSTR, DM_, DM_, DM_);

        // ---- attention reductions
        cudaMemsetAsync(KtV, 0, H_ * DK_ * DV_ * sizeof(float));
        cudaMemsetAsync(lseV, 0, H_ * DV_ * sizeof(float));
        lse_hmma2<<<dim3(N_ / 128, H_), 256, LSE2_SMEM>>>(
            QKVh, QKVl, QKVh + 1024, QKVl + 1024, lse);
        ktv_kernel<<<dim3(N_ / 256, H_), 256>>>(QKVh, QKVl, lse, KtV, lseV);

        // ---- fold attn@WO: G = KtV@WO/8 (bf16 hi/lo, transposed), bZ = bO - lseV@WO
        cudaMemcpyAsync(bZ, bOl, DM_ * sizeof(float), cudaMemcpyDeviceToDevice);
        ktv_wo<<<dim3(DM_ / 64, H_), 256>>>(KtV, lseV, WOl_, Gth, Gtl, bZ);

        // ---- Z = Q @ G + bZ  (split-K=2, atomic)
        cudaMemsetAsync(Z, 0, (size_t)N_ * DM_ * sizeof(float));
        hmma_gemm<false><<<dim3(DM_ / 128, N_ / 128, 2), 256, HG_SMEM>>>(
            QKVh, QKVl, Gth, Gtl, Z, nullptr, nullptr, bZ, N_, DM_, 1024, SSTR, 1024);

        // ---- h2 = LN(h + Z)
        ln_kernel<<<N_, 256>>>(h, Z, g1l, be1l, h2, h2h, h2l);

        // ---- F1 = relu(h2 @ W1 + b1) (bf16 hi/lo out only)
        hmma_gemm<true><<<dim3(DFF_ / 128, N_ / 128, 1), 256, HG_SMEM>>>(
            h2h, h2l, W1h, W1l_, nullptr, F1h, F1l, b1l, N_, DFF_, DM_, DM_, DM_);

        // ---- R = F1 @ W2 + b2  (split-K=4, atomic)
        cudaMemsetAsync(R, 0, (size_t)N_ * DM_ * sizeof(float));
        hmma_gemm<false><<<dim3(DM_ / 128, N_ / 128, 4), 256, HG_SMEM>>>(
            F1h, F1l, W2h, W2l_, R, nullptr, nullptr, b2l, N_, DM_, DFF_, DFF_, DFF_);

        // ---- h = LN(h2 + R)
        if (l == L_ - 1) {
            ln_kernel<<<N_, 256>>>(h2, R, g2l, be2l, out, nullptr, nullptr);
        } else {
            ln_kernel<<<N_, 256>>>(h2, R, g2l, be2l, h, hh, hl);
        }
    }
}